// round 1
// baseline (speedup 1.0000x reference)
#include <cuda_runtime.h>
#include <math.h>

#define NBATCH  2
#define S_LEN   2048
#define D_MODEL 2048
#define NHEADS  16
#define DHEAD   128
#define M_ROWS  (NBATCH * S_LEN)   // 4096

// ---------------- scratch (allocation-free: __device__ globals) ----------------
__device__ float g_Q[(size_t)M_ROWS * D_MODEL];
__device__ float g_K[(size_t)M_ROWS * D_MODEL];
__device__ float g_V[(size_t)M_ROWS * D_MODEL];
__device__ float g_Y[(size_t)M_ROWS * D_MODEL];

// ---------------- NT GEMM: C[m,n] = sum_k A[m,k] * B[n,k] ----------------
// A: [M,K] row-major, B: [N,K] row-major (i.e., computes A @ B^T)
#define GBM 128
#define GBN 128
#define GBK 16

__global__ __launch_bounds__(256) void gemm_nt_kernel(
    const float* __restrict__ A, const float* __restrict__ B,
    float* __restrict__ C, int M, int N, int K)
{
    __shared__ float As[GBK][GBM];
    __shared__ float Bs[GBK][GBN];

    const int tid = threadIdx.x;
    const int bm = blockIdx.y * GBM;
    const int bn = blockIdx.x * GBN;
    const int tx = tid & 15;        // 0..15 -> n microtile
    const int ty = tid >> 4;        // 0..15 -> m microtile

    // loader mapping: 128 rows x 16 cols; 2 threads per row, 8 floats each
    const int lr = tid >> 1;          // 0..127
    const int lc = (tid & 1) * 8;     // 0 or 8

    float acc[8][8];
#pragma unroll
    for (int i = 0; i < 8; i++)
#pragma unroll
        for (int j = 0; j < 8; j++) acc[i][j] = 0.0f;

    for (int k0 = 0; k0 < K; k0 += GBK) {
        // load A tile (transposed into smem)
        {
            const float* src = A + (size_t)(bm + lr) * K + k0 + lc;
            float4 v0 = *(const float4*)(src);
            float4 v1 = *(const float4*)(src + 4);
            As[lc + 0][lr] = v0.x; As[lc + 1][lr] = v0.y;
            As[lc + 2][lr] = v0.z; As[lc + 3][lr] = v0.w;
            As[lc + 4][lr] = v1.x; As[lc + 5][lr] = v1.y;
            As[lc + 6][lr] = v1.z; As[lc + 7][lr] = v1.w;
        }
        // load B tile
        {
            const float* src = B + (size_t)(bn + lr) * K + k0 + lc;
            float4 v0 = *(const float4*)(src);
            float4 v1 = *(const float4*)(src + 4);
            Bs[lc + 0][lr] = v0.x; Bs[lc + 1][lr] = v0.y;
            Bs[lc + 2][lr] = v0.z; Bs[lc + 3][lr] = v0.w;
            Bs[lc + 4][lr] = v1.x; Bs[lc + 5][lr] = v1.y;
            Bs[lc + 6][lr] = v1.z; Bs[lc + 7][lr] = v1.w;
        }
        __syncthreads();

#pragma unroll
        for (int kk = 0; kk < GBK; kk++) {
            float ra[8], rb[8];
            *(float4*)&ra[0] = *(const float4*)&As[kk][ty * 8];
            *(float4*)&ra[4] = *(const float4*)&As[kk][ty * 8 + 4];
            *(float4*)&rb[0] = *(const float4*)&Bs[kk][tx * 8];
            *(float4*)&rb[4] = *(const float4*)&Bs[kk][tx * 8 + 4];
#pragma unroll
            for (int i = 0; i < 8; i++)
#pragma unroll
                for (int j = 0; j < 8; j++)
                    acc[i][j] += ra[i] * rb[j];
        }
        __syncthreads();
    }

#pragma unroll
    for (int i = 0; i < 8; i++) {
        size_t row = (size_t)(bm + ty * 8 + i);
        float4 v0 = make_float4(acc[i][0], acc[i][1], acc[i][2], acc[i][3]);
        float4 v1 = make_float4(acc[i][4], acc[i][5], acc[i][6], acc[i][7]);
        *(float4*)(C + row * N + bn + tx * 8)     = v0;
        *(float4*)(C + row * N + bn + tx * 8 + 4) = v1;
    }
}

// ---------------- flash attention (fp32 SIMT) ----------------
// grid: (32 q-tiles, 32 b*h). 64-row q tile, 64-row k/v tiles, causal.
#define SMEM_ATTN_FLOATS (64*128*3 + 64*65 + 64*3)
#define SMEM_ATTN_BYTES  (SMEM_ATTN_FLOATS * 4)

__global__ __launch_bounds__(256) void attn_kernel(
    const float* __restrict__ Q, const float* __restrict__ K,
    const float* __restrict__ V, float* __restrict__ Y)
{
    extern __shared__ float sm[];
    float* sQ     = sm;                 // [64][128]
    float* sK     = sQ + 64 * 128;      // [64][128]
    float* sV     = sK + 64 * 128;      // [64][128]
    float* sP     = sV + 64 * 128;      // [64][65] padded
    float* sLrow  = sP + 64 * 65;       // [64]
    float* sScale = sLrow + 64;         // [64]

    const int tid = threadIdx.x;
    const int qt  = blockIdx.x;         // 0..31
    const int bh  = blockIdx.y;         // 0..31
    const int b   = bh >> 4;
    const int h   = bh & 15;
    const size_t base = ((size_t)b * S_LEN) * D_MODEL + (size_t)h * DHEAD;
    const float qscale = 0.08838834764831845f;   // 1/sqrt(128)

    // load Q tile (pre-scaled)
    for (int i = tid; i < 64 * 32; i += 256) {
        int r = i >> 5, c = (i & 31) << 2;
        float4 v = *(const float4*)(Q + base + (size_t)(qt * 64 + r) * D_MODEL + c);
        v.x *= qscale; v.y *= qscale; v.z *= qscale; v.w *= qscale;
        *(float4*)&sQ[r * 128 + c] = v;
    }

    // per-thread state
    const int oq = tid & 15;            // PV: q microrow group (4 rows)
    const int od = tid >> 4;            // PV: d group (8 cols)
    const int sr = tid >> 2;            // softmax row
    const int sseg = tid & 3;           // softmax segment (16 cols each)
    const int qi = tid & 15;            // score: q group
    const int ki = tid >> 4;            // score: k group

    float mrow = -1e30f;
    float lrow = 0.0f;
    float accO[4][8];
#pragma unroll
    for (int i = 0; i < 4; i++)
#pragma unroll
        for (int j = 0; j < 8; j++) accO[i][j] = 0.0f;

    const int njt = qt + 1;
    for (int jt = 0; jt < njt; jt++) {
        __syncthreads();    // protect sK/sV/sP from previous iteration consumers

        // load K, V tiles
        for (int i = tid; i < 64 * 32; i += 256) {
            int r = i >> 5, c = (i & 31) << 2;
            size_t g = base + (size_t)(jt * 64 + r) * D_MODEL + c;
            *(float4*)&sK[r * 128 + c] = *(const float4*)(K + g);
            *(float4*)&sV[r * 128 + c] = *(const float4*)(V + g);
        }
        __syncthreads();

        // ---- scores: 4x4 per thread over 64x64, dot over d=128 ----
        float s4[4][4];
#pragma unroll
        for (int i = 0; i < 4; i++)
#pragma unroll
            for (int j = 0; j < 4; j++) s4[i][j] = 0.0f;

#pragma unroll 8
        for (int dstep = 0; dstep < 32; dstep++) {
            int d = ((dstep + qi) & 31) << 2;   // rotate start to avoid conflicts
            float4 qa0 = *(const float4*)&sQ[(4 * qi + 0) * 128 + d];
            float4 qa1 = *(const float4*)&sQ[(4 * qi + 1) * 128 + d];
            float4 qa2 = *(const float4*)&sQ[(4 * qi + 2) * 128 + d];
            float4 qa3 = *(const float4*)&sQ[(4 * qi + 3) * 128 + d];
            float4 kb0 = *(const float4*)&sK[(4 * ki + 0) * 128 + d];
            float4 kb1 = *(const float4*)&sK[(4 * ki + 1) * 128 + d];
            float4 kb2 = *(const float4*)&sK[(4 * ki + 2) * 128 + d];
            float4 kb3 = *(const float4*)&sK[(4 * ki + 3) * 128 + d];
            float4 qa[4] = {qa0, qa1, qa2, qa3};
            float4 kb[4] = {kb0, kb1, kb2, kb3};
#pragma unroll
            for (int i = 0; i < 4; i++)
#pragma unroll
                for (int j = 0; j < 4; j++) {
                    float s = s4[i][j];
                    s = fmaf(qa[i].x, kb[j].x, s);
                    s = fmaf(qa[i].y, kb[j].y, s);
                    s = fmaf(qa[i].z, kb[j].z, s);
                    s = fmaf(qa[i].w, kb[j].w, s);
                    s4[i][j] = s;
                }
        }

        // write scores with causal mask
#pragma unroll
        for (int i = 0; i < 4; i++) {
            int qg = qt * 64 + 4 * qi + i;
#pragma unroll
            for (int j = 0; j < 4; j++) {
                int kg = jt * 64 + 4 * ki + j;
                sP[(4 * qi + i) * 65 + 4 * ki + j] = (kg > qg) ? -1e30f : s4[i][j];
            }
        }
        __syncthreads();

        // ---- online softmax: 4 threads per row, 16 cols each ----
        {
            float* prow = &sP[sr * 65 + sseg * 16];
            float mloc = -1e30f;
#pragma unroll
            for (int c = 0; c < 16; c++) mloc = fmaxf(mloc, prow[c]);
            mloc = fmaxf(mloc, __shfl_xor_sync(0xffffffffu, mloc, 1));
            mloc = fmaxf(mloc, __shfl_xor_sync(0xffffffffu, mloc, 2));
            float mnew = fmaxf(mrow, mloc);
            float corr = __expf(mrow - mnew);
            float psum = 0.0f;
#pragma unroll
            for (int c = 0; c < 16; c++) {
                float p = __expf(prow[c] - mnew);
                prow[c] = p;
                psum += p;
            }
            psum += __shfl_xor_sync(0xffffffffu, psum, 1);
            psum += __shfl_xor_sync(0xffffffffu, psum, 2);
            lrow = lrow * corr + psum;
            mrow = mnew;
            if (sseg == 0) { sScale[sr] = corr; sLrow[sr] = lrow; }
        }
        __syncthreads();

        // ---- PV: O[64][128] += P[64][64] @ V[64][128] ----
#pragma unroll
        for (int i = 0; i < 4; i++) {
            float c = sScale[4 * oq + i];
#pragma unroll
            for (int j = 0; j < 8; j++) accO[i][j] *= c;
        }
#pragma unroll 4
        for (int j = 0; j < 64; j++) {
            float4 v0 = *(const float4*)&sV[j * 128 + od * 8];
            float4 v1 = *(const float4*)&sV[j * 128 + od * 8 + 4];
#pragma unroll
            for (int i = 0; i < 4; i++) {
                float p = sP[(4 * oq + i) * 65 + j];
                accO[i][0] = fmaf(p, v0.x, accO[i][0]);
                accO[i][1] = fmaf(p, v0.y, accO[i][1]);
                accO[i][2] = fmaf(p, v0.z, accO[i][2]);
                accO[i][3] = fmaf(p, v0.w, accO[i][3]);
                accO[i][4] = fmaf(p, v1.x, accO[i][4]);
                accO[i][5] = fmaf(p, v1.y, accO[i][5]);
                accO[i][6] = fmaf(p, v1.z, accO[i][6]);
                accO[i][7] = fmaf(p, v1.w, accO[i][7]);
            }
        }
    }

    // final normalize + write (sLrow was synced before last PV phase)
#pragma unroll
    for (int i = 0; i < 4; i++) {
        int r = 4 * oq + i;
        float inv = 1.0f / sLrow[r];
        float4 o0 = make_float4(accO[i][0] * inv, accO[i][1] * inv,
                                accO[i][2] * inv, accO[i][3] * inv);
        float4 o1 = make_float4(accO[i][4] * inv, accO[i][5] * inv,
                                accO[i][6] * inv, accO[i][7] * inv);
        size_t g = base + (size_t)(qt * 64 + r) * D_MODEL + od * 8;
        *(float4*)(Y + g)     = o0;
        *(float4*)(Y + g + 4) = o1;
    }
}

// ---------------- launch ----------------
extern "C" void kernel_launch(void* const* d_in, const int* in_sizes, int n_in,
                              void* d_out, int out_size)
{
    (void)in_sizes; (void)n_in; (void)out_size;
    const float* x  = (const float*)d_in[0];
    // d_in[1] = attn_mask (causal, applied analytically)
    const float* Wq = (const float*)d_in[2];
    const float* Wk = (const float*)d_in[3];
    const float* Wv = (const float*)d_in[4];
    const float* Wo = (const float*)d_in[5];
    float* out = (float*)d_out;

    float *Qb, *Kb, *Vb, *Yb;
    cudaGetSymbolAddress((void**)&Qb, g_Q);
    cudaGetSymbolAddress((void**)&Kb, g_K);
    cudaGetSymbolAddress((void**)&Vb, g_V);
    cudaGetSymbolAddress((void**)&Yb, g_Y);

    cudaFuncSetAttribute(attn_kernel,
                         cudaFuncAttributeMaxDynamicSharedMemorySize,
                         SMEM_ATTN_BYTES);

    dim3 gGemm(D_MODEL / GBN, M_ROWS / GBM, 1);   // (16, 32)
    dim3 tGemm(256);

    gemm_nt_kernel<<<gGemm, tGemm>>>(x, Wq, Qb, M_ROWS, D_MODEL, D_MODEL);
    gemm_nt_kernel<<<gGemm, tGemm>>>(x, Wk, Kb, M_ROWS, D_MODEL, D_MODEL);
    gemm_nt_kernel<<<gGemm, tGemm>>>(x, Wv, Vb, M_ROWS, D_MODEL, D_MODEL);

    attn_kernel<<<dim3(S_LEN / 64, NBATCH * NHEADS), 256, SMEM_ATTN_BYTES>>>(Qb, Kb, Vb, Yb);

    gemm_nt_kernel<<<gGemm, tGemm>>>(Yb, Wo, out, M_ROWS, D_MODEL, D_MODEL);
}

// round 3
// speedup vs baseline: 4.0103x; 4.0103x over previous
#include <cuda_runtime.h>
#include <cuda_bf16.h>
#include <math.h>
#include <stdint.h>

// tcgen05 is only legal in the arch-specific ('a') device passes. The build
// also emits a plain compute_103 PTX pass, which must see stub bodies.
#if defined(__CUDA_ARCH__)
#if defined(__CUDA_ARCH_FEAT_SM103_ALL) || defined(__CUDA_ARCH_FEAT_SM100_ALL) || defined(__CUDA_ARCH_FEAT_SM101_ALL)
#define TCGEN05_OK 1
#else
#define TCGEN05_OK 0
#endif
#else
#define TCGEN05_OK 0
#endif

#define NBATCH  2
#define S_LEN   2048
#define D_MODEL 2048
#define NHEADS  16
#define DHEAD   128
#define M_ROWS  (NBATCH * S_LEN)   // 4096
#define DD      (D_MODEL * D_MODEL)

// ---------------- scratch (allocation-free: __device__ globals) ----------------
__device__ float g_Q[(size_t)M_ROWS * D_MODEL];
__device__ float g_K[(size_t)M_ROWS * D_MODEL];
__device__ float g_V[(size_t)M_ROWS * D_MODEL];
__device__ float g_Y[(size_t)M_ROWS * D_MODEL];

__device__ __nv_bfloat16 g_xhi[(size_t)M_ROWS * D_MODEL];
__device__ __nv_bfloat16 g_xlo[(size_t)M_ROWS * D_MODEL];
__device__ __nv_bfloat16 g_yhi[(size_t)M_ROWS * D_MODEL];
__device__ __nv_bfloat16 g_ylo[(size_t)M_ROWS * D_MODEL];
__device__ __nv_bfloat16 g_whi[(size_t)4 * DD];
__device__ __nv_bfloat16 g_wlo[(size_t)4 * DD];

// ---------------- PTX helpers (stubbed in non-'a' PTX passes) ----------------
__device__ __forceinline__ uint32_t smem_u32(const void* p) {
    uint32_t a;
    asm("{ .reg .u64 t; cvta.to.shared.u64 t, %1; cvt.u32.u64 %0, t; }"
        : "=r"(a) : "l"(p));
    return a;
}

__device__ __forceinline__ uint32_t elect1() {
#if TCGEN05_OK
    uint32_t p;
    asm volatile(
        "{\n\t.reg .pred p;\n\t"
        "elect.sync _|p, 0xFFFFFFFF;\n\t"
        "selp.b32 %0, 1, 0, p;\n\t}"
        : "=r"(p));
    return p;
#else
    return 0;
#endif
}

__device__ __forceinline__ void mbar_init(uint32_t addr, uint32_t count) {
    asm volatile("mbarrier.init.shared.b64 [%0], %1;" :: "r"(addr), "r"(count) : "memory");
}
__device__ __forceinline__ void mbar_inval(uint32_t addr) {
    asm volatile("mbarrier.inval.shared.b64 [%0];" :: "r"(addr) : "memory");
}
__device__ __forceinline__ void mbar_wait(uint32_t addr, uint32_t parity) {
    asm volatile(
        "{\n\t.reg .pred P;\n\t"
        "WL_%=:\n\t"
        "mbarrier.try_wait.parity.acquire.cta.shared::cta.b64 P, [%0], %1, 0x989680;\n\t"
        "@P bra.uni WD_%=;\n\t"
        "bra.uni WL_%=;\n\t"
        "WD_%=:\n\t}"
        :: "r"(addr), "r"(parity) : "memory");
}

__device__ __forceinline__ void tmem_alloc(uint32_t smem_dst, uint32_t ncols) {
#if TCGEN05_OK
    asm volatile("tcgen05.alloc.cta_group::1.sync.aligned.shared::cta.b32 [%0], %1;"
                 :: "r"(smem_dst), "r"(ncols) : "memory");
#endif
}
__device__ __forceinline__ void tmem_dealloc(uint32_t tmem, uint32_t ncols) {
#if TCGEN05_OK
    asm volatile("tcgen05.dealloc.cta_group::1.sync.aligned.b32 %0, %1;"
                 :: "r"(tmem), "r"(ncols));
#endif
}
__device__ __forceinline__ void tmem_relinquish() {
#if TCGEN05_OK
    asm volatile("tcgen05.relinquish_alloc_permit.cta_group::1.sync.aligned;");
#endif
}

__device__ __forceinline__ void mma_f16_ss(uint32_t d_tmem, uint64_t a_desc,
                                           uint64_t b_desc, uint32_t idesc,
                                           uint32_t enable_d) {
#if TCGEN05_OK
    asm volatile(
        "{\n\t.reg .pred p;\n\t"
        "setp.ne.u32 p, %4, 0;\n\t"
        "tcgen05.mma.cta_group::1.kind::f16 [%0], %1, %2, %3, {%5, %5, %5, %5}, p;\n\t}"
        :: "r"(d_tmem), "l"(a_desc), "l"(b_desc), "r"(idesc), "r"(enable_d), "r"(0u)
        : "memory");
#endif
}

__device__ __forceinline__ void mma_commit(uint32_t mbar_addr) {
#if TCGEN05_OK
    asm volatile(
        "tcgen05.commit.cta_group::1.mbarrier::arrive::one.shared::cluster.b64 [%0];"
        :: "r"(mbar_addr) : "memory");
#endif
}

__device__ __forceinline__ void tcg_fence_after() {
#if TCGEN05_OK
    asm volatile("tcgen05.fence::after_thread_sync;" ::: "memory");
#endif
}
__device__ __forceinline__ void fence_proxy_async_s() {
    asm volatile("fence.proxy.async.shared::cta;" ::: "memory");
}
__device__ __forceinline__ void tcg_wait_ld() {
#if TCGEN05_OK
    asm volatile("tcgen05.wait::ld.sync.aligned;" ::: "memory");
#endif
}

__device__ __forceinline__ void ldtm_x32(uint32_t* r, uint32_t addr) {
#if TCGEN05_OK
    asm volatile(
        "tcgen05.ld.sync.aligned.32x32b.x32.b32 "
        "{%0, %1, %2, %3, %4, %5, %6, %7, "
        " %8, %9, %10, %11, %12, %13, %14, %15, "
        " %16, %17, %18, %19, %20, %21, %22, %23, "
        " %24, %25, %26, %27, %28, %29, %30, %31}, [%32];"
        : "=r"(r[0]),  "=r"(r[1]),  "=r"(r[2]),  "=r"(r[3]),
          "=r"(r[4]),  "=r"(r[5]),  "=r"(r[6]),  "=r"(r[7]),
          "=r"(r[8]),  "=r"(r[9]),  "=r"(r[10]), "=r"(r[11]),
          "=r"(r[12]), "=r"(r[13]), "=r"(r[14]), "=r"(r[15]),
          "=r"(r[16]), "=r"(r[17]), "=r"(r[18]), "=r"(r[19]),
          "=r"(r[20]), "=r"(r[21]), "=r"(r[22]), "=r"(r[23]),
          "=r"(r[24]), "=r"(r[25]), "=r"(r[26]), "=r"(r[27]),
          "=r"(r[28]), "=r"(r[29]), "=r"(r[30]), "=r"(r[31])
        : "r"(addr));
#else
    for (int i = 0; i < 32; i++) r[i] = 0;
#endif
}

// SW128 smem descriptor base: layout=SW128(2), version=1, SBO=64, LBO=1
#define DESC_BASE ((2ull << 61) | (1ull << 46) | (64ull << 32) | (1ull << 16))

// idesc kind::f16: dtype=F32, a/b=BF16, N=128, M=128
#define IDESC_BF16 ((1u << 4) | (1u << 7) | (1u << 10) | (16u << 17) | (8u << 24))

// ---------------- fp32 -> (hi, lo) bf16 split ----------------
__global__ __launch_bounds__(256) void split_bf16_kernel(
    const float* __restrict__ src,
    __nv_bfloat16* __restrict__ hi, __nv_bfloat16* __restrict__ lo, int n4)
{
    int i = blockIdx.x * 256 + threadIdx.x;
    if (i >= n4) return;
    float4 v = ((const float4*)src)[i];
    __nv_bfloat16 h0 = __float2bfloat16(v.x);
    __nv_bfloat16 h1 = __float2bfloat16(v.y);
    __nv_bfloat16 h2 = __float2bfloat16(v.z);
    __nv_bfloat16 h3 = __float2bfloat16(v.w);
    __nv_bfloat16 l0 = __float2bfloat16(v.x - __bfloat162float(h0));
    __nv_bfloat16 l1 = __float2bfloat16(v.y - __bfloat162float(h1));
    __nv_bfloat16 l2 = __float2bfloat16(v.z - __bfloat162float(h2));
    __nv_bfloat16 l3 = __float2bfloat16(v.w - __bfloat162float(h3));
    __nv_bfloat162* hp = (__nv_bfloat162*)hi;
    __nv_bfloat162* lp = (__nv_bfloat162*)lo;
    __nv_bfloat162 a, b;
    a.x = h0; a.y = h1; b.x = h2; b.y = h3;
    hp[2 * i] = a; hp[2 * i + 1] = b;
    a.x = l0; a.y = l1; b.x = l2; b.y = l3;
    lp[2 * i] = a; lp[2 * i + 1] = b;
}

// ---------------- tcgen05 GEMM: C = A @ B^T, 3-term bf16 split ----------------
#define OFF_A0 1024
#define OFF_B0 (1024 + 16384)
#define OFF_A1 (1024 + 2 * 16384)
#define OFF_B1 (1024 + 3 * 16384)
#define GSMEM_TOTAL (1024 + 4 * 16384)

__global__ __launch_bounds__(256) void gemm_bf16x3_kernel(
    const __nv_bfloat16* __restrict__ Ahi, const __nv_bfloat16* __restrict__ Alo,
    const __nv_bfloat16* __restrict__ Bhi, const __nv_bfloat16* __restrict__ Blo,
    float* __restrict__ C, int M, int N, int K)
{
#if TCGEN05_OK
    extern __shared__ char smem[];
    const uint32_t sb = smem_u32(smem);
    const int tid = threadIdx.x;
    const int wid = tid >> 5;
    const int lid = tid & 31;
    const int bm = blockIdx.y * 128;
    const int bn = blockIdx.x * 128;

    if (wid == 0) {
        tmem_alloc(sb, 128);
        tmem_relinquish();
    }
    if (tid == 0) {
        mbar_init(sb + 8, 1);
        mbar_init(sb + 16, 1);
    }
    __syncthreads();
    uint32_t tmem;
    asm volatile("ld.shared.b32 %0, [%1];" : "=r"(tmem) : "r"(sb));

    const int nk = K / 64;           // 32
    const int nchunks = 3 * nk;      // 96
    uint32_t ph0 = 0, ph1 = 0;

    for (int i = 0; i < nchunks; i++) {
        const int term = i / nk;
        const int k0 = (i - term * nk) * 64;
        const __nv_bfloat16* As = (term == 2) ? Alo : Ahi;
        const __nv_bfloat16* Bs = (term == 1) ? Blo : Bhi;

        // prefetch gmem into registers (each thread: 4x16B from A, 4x16B from B)
        uint4 ra[4], rb[4];
#pragma unroll
        for (int j = 0; j < 4; j++) {
            int u = tid + j * 256;       // 16B-unit index, 0..1023
            int r = u >> 3, cs = u & 7;  // row, 16B segment in row
            ra[j] = *(const uint4*)(As + (size_t)(bm + r) * K + k0 + cs * 8);
            rb[j] = *(const uint4*)(Bs + (size_t)(bn + r) * K + k0 + cs * 8);
        }

        const int buf = i & 1;
        if (i >= 2) {
            if (buf == 0) { mbar_wait(sb + 8, ph0);  ph0 ^= 1; }
            else          { mbar_wait(sb + 16, ph1); ph1 ^= 1; }
        }
        const uint32_t offA = buf ? OFF_A1 : OFF_A0;
        const uint32_t offB = buf ? OFF_B1 : OFF_B0;
#pragma unroll
        for (int j = 0; j < 4; j++) {
            int u = tid + j * 256;
            uint32_t bo = (uint32_t)u * 16u;
            uint32_t sw = bo ^ ((bo >> 3) & 0x70);   // SW128 swizzle
            *(uint4*)(smem + offA + sw) = ra[j];
            *(uint4*)(smem + offB + sw) = rb[j];
        }
        __syncthreads();

        if (wid == 0 && elect1()) {
            fence_proxy_async_s();
            uint64_t ad = DESC_BASE | ((uint64_t)((sb + offA) >> 4) & 0x3FFF);
            uint64_t bd = DESC_BASE | ((uint64_t)((sb + offB) >> 4) & 0x3FFF);
#pragma unroll
            for (int k = 0; k < 4; k++) {
                uint32_t en = !(i == 0 && k == 0);
                mma_f16_ss(tmem, ad + k * 2, bd + k * 2, IDESC_BF16, en);
            }
            mma_commit(buf ? (sb + 16) : (sb + 8));
        }
    }

    // last chunk (95) committed to mbar1; commit covers ALL prior MMAs
    mbar_wait(sb + 16, ph1);
    tcg_fence_after();

    if (wid < 4) {
        const size_t row = (size_t)(bm + wid * 32 + lid);
        float* crow = C + row * (size_t)N + bn;
#pragma unroll
        for (int cb = 0; cb < 128; cb += 32) {
            uint32_t dr[32];
            ldtm_x32(dr, tmem + cb);
            tcg_wait_ld();
#pragma unroll
            for (int c = 0; c < 32; c += 4) {
                float4 v = make_float4(__uint_as_float(dr[c]),
                                       __uint_as_float(dr[c + 1]),
                                       __uint_as_float(dr[c + 2]),
                                       __uint_as_float(dr[c + 3]));
                *(float4*)(crow + cb + c) = v;
            }
        }
    }
    __syncthreads();
    if (tid == 0) { mbar_inval(sb + 8); mbar_inval(sb + 16); }
    if (wid == 0) tmem_dealloc(tmem, 128);
#endif  // TCGEN05_OK
}

// ---------------- flash attention (fp32 SIMT, unchanged from R1) ----------------
#define SMEM_ATTN_FLOATS (64*128*3 + 64*65 + 64*3)
#define SMEM_ATTN_BYTES  (SMEM_ATTN_FLOATS * 4)

__global__ __launch_bounds__(256) void attn_kernel(
    const float* __restrict__ Q, const float* __restrict__ K,
    const float* __restrict__ V, float* __restrict__ Y)
{
    extern __shared__ float sm[];
    float* sQ     = sm;
    float* sK     = sQ + 64 * 128;
    float* sV     = sK + 64 * 128;
    float* sP     = sV + 64 * 128;
    float* sLrow  = sP + 64 * 65;
    float* sScale = sLrow + 64;

    const int tid = threadIdx.x;
    const int qt  = blockIdx.x;
    const int bh  = blockIdx.y;
    const int b   = bh >> 4;
    const int h   = bh & 15;
    const size_t base = ((size_t)b * S_LEN) * D_MODEL + (size_t)h * DHEAD;
    const float qscale = 0.08838834764831845f;

    for (int i = tid; i < 64 * 32; i += 256) {
        int r = i >> 5, c = (i & 31) << 2;
        float4 v = *(const float4*)(Q + base + (size_t)(qt * 64 + r) * D_MODEL + c);
        v.x *= qscale; v.y *= qscale; v.z *= qscale; v.w *= qscale;
        *(float4*)&sQ[r * 128 + c] = v;
    }

    const int oq = tid & 15;
    const int od = tid >> 4;
    const int sr = tid >> 2;
    const int sseg = tid & 3;
    const int qi = tid & 15;
    const int ki = tid >> 4;

    float mrow = -1e30f;
    float lrow = 0.0f;
    float accO[4][8];
#pragma unroll
    for (int i = 0; i < 4; i++)
#pragma unroll
        for (int j = 0; j < 8; j++) accO[i][j] = 0.0f;

    const int njt = qt + 1;
    for (int jt = 0; jt < njt; jt++) {
        __syncthreads();

        for (int i = tid; i < 64 * 32; i += 256) {
            int r = i >> 5, c = (i & 31) << 2;
            size_t g = base + (size_t)(jt * 64 + r) * D_MODEL + c;
            *(float4*)&sK[r * 128 + c] = *(const float4*)(K + g);
            *(float4*)&sV[r * 128 + c] = *(const float4*)(V + g);
        }
        __syncthreads();

        float s4[4][4];
#pragma unroll
        for (int i = 0; i < 4; i++)
#pragma unroll
            for (int j = 0; j < 4; j++) s4[i][j] = 0.0f;

#pragma unroll 8
        for (int dstep = 0; dstep < 32; dstep++) {
            int d = ((dstep + qi) & 31) << 2;
            float4 qa0 = *(const float4*)&sQ[(4 * qi + 0) * 128 + d];
            float4 qa1 = *(const float4*)&sQ[(4 * qi + 1) * 128 + d];
            float4 qa2 = *(const float4*)&sQ[(4 * qi + 2) * 128 + d];
            float4 qa3 = *(const float4*)&sQ[(4 * qi + 3) * 128 + d];
            float4 kb0 = *(const float4*)&sK[(4 * ki + 0) * 128 + d];
            float4 kb1 = *(const float4*)&sK[(4 * ki + 1) * 128 + d];
            float4 kb2 = *(const float4*)&sK[(4 * ki + 2) * 128 + d];
            float4 kb3 = *(const float4*)&sK[(4 * ki + 3) * 128 + d];
            float4 qa[4] = {qa0, qa1, qa2, qa3};
            float4 kb[4] = {kb0, kb1, kb2, kb3};
#pragma unroll
            for (int i = 0; i < 4; i++)
#pragma unroll
                for (int j = 0; j < 4; j++) {
                    float s = s4[i][j];
                    s = fmaf(qa[i].x, kb[j].x, s);
                    s = fmaf(qa[i].y, kb[j].y, s);
                    s = fmaf(qa[i].z, kb[j].z, s);
                    s = fmaf(qa[i].w, kb[j].w, s);
                    s4[i][j] = s;
                }
        }

#pragma unroll
        for (int i = 0; i < 4; i++) {
            int qg = qt * 64 + 4 * qi + i;
#pragma unroll
            for (int j = 0; j < 4; j++) {
                int kg = jt * 64 + 4 * ki + j;
                sP[(4 * qi + i) * 65 + 4 * ki + j] = (kg > qg) ? -1e30f : s4[i][j];
            }
        }
        __syncthreads();

        {
            float* prow = &sP[sr * 65 + sseg * 16];
            float mloc = -1e30f;
#pragma unroll
            for (int c = 0; c < 16; c++) mloc = fmaxf(mloc, prow[c]);
            mloc = fmaxf(mloc, __shfl_xor_sync(0xffffffffu, mloc, 1));
            mloc = fmaxf(mloc, __shfl_xor_sync(0xffffffffu, mloc, 2));
            float mnew = fmaxf(mrow, mloc);
            float corr = __expf(mrow - mnew);
            float psum = 0.0f;
#pragma unroll
            for (int c = 0; c < 16; c++) {
                float p = __expf(prow[c] - mnew);
                prow[c] = p;
                psum += p;
            }
            psum += __shfl_xor_sync(0xffffffffu, psum, 1);
            psum += __shfl_xor_sync(0xffffffffu, psum, 2);
            lrow = lrow * corr + psum;
            mrow = mnew;
            if (sseg == 0) { sScale[sr] = corr; sLrow[sr] = lrow; }
        }
        __syncthreads();

#pragma unroll
        for (int i = 0; i < 4; i++) {
            float c = sScale[4 * oq + i];
#pragma unroll
            for (int j = 0; j < 8; j++) accO[i][j] *= c;
        }
#pragma unroll 4
        for (int j = 0; j < 64; j++) {
            float4 v0 = *(const float4*)&sV[j * 128 + od * 8];
            float4 v1 = *(const float4*)&sV[j * 128 + od * 8 + 4];
#pragma unroll
            for (int i = 0; i < 4; i++) {
                float p = sP[(4 * oq + i) * 65 + j];
                accO[i][0] = fmaf(p, v0.x, accO[i][0]);
                accO[i][1] = fmaf(p, v0.y, accO[i][1]);
                accO[i][2] = fmaf(p, v0.z, accO[i][2]);
                accO[i][3] = fmaf(p, v0.w, accO[i][3]);
                accO[i][4] = fmaf(p, v1.x, accO[i][4]);
                accO[i][5] = fmaf(p, v1.y, accO[i][5]);
                accO[i][6] = fmaf(p, v1.z, accO[i][6]);
                accO[i][7] = fmaf(p, v1.w, accO[i][7]);
            }
        }
    }

#pragma unroll
    for (int i = 0; i < 4; i++) {
        int r = 4 * oq + i;
        float inv = 1.0f / sLrow[r];
        float4 o0 = make_float4(accO[i][0] * inv, accO[i][1] * inv,
                                accO[i][2] * inv, accO[i][3] * inv);
        float4 o1 = make_float4(accO[i][4] * inv, accO[i][5] * inv,
                                accO[i][6] * inv, accO[i][7] * inv);
        size_t g = base + (size_t)(qt * 64 + r) * D_MODEL + od * 8;
        *(float4*)(Y + g)     = o0;
        *(float4*)(Y + g + 4) = o1;
    }
}

// ---------------- launch ----------------
extern "C" void kernel_launch(void* const* d_in, const int* in_sizes, int n_in,
                              void* d_out, int out_size)
{
    (void)in_sizes; (void)n_in; (void)out_size;
    const float* x  = (const float*)d_in[0];
    const float* Wq = (const float*)d_in[2];
    const float* Wk = (const float*)d_in[3];
    const float* Wv = (const float*)d_in[4];
    const float* Wo = (const float*)d_in[5];
    float* out = (float*)d_out;

    float *Qb, *Kb, *Vb, *Yb;
    cudaGetSymbolAddress((void**)&Qb, g_Q);
    cudaGetSymbolAddress((void**)&Kb, g_K);
    cudaGetSymbolAddress((void**)&Vb, g_V);
    cudaGetSymbolAddress((void**)&Yb, g_Y);
    __nv_bfloat16 *xhi, *xlo, *yhi, *ylo, *whi, *wlo;
    cudaGetSymbolAddress((void**)&xhi, g_xhi);
    cudaGetSymbolAddress((void**)&xlo, g_xlo);
    cudaGetSymbolAddress((void**)&yhi, g_yhi);
    cudaGetSymbolAddress((void**)&ylo, g_ylo);
    cudaGetSymbolAddress((void**)&whi, g_whi);
    cudaGetSymbolAddress((void**)&wlo, g_wlo);

    cudaFuncSetAttribute(attn_kernel,
                         cudaFuncAttributeMaxDynamicSharedMemorySize,
                         SMEM_ATTN_BYTES);
    cudaFuncSetAttribute(gemm_bf16x3_kernel,
                         cudaFuncAttributeMaxDynamicSharedMemorySize,
                         GSMEM_TOTAL);

    // split fp32 -> bf16 hi/lo
    const int n4x = M_ROWS * D_MODEL / 4;
    const int n4w = DD / 4;
    split_bf16_kernel<<<n4x / 256, 256>>>(x, xhi, xlo, n4x);
    split_bf16_kernel<<<n4w / 256, 256>>>(Wq, whi + 0 * (size_t)DD, wlo + 0 * (size_t)DD, n4w);
    split_bf16_kernel<<<n4w / 256, 256>>>(Wk, whi + 1 * (size_t)DD, wlo + 1 * (size_t)DD, n4w);
    split_bf16_kernel<<<n4w / 256, 256>>>(Wv, whi + 2 * (size_t)DD, wlo + 2 * (size_t)DD, n4w);
    split_bf16_kernel<<<n4w / 256, 256>>>(Wo, whi + 3 * (size_t)DD, wlo + 3 * (size_t)DD, n4w);

    dim3 gGemm(D_MODEL / 128, M_ROWS / 128);   // (16, 32)
    gemm_bf16x3_kernel<<<gGemm, 256, GSMEM_TOTAL>>>(
        xhi, xlo, whi + 0 * (size_t)DD, wlo + 0 * (size_t)DD, Qb, M_ROWS, D_MODEL, D_MODEL);
    gemm_bf16x3_kernel<<<gGemm, 256, GSMEM_TOTAL>>>(
        xhi, xlo, whi + 1 * (size_t)DD, wlo + 1 * (size_t)DD, Kb, M_ROWS, D_MODEL, D_MODEL);
    gemm_bf16x3_kernel<<<gGemm, 256, GSMEM_TOTAL>>>(
        xhi, xlo, whi + 2 * (size_t)DD, wlo + 2 * (size_t)DD, Vb, M_ROWS, D_MODEL, D_MODEL);

    attn_kernel<<<dim3(S_LEN / 64, NBATCH * NHEADS), 256, SMEM_ATTN_BYTES>>>(Qb, Kb, Vb, Yb);

    split_bf16_kernel<<<n4x / 256, 256>>>(Yb, yhi, ylo, n4x);
    gemm_bf16x3_kernel<<<gGemm, 256, GSMEM_TOTAL>>>(
        yhi, ylo, whi + 3 * (size_t)DD, wlo + 3 * (size_t)DD, out, M_ROWS, D_MODEL, D_MODEL);
}

// round 4
// speedup vs baseline: 5.6682x; 1.4134x over previous
#include <cuda_runtime.h>
#include <cuda_bf16.h>
#include <math.h>
#include <stdint.h>

#if defined(__CUDA_ARCH__)
#if defined(__CUDA_ARCH_FEAT_SM103_ALL) || defined(__CUDA_ARCH_FEAT_SM100_ALL) || defined(__CUDA_ARCH_FEAT_SM101_ALL)
#define TCGEN05_OK 1
#else
#define TCGEN05_OK 0
#endif
#else
#define TCGEN05_OK 0
#endif

#define NBATCH  2
#define S_LEN   2048
#define D_MODEL 2048
#define NHEADS  16
#define DHEAD   128
#define M_ROWS  (NBATCH * S_LEN)   // 4096
#define DD      (D_MODEL * D_MODEL)

// ---------------- scratch (allocation-free: __device__ globals) ----------------
__device__ float g_V[(size_t)M_ROWS * D_MODEL];

__device__ __nv_bfloat16 g_xhi[(size_t)M_ROWS * D_MODEL];
__device__ __nv_bfloat16 g_xlo[(size_t)M_ROWS * D_MODEL];
__device__ __nv_bfloat16 g_yhi[(size_t)M_ROWS * D_MODEL];
__device__ __nv_bfloat16 g_ylo[(size_t)M_ROWS * D_MODEL];
__device__ __nv_bfloat16 g_whi[(size_t)4 * DD];
__device__ __nv_bfloat16 g_wlo[(size_t)4 * DD];
__device__ __nv_bfloat16 g_qhi[(size_t)M_ROWS * D_MODEL];
__device__ __nv_bfloat16 g_qlo[(size_t)M_ROWS * D_MODEL];
__device__ __nv_bfloat16 g_khi[(size_t)M_ROWS * D_MODEL];
__device__ __nv_bfloat16 g_klo[(size_t)M_ROWS * D_MODEL];
__device__ __nv_bfloat16 g_vthi[(size_t)M_ROWS * D_MODEL];  // [b*2048+dg][s]
__device__ __nv_bfloat16 g_vtlo[(size_t)M_ROWS * D_MODEL];

// ---------------- PTX helpers (stubbed in non-'a' PTX passes) ----------------
__device__ __forceinline__ uint32_t smem_u32(const void* p) {
    uint32_t a;
    asm("{ .reg .u64 t; cvta.to.shared.u64 t, %1; cvt.u32.u64 %0, t; }"
        : "=r"(a) : "l"(p));
    return a;
}

__device__ __forceinline__ uint32_t elect1() {
#if TCGEN05_OK
    uint32_t p;
    asm volatile(
        "{\n\t.reg .pred p;\n\t"
        "elect.sync _|p, 0xFFFFFFFF;\n\t"
        "selp.b32 %0, 1, 0, p;\n\t}"
        : "=r"(p));
    return p;
#else
    return 0;
#endif
}

__device__ __forceinline__ void mbar_init(uint32_t addr, uint32_t count) {
    asm volatile("mbarrier.init.shared.b64 [%0], %1;" :: "r"(addr), "r"(count) : "memory");
}
__device__ __forceinline__ void mbar_inval(uint32_t addr) {
    asm volatile("mbarrier.inval.shared.b64 [%0];" :: "r"(addr) : "memory");
}
__device__ __forceinline__ void mbar_wait(uint32_t addr, uint32_t parity) {
    asm volatile(
        "{\n\t.reg .pred P;\n\t"
        "WL_%=:\n\t"
        "mbarrier.try_wait.parity.acquire.cta.shared::cta.b64 P, [%0], %1, 0x989680;\n\t"
        "@P bra.uni WD_%=;\n\t"
        "bra.uni WL_%=;\n\t"
        "WD_%=:\n\t}"
        :: "r"(addr), "r"(parity) : "memory");
}

__device__ __forceinline__ void tmem_alloc(uint32_t smem_dst, uint32_t ncols) {
#if TCGEN05_OK
    asm volatile("tcgen05.alloc.cta_group::1.sync.aligned.shared::cta.b32 [%0], %1;"
                 :: "r"(smem_dst), "r"(ncols) : "memory");
#endif
}
__device__ __forceinline__ void tmem_dealloc(uint32_t tmem, uint32_t ncols) {
#if TCGEN05_OK
    asm volatile("tcgen05.dealloc.cta_group::1.sync.aligned.b32 %0, %1;"
                 :: "r"(tmem), "r"(ncols));
#endif
}
__device__ __forceinline__ void tmem_relinquish() {
#if TCGEN05_OK
    asm volatile("tcgen05.relinquish_alloc_permit.cta_group::1.sync.aligned;");
#endif
}

__device__ __forceinline__ void mma_f16_ss(uint32_t d_tmem, uint64_t a_desc,
                                           uint64_t b_desc, uint32_t idesc,
                                           uint32_t enable_d) {
#if TCGEN05_OK
    asm volatile(
        "{\n\t.reg .pred p;\n\t"
        "setp.ne.u32 p, %4, 0;\n\t"
        "tcgen05.mma.cta_group::1.kind::f16 [%0], %1, %2, %3, {%5, %5, %5, %5}, p;\n\t}"
        :: "r"(d_tmem), "l"(a_desc), "l"(b_desc), "r"(idesc), "r"(enable_d), "r"(0u)
        : "memory");
#endif
}

__device__ __forceinline__ void mma_commit(uint32_t mbar_addr) {
#if TCGEN05_OK
    asm volatile(
        "tcgen05.commit.cta_group::1.mbarrier::arrive::one.shared::cluster.b64 [%0];"
        :: "r"(mbar_addr) : "memory");
#endif
}

__device__ __forceinline__ void tcg_fence_after() {
#if TCGEN05_OK
    asm volatile("tcgen05.fence::after_thread_sync;" ::: "memory");
#endif
}
__device__ __forceinline__ void fence_proxy_async_s() {
    asm volatile("fence.proxy.async.shared::cta;" ::: "memory");
}
__device__ __forceinline__ void tcg_wait_ld() {
#if TCGEN05_OK
    asm volatile("tcgen05.wait::ld.sync.aligned;" ::: "memory");
#endif
}

__device__ __forceinline__ void ldtm_x32(uint32_t* r, uint32_t addr) {
#if TCGEN05_OK
    asm volatile(
        "tcgen05.ld.sync.aligned.32x32b.x32.b32 "
        "{%0, %1, %2, %3, %4, %5, %6, %7, "
        " %8, %9, %10, %11, %12, %13, %14, %15, "
        " %16, %17, %18, %19, %20, %21, %22, %23, "
        " %24, %25, %26, %27, %28, %29, %30, %31}, [%32];"
        : "=r"(r[0]),  "=r"(r[1]),  "=r"(r[2]),  "=r"(r[3]),
          "=r"(r[4]),  "=r"(r[5]),  "=r"(r[6]),  "=r"(r[7]),
          "=r"(r[8]),  "=r"(r[9]),  "=r"(r[10]), "=r"(r[11]),
          "=r"(r[12]), "=r"(r[13]), "=r"(r[14]), "=r"(r[15]),
          "=r"(r[16]), "=r"(r[17]), "=r"(r[18]), "=r"(r[19]),
          "=r"(r[20]), "=r"(r[21]), "=r"(r[22]), "=r"(r[23]),
          "=r"(r[24]), "=r"(r[25]), "=r"(r[26]), "=r"(r[27]),
          "=r"(r[28]), "=r"(r[29]), "=r"(r[30]), "=r"(r[31])
        : "r"(addr));
#else
    for (int i = 0; i < 32; i++) r[i] = 0;
#endif
}

// SW128 smem descriptor base: layout=SW128(2), version=1, SBO=64, LBO=1
#define DESC_BASE ((2ull << 61) | (1ull << 46) | (64ull << 32) | (1ull << 16))

// idesc kind::f16: dtype=F32, a/b=BF16
#define IDESC_N128 ((1u << 4) | (1u << 7) | (1u << 10) | (16u << 17) | (8u << 24))
#define IDESC_N64  ((1u << 4) | (1u << 7) | (1u << 10) | (8u << 17)  | (8u << 24))

__device__ __forceinline__ uint32_t sw128(uint32_t bo) {
    return bo ^ ((bo >> 3) & 0x70);
}
__device__ __forceinline__ uint32_t pack_bf2(float a, float b) {
    __nv_bfloat162 v;
    v.x = __float2bfloat16(a);
    v.y = __float2bfloat16(b);
    return *(uint32_t*)&v;
}

// ---------------- fp32 -> (hi, lo) bf16 split ----------------
__global__ __launch_bounds__(256) void split_bf16_kernel(
    const float* __restrict__ src,
    __nv_bfloat16* __restrict__ hi, __nv_bfloat16* __restrict__ lo, int n4)
{
    int i = blockIdx.x * 256 + threadIdx.x;
    if (i >= n4) return;
    float4 v = ((const float4*)src)[i];
    __nv_bfloat16 h0 = __float2bfloat16(v.x);
    __nv_bfloat16 h1 = __float2bfloat16(v.y);
    __nv_bfloat16 h2 = __float2bfloat16(v.z);
    __nv_bfloat16 h3 = __float2bfloat16(v.w);
    __nv_bfloat16 l0 = __float2bfloat16(v.x - __bfloat162float(h0));
    __nv_bfloat16 l1 = __float2bfloat16(v.y - __bfloat162float(h1));
    __nv_bfloat16 l2 = __float2bfloat16(v.z - __bfloat162float(h2));
    __nv_bfloat16 l3 = __float2bfloat16(v.w - __bfloat162float(h3));
    __nv_bfloat162* hp = (__nv_bfloat162*)hi;
    __nv_bfloat162* lp = (__nv_bfloat162*)lo;
    __nv_bfloat162 a, b;
    a.x = h0; a.y = h1; b.x = h2; b.y = h3;
    hp[2 * i] = a; hp[2 * i + 1] = b;
    a.x = l0; a.y = l1; b.x = l2; b.y = l3;
    lp[2 * i] = a; lp[2 * i + 1] = b;
}

// ---------------- V transpose + split: vt[b*2048+dg][s] ----------------
__global__ __launch_bounds__(256) void vtrans_kernel(
    const float* __restrict__ V,
    __nv_bfloat16* __restrict__ vthi, __nv_bfloat16* __restrict__ vtlo)
{
    __shared__ float t[32][33];
    const int b  = blockIdx.z;
    const int s0 = blockIdx.x * 32;
    const int d0 = blockIdx.y * 32;
    const int tx = threadIdx.x;
    const int ty = threadIdx.y;
#pragma unroll
    for (int i = 0; i < 4; i++) {
        int s = s0 + ty + i * 8;
        t[ty + i * 8][tx] = V[((size_t)b * S_LEN + s) * D_MODEL + d0 + tx];
    }
    __syncthreads();
#pragma unroll
    for (int i = 0; i < 4; i++) {
        int d = d0 + ty + i * 8;
        float v = t[tx][ty + i * 8];
        __nv_bfloat16 h = __float2bfloat16(v);
        __nv_bfloat16 l = __float2bfloat16(v - __bfloat162float(h));
        size_t o = ((size_t)b * D_MODEL + d) * S_LEN + s0 + tx;
        vthi[o] = h;
        vtlo[o] = l;
    }
}

// ---------------- tcgen05 GEMM: C = A @ B^T, 3-term bf16 split ----------------
// epilogue: if Chi != null, write (hi, lo) bf16 of scale*C; else write fp32 C.
#define OFF_A0 1024
#define OFF_B0 (1024 + 16384)
#define OFF_A1 (1024 + 2 * 16384)
#define OFF_B1 (1024 + 3 * 16384)
#define GSMEM_TOTAL (1024 + 4 * 16384)

__global__ __launch_bounds__(256) void gemm_bf16x3_kernel(
    const __nv_bfloat16* __restrict__ Ahi, const __nv_bfloat16* __restrict__ Alo,
    const __nv_bfloat16* __restrict__ Bhi, const __nv_bfloat16* __restrict__ Blo,
    float* __restrict__ C,
    __nv_bfloat16* __restrict__ Chi, __nv_bfloat16* __restrict__ Clo,
    float scale, int M, int N, int K)
{
#if TCGEN05_OK
    extern __shared__ char smem[];
    const uint32_t sb = smem_u32(smem);
    const int tid = threadIdx.x;
    const int wid = tid >> 5;
    const int lid = tid & 31;
    const int bm = blockIdx.y * 128;
    const int bn = blockIdx.x * 128;

    if (wid == 0) {
        tmem_alloc(sb, 128);
        tmem_relinquish();
    }
    if (tid == 0) {
        mbar_init(sb + 8, 1);
        mbar_init(sb + 16, 1);
    }
    __syncthreads();
    uint32_t tmem;
    asm volatile("ld.shared.b32 %0, [%1];" : "=r"(tmem) : "r"(sb));

    const int nk = K / 64;
    const int nchunks = 3 * nk;
    uint32_t ph0 = 0, ph1 = 0;

    for (int i = 0; i < nchunks; i++) {
        const int term = i / nk;
        const int k0 = (i - term * nk) * 64;
        const __nv_bfloat16* As = (term == 2) ? Alo : Ahi;
        const __nv_bfloat16* Bs = (term == 1) ? Blo : Bhi;

        uint4 ra[4], rb[4];
#pragma unroll
        for (int j = 0; j < 4; j++) {
            int u = tid + j * 256;
            int r = u >> 3, cs = u & 7;
            ra[j] = *(const uint4*)(As + (size_t)(bm + r) * K + k0 + cs * 8);
            rb[j] = *(const uint4*)(Bs + (size_t)(bn + r) * K + k0 + cs * 8);
        }

        const int buf = i & 1;
        if (i >= 2) {
            if (buf == 0) { mbar_wait(sb + 8, ph0);  ph0 ^= 1; }
            else          { mbar_wait(sb + 16, ph1); ph1 ^= 1; }
        }
        const uint32_t offA = buf ? OFF_A1 : OFF_A0;
        const uint32_t offB = buf ? OFF_B1 : OFF_B0;
#pragma unroll
        for (int j = 0; j < 4; j++) {
            int u = tid + j * 256;
            uint32_t sw = sw128((uint32_t)u * 16u);
            *(uint4*)(smem + offA + sw) = ra[j];
            *(uint4*)(smem + offB + sw) = rb[j];
        }
        __syncthreads();

        if (wid == 0 && elect1()) {
            fence_proxy_async_s();
            uint64_t ad = DESC_BASE | ((uint64_t)((sb + offA) >> 4) & 0x3FFF);
            uint64_t bd = DESC_BASE | ((uint64_t)((sb + offB) >> 4) & 0x3FFF);
#pragma unroll
            for (int k = 0; k < 4; k++) {
                uint32_t en = !(i == 0 && k == 0);
                mma_f16_ss(tmem, ad + k * 2, bd + k * 2, IDESC_N128, en);
            }
            mma_commit(buf ? (sb + 16) : (sb + 8));
        }
    }

    mbar_wait(sb + 16, ph1);
    tcg_fence_after();

    if (wid < 4) {
        const size_t row = (size_t)(bm + wid * 32 + lid);
#pragma unroll
        for (int cb = 0; cb < 128; cb += 32) {
            uint32_t dr[32];
            ldtm_x32(dr, tmem + cb);
            tcg_wait_ld();
            if (Chi) {
                __nv_bfloat16* hrow = Chi + row * (size_t)N + bn + cb;
                __nv_bfloat16* lrow = Clo + row * (size_t)N + bn + cb;
#pragma unroll
                for (int c = 0; c < 32; c += 2) {
                    float v0 = __uint_as_float(dr[c]) * scale;
                    float v1 = __uint_as_float(dr[c + 1]) * scale;
                    __nv_bfloat16 h0 = __float2bfloat16(v0);
                    __nv_bfloat16 h1 = __float2bfloat16(v1);
                    __nv_bfloat162 hp; hp.x = h0; hp.y = h1;
                    __nv_bfloat162 lp;
                    lp.x = __float2bfloat16(v0 - __bfloat162float(h0));
                    lp.y = __float2bfloat16(v1 - __bfloat162float(h1));
                    *(__nv_bfloat162*)(hrow + c) = hp;
                    *(__nv_bfloat162*)(lrow + c) = lp;
                }
            } else {
                float* crow = C + row * (size_t)N + bn;
#pragma unroll
                for (int c = 0; c < 32; c += 4) {
                    float4 v = make_float4(__uint_as_float(dr[c]),
                                           __uint_as_float(dr[c + 1]),
                                           __uint_as_float(dr[c + 2]),
                                           __uint_as_float(dr[c + 3]));
                    *(float4*)(crow + cb + c) = v;
                }
            }
        }
    }
    __syncthreads();
    if (tid == 0) { mbar_inval(sb + 8); mbar_inval(sb + 16); }
    if (wid == 0) tmem_dealloc(tmem, 128);
#endif
}

// ---------------- tcgen05 flash attention ----------------
// q-tile 128, kv-tile 64; 3-term split for QK^T and PV; O in registers.
// smem map (bytes, 1024-aligned tiles):
#define AT_RED   128          // float[256] reduction buffer
#define AT_QHI   2048         // [128][128] bf16, blocked atoms (2 atom cols)
#define AT_QLO   (AT_QHI + 32768)
#define AT_KHI   (AT_QLO + 32768)     // [64][128] bf16
#define AT_KLO   (AT_KHI + 16384)
#define AT_VTHI  (AT_KLO + 16384)     // [128 d][64 kv] bf16
#define AT_VTLO  (AT_VTHI + 16384)
#define AT_PHI   (AT_VTLO + 16384)    // [128 q][64 kv] bf16
#define AT_PLO   (AT_PHI + 16384)
#define AT_TOTAL (AT_PLO + 16384)     // 165888
#define AT_STAGE AT_KHI               // fp32 staging [128][132] reuses K/VT region

__global__ __launch_bounds__(256) void attn_tc_kernel(
    const __nv_bfloat16* __restrict__ Qhi, const __nv_bfloat16* __restrict__ Qlo,
    const __nv_bfloat16* __restrict__ Khi, const __nv_bfloat16* __restrict__ Klo,
    const __nv_bfloat16* __restrict__ VThi, const __nv_bfloat16* __restrict__ VTlo,
    __nv_bfloat16* __restrict__ Yhi, __nv_bfloat16* __restrict__ Ylo)
{
#if TCGEN05_OK
    extern __shared__ char smem[];
    const uint32_t sb = smem_u32(smem);
    const int tid = threadIdx.x;
    const int w   = tid >> 5;
    const int l   = tid & 31;
    const int r   = (w & 3) * 32 + l;     // q row within tile / TMEM lane
    const int hf  = w >> 2;               // column half
    const int qt  = blockIdx.x;           // 0..15 (128-row q tiles)
    const int bh  = blockIdx.y;           // 0..31
    const int b   = bh >> 4;
    const int h   = bh & 15;
    const uint32_t woff = (uint32_t)(w & 3) << 21;

    if (w == 0) {
        tmem_alloc(sb, 256);
        tmem_relinquish();
    }
    if (tid == 0) {
        mbar_init(sb + 8, 1);    // mbarS
        mbar_init(sb + 16, 1);   // mbarO
    }
    __syncthreads();
    uint32_t tmem;
    asm volatile("ld.shared.b32 %0, [%1];" : "=r"(tmem) : "r"(sb));
    const uint32_t S_T = tmem;          // cols 0..63
    const uint32_t O_T = tmem + 64;     // cols 64..191

    // ---- load Q tile (hi+lo), blocked-atom SW128, 2 atom cols ----
#pragma unroll
    for (int j = 0; j < 8; j++) {
        int u = tid + j * 256;           // 0..2047 16B-units
        int row = u >> 4, cu = u & 15;
        size_t g = ((size_t)(b * S_LEN + qt * 128 + row)) * D_MODEL + h * DHEAD + cu * 8;
        uint32_t bo = ((uint32_t)(row >> 3) + ((uint32_t)(cu >> 3) << 4)) * 1024u
                    + (uint32_t)(row & 7) * 128u + (uint32_t)(cu & 7) * 16u;
        uint32_t sw = sw128(bo);
        *(uint4*)(smem + AT_QHI + sw) = *(const uint4*)(Qhi + g);
        *(uint4*)(smem + AT_QLO + sw) = *(const uint4*)(Qlo + g);
    }

    const int qg = qt * 128 + r;          // global q row
    float m_run = -1e30f, l_run = 0.0f;
    float O[64];
#pragma unroll
    for (int j = 0; j < 64; j++) O[j] = 0.0f;

    uint32_t phS = 0, phO = 0;
    const int njt = 2 * qt + 2;

    for (int jt = 0; jt < njt; jt++) {
        __syncthreads();   // smem tiles free (prev PV awaited at loop bottom)

        // ---- fill K (hi/lo) [64][128] and VT (hi/lo) [128][64] ----
#pragma unroll
        for (int j = 0; j < 4; j++) {
            int u = tid + j * 256;               // 0..1023
            {   // K tile: row=kv, 16 units/row
                int row = u >> 4, cu = u & 15;
                size_t g = ((size_t)(b * S_LEN + jt * 64 + row)) * D_MODEL + h * DHEAD + cu * 8;
                uint32_t bo = ((uint32_t)(row >> 3) + ((uint32_t)(cu >> 3) << 3)) * 1024u
                            + (uint32_t)(row & 7) * 128u + (uint32_t)(cu & 7) * 16u;
                uint32_t sw = sw128(bo);
                *(uint4*)(smem + AT_KHI + sw) = *(const uint4*)(Khi + g);
                *(uint4*)(smem + AT_KLO + sw) = *(const uint4*)(Klo + g);
            }
            {   // VT tile: row=d, 8 units/row
                int row = u >> 3, cu = u & 7;
                size_t g = ((size_t)(bh * DHEAD + row)) * S_LEN + jt * 64 + cu * 8;
                uint32_t bo = (uint32_t)(row >> 3) * 1024u
                            + (uint32_t)(row & 7) * 128u + (uint32_t)cu * 16u;
                uint32_t sw = sw128(bo);
                *(uint4*)(smem + AT_VTHI + sw) = *(const uint4*)(VThi + g);
                *(uint4*)(smem + AT_VTLO + sw) = *(const uint4*)(VTlo + g);
            }
        }
        __syncthreads();

        // ---- QK^T: S[128q x 64kv] = Qhi.Khi + Qhi.Klo + Qlo.Khi ----
        if (w == 0 && elect1()) {
            fence_proxy_async_s();
            uint64_t dQh = DESC_BASE | ((uint64_t)((sb + AT_QHI) >> 4) & 0x3FFF);
            uint64_t dQl = DESC_BASE | ((uint64_t)((sb + AT_QLO) >> 4) & 0x3FFF);
            uint64_t dKh = DESC_BASE | ((uint64_t)((sb + AT_KHI) >> 4) & 0x3FFF);
            uint64_t dKl = DESC_BASE | ((uint64_t)((sb + AT_KLO) >> 4) & 0x3FFF);
            const uint64_t qo[8] = {0, 2, 4, 6, 1024, 1026, 1028, 1030};
            const uint64_t ko[8] = {0, 2, 4, 6, 512, 514, 516, 518};
            uint64_t aT[3] = {dQh, dQh, dQl};
            uint64_t bT[3] = {dKh, dKl, dKh};
#pragma unroll
            for (int t = 0; t < 3; t++)
#pragma unroll
                for (int s = 0; s < 8; s++)
                    mma_f16_ss(S_T, aT[t] + qo[s], bT[t] + ko[s], IDESC_N64,
                               !(t == 0 && s == 0));
            mma_commit(sb + 8);
        }
        mbar_wait(sb + 8, phS); phS ^= 1;
        tcg_fence_after();

        // ---- softmax (each thread: its row, 32 cols of half hf) ----
        uint32_t sr[32];
        ldtm_x32(sr, S_T + hf * 32 + woff);
        tcg_wait_ld();
        float sv[32];
        const int kgb = jt * 64 + hf * 32;
#pragma unroll
        for (int i = 0; i < 32; i++) {
            float s = __uint_as_float(sr[i]);
            sv[i] = (kgb + i > qg) ? -1e30f : s;
        }
        float tmax = -1e30f;
#pragma unroll
        for (int i = 0; i < 32; i++) tmax = fmaxf(tmax, sv[i]);
        float* red = (float*)(smem + AT_RED);
        red[hf * 128 + r] = tmax;
        __syncthreads();
        tmax = fmaxf(tmax, red[(1 - hf) * 128 + r]);
        float mnew = fmaxf(m_run, tmax);
        float corr = __expf(m_run - mnew);
        float p[32], psum = 0.0f;
#pragma unroll
        for (int i = 0; i < 32; i++) {
            p[i] = __expf(sv[i] - mnew);
            psum += p[i];
        }
        __syncthreads();   // red reuse
        red[hf * 128 + r] = psum;
        __syncthreads();
        float ptot = psum + red[(1 - hf) * 128 + r];
        l_run = l_run * corr + ptot;
        m_run = mnew;

        // ---- P -> bf16 hi/lo into smem ----
        {
            uint32_t rowbase = (uint32_t)(r >> 3) * 1024u + (uint32_t)(r & 7) * 128u;
#pragma unroll
            for (int i = 0; i < 32; i += 2) {
                float p0 = p[i], p1 = p[i + 1];
                __nv_bfloat16 h0 = __float2bfloat16(p0);
                __nv_bfloat16 h1 = __float2bfloat16(p1);
                __nv_bfloat162 hp; hp.x = h0; hp.y = h1;
                __nv_bfloat162 lp;
                lp.x = __float2bfloat16(p0 - __bfloat162float(h0));
                lp.y = __float2bfloat16(p1 - __bfloat162float(h1));
                uint32_t sw = sw128(rowbase + (uint32_t)(hf * 32 + i) * 2u);
                *(uint32_t*)(smem + AT_PHI + sw) = *(uint32_t*)&hp;
                *(uint32_t*)(smem + AT_PLO + sw) = *(uint32_t*)&lp;
            }
        }
        // rescale O while P stores land
#pragma unroll
        for (int j = 0; j < 64; j++) O[j] *= corr;
        __syncthreads();

        // ---- PV: Ot[128q x 128d] = Phi.Vhi + Phi.Vlo + Plo.Vhi ----
        if (w == 0 && elect1()) {
            fence_proxy_async_s();
            uint64_t dPh = DESC_BASE | ((uint64_t)((sb + AT_PHI) >> 4) & 0x3FFF);
            uint64_t dPl = DESC_BASE | ((uint64_t)((sb + AT_PLO) >> 4) & 0x3FFF);
            uint64_t dVh = DESC_BASE | ((uint64_t)((sb + AT_VTHI) >> 4) & 0x3FFF);
            uint64_t dVl = DESC_BASE | ((uint64_t)((sb + AT_VTLO) >> 4) & 0x3FFF);
            uint64_t aT[3] = {dPh, dPh, dPl};
            uint64_t bT[3] = {dVh, dVl, dVh};
#pragma unroll
            for (int t = 0; t < 3; t++)
#pragma unroll
                for (int s = 0; s < 4; s++)
                    mma_f16_ss(O_T, aT[t] + 2 * s, bT[t] + 2 * s, IDESC_N128,
                               !(t == 0 && s == 0));
            mma_commit(sb + 16);
        }
        mbar_wait(sb + 16, phO); phO ^= 1;
        tcg_fence_after();

        // ---- accumulate PV tile into O regs ----
        {
            uint32_t o0[32], o1[32];
            ldtm_x32(o0, O_T + hf * 64 + woff);
            ldtm_x32(o1, O_T + hf * 64 + 32 + woff);
            tcg_wait_ld();
#pragma unroll
            for (int j = 0; j < 32; j++) {
                O[j]      += __uint_as_float(o0[j]);
                O[32 + j] += __uint_as_float(o1[j]);
            }
        }
    }

    // ---- normalize + stage + write hi/lo bf16 ----
    {
        float inv = 1.0f / l_run;
        float* st = (float*)(smem + AT_STAGE);
#pragma unroll
        for (int j = 0; j < 64; j += 4) {
            float4 v = make_float4(O[j] * inv, O[j + 1] * inv,
                                   O[j + 2] * inv, O[j + 3] * inv);
            *(float4*)(st + r * 132 + hf * 64 + j) = v;
        }
    }
    __syncthreads();
    {
        const float* st = (const float*)(smem + AT_STAGE);
#pragma unroll
        for (int j = 0; j < 16; j++) {
            int u = tid + j * 256;           // 0..4095 float4 units
            int row = u >> 5, c4 = u & 31;
            float4 v = *(const float4*)(st + row * 132 + c4 * 4);
            size_t g = ((size_t)(b * S_LEN + qt * 128 + row)) * D_MODEL + h * DHEAD + c4 * 4;
            __nv_bfloat16 h0 = __float2bfloat16(v.x);
            __nv_bfloat16 h1 = __float2bfloat16(v.y);
            __nv_bfloat16 h2 = __float2bfloat16(v.z);
            __nv_bfloat16 h3 = __float2bfloat16(v.w);
            uint2 hh, ll;
            hh.x = pack_bf2(v.x, v.y); hh.y = pack_bf2(v.z, v.w);
            ll.x = pack_bf2(v.x - __bfloat162float(h0), v.y - __bfloat162float(h1));
            ll.y = pack_bf2(v.z - __bfloat162float(h2), v.w - __bfloat162float(h3));
            *(uint2*)(Yhi + g) = hh;
            *(uint2*)(Ylo + g) = ll;
        }
    }
    __syncthreads();
    if (tid == 0) { mbar_inval(sb + 8); mbar_inval(sb + 16); }
    if (w == 0) tmem_dealloc(tmem, 256);
#endif
}

// ---------------- launch ----------------
extern "C" void kernel_launch(void* const* d_in, const int* in_sizes, int n_in,
                              void* d_out, int out_size)
{
    (void)in_sizes; (void)n_in; (void)out_size;
    const float* x  = (const float*)d_in[0];
    const float* Wq = (const float*)d_in[2];
    const float* Wk = (const float*)d_in[3];
    const float* Wv = (const float*)d_in[4];
    const float* Wo = (const float*)d_in[5];
    float* out = (float*)d_out;

    float* Vb;
    cudaGetSymbolAddress((void**)&Vb, g_V);
    __nv_bfloat16 *xhi, *xlo, *yhi, *ylo, *whi, *wlo;
    __nv_bfloat16 *qhi, *qlo, *khi, *klo, *vthi, *vtlo;
    cudaGetSymbolAddress((void**)&xhi, g_xhi);
    cudaGetSymbolAddress((void**)&xlo, g_xlo);
    cudaGetSymbolAddress((void**)&yhi, g_yhi);
    cudaGetSymbolAddress((void**)&ylo, g_ylo);
    cudaGetSymbolAddress((void**)&whi, g_whi);
    cudaGetSymbolAddress((void**)&wlo, g_wlo);
    cudaGetSymbolAddress((void**)&qhi, g_qhi);
    cudaGetSymbolAddress((void**)&qlo, g_qlo);
    cudaGetSymbolAddress((void**)&khi, g_khi);
    cudaGetSymbolAddress((void**)&klo, g_klo);
    cudaGetSymbolAddress((void**)&vthi, g_vthi);
    cudaGetSymbolAddress((void**)&vtlo, g_vtlo);

    cudaFuncSetAttribute(gemm_bf16x3_kernel,
                         cudaFuncAttributeMaxDynamicSharedMemorySize, GSMEM_TOTAL);
    cudaFuncSetAttribute(attn_tc_kernel,
                         cudaFuncAttributeMaxDynamicSharedMemorySize, AT_TOTAL);

    const int n4x = M_ROWS * D_MODEL / 4;
    const int n4w = DD / 4;
    split_bf16_kernel<<<n4x / 256, 256>>>(x, xhi, xlo, n4x);
    split_bf16_kernel<<<n4w / 256, 256>>>(Wq, whi + 0 * (size_t)DD, wlo + 0 * (size_t)DD, n4w);
    split_bf16_kernel<<<n4w / 256, 256>>>(Wk, whi + 1 * (size_t)DD, wlo + 1 * (size_t)DD, n4w);
    split_bf16_kernel<<<n4w / 256, 256>>>(Wv, whi + 2 * (size_t)DD, wlo + 2 * (size_t)DD, n4w);
    split_bf16_kernel<<<n4w / 256, 256>>>(Wo, whi + 3 * (size_t)DD, wlo + 3 * (size_t)DD, n4w);

    const float qscale = 0.08838834764831845f;   // 1/sqrt(128)
    dim3 gGemm(D_MODEL / 128, M_ROWS / 128);
    // Q: emit pre-scaled hi/lo bf16 directly
    gemm_bf16x3_kernel<<<gGemm, 256, GSMEM_TOTAL>>>(
        xhi, xlo, whi + 0 * (size_t)DD, wlo + 0 * (size_t)DD,
        nullptr, qhi, qlo, qscale, M_ROWS, D_MODEL, D_MODEL);
    // K: hi/lo bf16
    gemm_bf16x3_kernel<<<gGemm, 256, GSMEM_TOTAL>>>(
        xhi, xlo, whi + 1 * (size_t)DD, wlo + 1 * (size_t)DD,
        nullptr, khi, klo, 1.0f, M_ROWS, D_MODEL, D_MODEL);
    // V: fp32 (transposed+split next)
    gemm_bf16x3_kernel<<<gGemm, 256, GSMEM_TOTAL>>>(
        xhi, xlo, whi + 2 * (size_t)DD, wlo + 2 * (size_t)DD,
        Vb, nullptr, nullptr, 1.0f, M_ROWS, D_MODEL, D_MODEL);

    vtrans_kernel<<<dim3(S_LEN / 32, D_MODEL / 32, NBATCH), dim3(32, 8)>>>(Vb, vthi, vtlo);

    attn_tc_kernel<<<dim3(S_LEN / 128, NBATCH * NHEADS), 256, AT_TOTAL>>>(
        qhi, qlo, khi, klo, vthi, vtlo, yhi, ylo);

    gemm_bf16x3_kernel<<<gGemm, 256, GSMEM_TOTAL>>>(
        yhi, ylo, whi + 3 * (size_t)DD, wlo + 3 * (size_t)DD,
        out, nullptr, nullptr, 1.0f, M_ROWS, D_MODEL, D_MODEL);
}

// round 5
// speedup vs baseline: 7.4482x; 1.3140x over previous
#include <cuda_runtime.h>
#include <cuda_bf16.h>
#include <math.h>
#include <stdint.h>

#if defined(__CUDA_ARCH__)
#if defined(__CUDA_ARCH_FEAT_SM103_ALL) || defined(__CUDA_ARCH_FEAT_SM100_ALL) || defined(__CUDA_ARCH_FEAT_SM101_ALL)
#define TCGEN05_OK 1
#else
#define TCGEN05_OK 0
#endif
#else
#define TCGEN05_OK 0
#endif

#define NBATCH  2
#define S_LEN   2048
#define D_MODEL 2048
#define NHEADS  16
#define DHEAD   128
#define M_ROWS  (NBATCH * S_LEN)   // 4096
#define DD      (D_MODEL * D_MODEL)

// ---------------- scratch (allocation-free: __device__ globals) ----------------
__device__ float g_V[(size_t)M_ROWS * D_MODEL];

__device__ __nv_bfloat16 g_xhi[(size_t)M_ROWS * D_MODEL];
__device__ __nv_bfloat16 g_xlo[(size_t)M_ROWS * D_MODEL];
__device__ __nv_bfloat16 g_yhi[(size_t)M_ROWS * D_MODEL];
__device__ __nv_bfloat16 g_ylo[(size_t)M_ROWS * D_MODEL];
__device__ __nv_bfloat16 g_whi[(size_t)4 * DD];
__device__ __nv_bfloat16 g_wlo[(size_t)4 * DD];
__device__ __nv_bfloat16 g_qhi[(size_t)M_ROWS * D_MODEL];
__device__ __nv_bfloat16 g_qlo[(size_t)M_ROWS * D_MODEL];
__device__ __nv_bfloat16 g_khi[(size_t)M_ROWS * D_MODEL];
__device__ __nv_bfloat16 g_klo[(size_t)M_ROWS * D_MODEL];
__device__ __nv_bfloat16 g_vthi[(size_t)M_ROWS * D_MODEL];  // [b*2048+d][s]
__device__ __nv_bfloat16 g_vtlo[(size_t)M_ROWS * D_MODEL];

// ---------------- PTX helpers (stubbed in non-'a' PTX passes) ----------------
__device__ __forceinline__ uint32_t smem_u32(const void* p) {
    uint32_t a;
    asm("{ .reg .u64 t; cvta.to.shared.u64 t, %1; cvt.u32.u64 %0, t; }"
        : "=r"(a) : "l"(p));
    return a;
}

__device__ __forceinline__ uint32_t elect1() {
#if TCGEN05_OK
    uint32_t p;
    asm volatile(
        "{\n\t.reg .pred p;\n\t"
        "elect.sync _|p, 0xFFFFFFFF;\n\t"
        "selp.b32 %0, 1, 0, p;\n\t}"
        : "=r"(p));
    return p;
#else
    return 0;
#endif
}

__device__ __forceinline__ void mbar_init(uint32_t addr, uint32_t count) {
    asm volatile("mbarrier.init.shared.b64 [%0], %1;" :: "r"(addr), "r"(count) : "memory");
}
__device__ __forceinline__ void mbar_inval(uint32_t addr) {
    asm volatile("mbarrier.inval.shared.b64 [%0];" :: "r"(addr) : "memory");
}
__device__ __forceinline__ void mbar_wait(uint32_t addr, uint32_t parity) {
    asm volatile(
        "{\n\t.reg .pred P;\n\t"
        "WL_%=:\n\t"
        "mbarrier.try_wait.parity.acquire.cta.shared::cta.b64 P, [%0], %1, 0x989680;\n\t"
        "@P bra.uni WD_%=;\n\t"
        "bra.uni WL_%=;\n\t"
        "WD_%=:\n\t}"
        :: "r"(addr), "r"(parity) : "memory");
}

__device__ __forceinline__ void tmem_alloc(uint32_t smem_dst, uint32_t ncols) {
#if TCGEN05_OK
    asm volatile("tcgen05.alloc.cta_group::1.sync.aligned.shared::cta.b32 [%0], %1;"
                 :: "r"(smem_dst), "r"(ncols) : "memory");
#endif
}
__device__ __forceinline__ void tmem_dealloc(uint32_t tmem, uint32_t ncols) {
#if TCGEN05_OK
    asm volatile("tcgen05.dealloc.cta_group::1.sync.aligned.b32 %0, %1;"
                 :: "r"(tmem), "r"(ncols));
#endif
}
__device__ __forceinline__ void tmem_relinquish() {
#if TCGEN05_OK
    asm volatile("tcgen05.relinquish_alloc_permit.cta_group::1.sync.aligned;");
#endif
}

__device__ __forceinline__ void mma_f16_ss(uint32_t d_tmem, uint64_t a_desc,
                                           uint64_t b_desc, uint32_t idesc,
                                           uint32_t enable_d) {
#if TCGEN05_OK
    asm volatile(
        "{\n\t.reg .pred p;\n\t"
        "setp.ne.u32 p, %4, 0;\n\t"
        "tcgen05.mma.cta_group::1.kind::f16 [%0], %1, %2, %3, {%5, %5, %5, %5}, p;\n\t}"
        :: "r"(d_tmem), "l"(a_desc), "l"(b_desc), "r"(idesc), "r"(enable_d), "r"(0u)
        : "memory");
#endif
}

__device__ __forceinline__ void mma_commit(uint32_t mbar_addr) {
#if TCGEN05_OK
    asm volatile(
        "tcgen05.commit.cta_group::1.mbarrier::arrive::one.shared::cluster.b64 [%0];"
        :: "r"(mbar_addr) : "memory");
#endif
}

__device__ __forceinline__ void tcg_fence_after() {
#if TCGEN05_OK
    asm volatile("tcgen05.fence::after_thread_sync;" ::: "memory");
#endif
}
__device__ __forceinline__ void fence_proxy_async_s() {
    asm volatile("fence.proxy.async.shared::cta;" ::: "memory");
}
__device__ __forceinline__ void tcg_wait_ld() {
#if TCGEN05_OK
    asm volatile("tcgen05.wait::ld.sync.aligned;" ::: "memory");
#endif
}

__device__ __forceinline__ void ldtm_x32(uint32_t* r, uint32_t addr) {
#if TCGEN05_OK
    asm volatile(
        "tcgen05.ld.sync.aligned.32x32b.x32.b32 "
        "{%0, %1, %2, %3, %4, %5, %6, %7, "
        " %8, %9, %10, %11, %12, %13, %14, %15, "
        " %16, %17, %18, %19, %20, %21, %22, %23, "
        " %24, %25, %26, %27, %28, %29, %30, %31}, [%32];"
        : "=r"(r[0]),  "=r"(r[1]),  "=r"(r[2]),  "=r"(r[3]),
          "=r"(r[4]),  "=r"(r[5]),  "=r"(r[6]),  "=r"(r[7]),
          "=r"(r[8]),  "=r"(r[9]),  "=r"(r[10]), "=r"(r[11]),
          "=r"(r[12]), "=r"(r[13]), "=r"(r[14]), "=r"(r[15]),
          "=r"(r[16]), "=r"(r[17]), "=r"(r[18]), "=r"(r[19]),
          "=r"(r[20]), "=r"(r[21]), "=r"(r[22]), "=r"(r[23]),
          "=r"(r[24]), "=r"(r[25]), "=r"(r[26]), "=r"(r[27]),
          "=r"(r[28]), "=r"(r[29]), "=r"(r[30]), "=r"(r[31])
        : "r"(addr));
#else
    for (int i = 0; i < 32; i++) r[i] = 0;
#endif
}

// SW128 smem descriptor base: layout=SW128(2), version=1, SBO=64, LBO=1
#define DESC_BASE ((2ull << 61) | (1ull << 46) | (64ull << 32) | (1ull << 16))

// idesc kind::f16: dtype=F32, a/b=BF16
#define IDESC_N128 ((1u << 4) | (1u << 7) | (1u << 10) | (16u << 17) | (8u << 24))
#define IDESC_N64  ((1u << 4) | (1u << 7) | (1u << 10) | (8u << 17)  | (8u << 24))

__device__ __forceinline__ uint32_t sw128(uint32_t bo) {
    return bo ^ ((bo >> 3) & 0x70);
}
__device__ __forceinline__ uint32_t pack_bf2(float a, float b) {
    __nv_bfloat162 v;
    v.x = __float2bfloat16(a);
    v.y = __float2bfloat16(b);
    return *(uint32_t*)&v;
}

// ---------------- fp32 -> (hi, lo) bf16 split ----------------
__global__ __launch_bounds__(256) void split_bf16_kernel(
    const float* __restrict__ src,
    __nv_bfloat16* __restrict__ hi, __nv_bfloat16* __restrict__ lo, int n4)
{
    int i = blockIdx.x * 256 + threadIdx.x;
    if (i >= n4) return;
    float4 v = ((const float4*)src)[i];
    __nv_bfloat16 h0 = __float2bfloat16(v.x);
    __nv_bfloat16 h1 = __float2bfloat16(v.y);
    __nv_bfloat16 h2 = __float2bfloat16(v.z);
    __nv_bfloat16 h3 = __float2bfloat16(v.w);
    __nv_bfloat16 l0 = __float2bfloat16(v.x - __bfloat162float(h0));
    __nv_bfloat16 l1 = __float2bfloat16(v.y - __bfloat162float(h1));
    __nv_bfloat16 l2 = __float2bfloat16(v.z - __bfloat162float(h2));
    __nv_bfloat16 l3 = __float2bfloat16(v.w - __bfloat162float(h3));
    __nv_bfloat162* hp = (__nv_bfloat162*)hi;
    __nv_bfloat162* lp = (__nv_bfloat162*)lo;
    __nv_bfloat162 a, b;
    a.x = h0; a.y = h1; b.x = h2; b.y = h3;
    hp[2 * i] = a; hp[2 * i + 1] = b;
    a.x = l0; a.y = l1; b.x = l2; b.y = l3;
    lp[2 * i] = a; lp[2 * i + 1] = b;
}

// ---------------- V transpose + split: vt[b*2048+d][s] ----------------
__global__ __launch_bounds__(256) void vtrans_kernel(
    const float* __restrict__ V,
    __nv_bfloat16* __restrict__ vthi, __nv_bfloat16* __restrict__ vtlo)
{
    __shared__ float t[32][33];
    const int b  = blockIdx.z;
    const int s0 = blockIdx.x * 32;
    const int d0 = blockIdx.y * 32;
    const int tx = threadIdx.x;
    const int ty = threadIdx.y;
#pragma unroll
    for (int i = 0; i < 4; i++) {
        int s = s0 + ty + i * 8;
        t[ty + i * 8][tx] = V[((size_t)b * S_LEN + s) * D_MODEL + d0 + tx];
    }
    __syncthreads();
#pragma unroll
    for (int i = 0; i < 4; i++) {
        int d = d0 + ty + i * 8;
        float v = t[tx][ty + i * 8];
        __nv_bfloat16 h = __float2bfloat16(v);
        __nv_bfloat16 l = __float2bfloat16(v - __bfloat162float(h));
        size_t o = ((size_t)b * D_MODEL + d) * S_LEN + s0 + tx;
        vthi[o] = h;
        vtlo[o] = l;
    }
}

// ---------------- tcgen05 GEMM: C = A @ B^T, 3-term bf16 split ----------------
#define OFF_A0 1024
#define OFF_B0 (1024 + 16384)
#define OFF_A1 (1024 + 2 * 16384)
#define OFF_B1 (1024 + 3 * 16384)
#define GSMEM_TOTAL (1024 + 4 * 16384)

__global__ __launch_bounds__(256) void gemm_bf16x3_kernel(
    const __nv_bfloat16* __restrict__ Ahi, const __nv_bfloat16* __restrict__ Alo,
    const __nv_bfloat16* __restrict__ Bhi, const __nv_bfloat16* __restrict__ Blo,
    float* __restrict__ C,
    __nv_bfloat16* __restrict__ Chi, __nv_bfloat16* __restrict__ Clo,
    float scale, int M, int N, int K)
{
#if TCGEN05_OK
    extern __shared__ char smem[];
    const uint32_t sb = smem_u32(smem);
    const int tid = threadIdx.x;
    const int wid = tid >> 5;
    const int lid = tid & 31;
    const int bm = blockIdx.y * 128;
    const int bn = blockIdx.x * 128;

    if (wid == 0) {
        tmem_alloc(sb, 128);
        tmem_relinquish();
    }
    if (tid == 0) {
        mbar_init(sb + 8, 1);
        mbar_init(sb + 16, 1);
    }
    __syncthreads();
    uint32_t tmem;
    asm volatile("ld.shared.b32 %0, [%1];" : "=r"(tmem) : "r"(sb));

    const int nk = K / 64;
    const int nchunks = 3 * nk;
    uint32_t ph0 = 0, ph1 = 0;

    for (int i = 0; i < nchunks; i++) {
        const int term = i / nk;
        const int k0 = (i - term * nk) * 64;
        const __nv_bfloat16* As = (term == 2) ? Alo : Ahi;
        const __nv_bfloat16* Bs = (term == 1) ? Blo : Bhi;

        uint4 ra[4], rb[4];
#pragma unroll
        for (int j = 0; j < 4; j++) {
            int u = tid + j * 256;
            int r = u >> 3, cs = u & 7;
            ra[j] = *(const uint4*)(As + (size_t)(bm + r) * K + k0 + cs * 8);
            rb[j] = *(const uint4*)(Bs + (size_t)(bn + r) * K + k0 + cs * 8);
        }

        const int buf = i & 1;
        if (i >= 2) {
            if (buf == 0) { mbar_wait(sb + 8, ph0);  ph0 ^= 1; }
            else          { mbar_wait(sb + 16, ph1); ph1 ^= 1; }
        }
        const uint32_t offA = buf ? OFF_A1 : OFF_A0;
        const uint32_t offB = buf ? OFF_B1 : OFF_B0;
#pragma unroll
        for (int j = 0; j < 4; j++) {
            int u = tid + j * 256;
            uint32_t sw = sw128((uint32_t)u * 16u);
            *(uint4*)(smem + offA + sw) = ra[j];
            *(uint4*)(smem + offB + sw) = rb[j];
        }
        __syncthreads();

        if (wid == 0 && elect1()) {
            fence_proxy_async_s();
            uint64_t ad = DESC_BASE | ((uint64_t)((sb + offA) >> 4) & 0x3FFF);
            uint64_t bd = DESC_BASE | ((uint64_t)((sb + offB) >> 4) & 0x3FFF);
#pragma unroll
            for (int k = 0; k < 4; k++) {
                uint32_t en = !(i == 0 && k == 0);
                mma_f16_ss(tmem, ad + k * 2, bd + k * 2, IDESC_N128, en);
            }
            mma_commit(buf ? (sb + 16) : (sb + 8));
        }
    }

    mbar_wait(sb + 16, ph1);
    tcg_fence_after();
    __syncthreads();     // A/B buffers dead; reuse as staging

    // coalesced epilogue via smem staging: st[128][68] fp32
    float* st = (float*)(smem + OFF_A0);
#pragma unroll
    for (int half = 0; half < 2; half++) {
        if (wid < 4) {
            uint32_t d0[32], d1[32];
            ldtm_x32(d0, tmem + half * 64);
            ldtm_x32(d1, tmem + half * 64 + 32);
            tcg_wait_ld();
            float* srow = st + (wid * 32 + lid) * 68;
#pragma unroll
            for (int c = 0; c < 32; c++) {
                srow[c]      = __uint_as_float(d0[c]);
                srow[32 + c] = __uint_as_float(d1[c]);
            }
        }
        __syncthreads();
#pragma unroll
        for (int j = 0; j < 8; j++) {
            int u = tid + j * 256;           // 2048 float4-units = 128 rows x 16
            int row = u >> 4, c4 = u & 15;
            float4 v = *(const float4*)(st + row * 68 + c4 * 4);
            size_t grow = (size_t)(bm + row);
            int gcol = bn + half * 64 + c4 * 4;
            if (Chi) {
                float v0 = v.x * scale, v1 = v.y * scale;
                float v2 = v.z * scale, v3 = v.w * scale;
                __nv_bfloat16 h0 = __float2bfloat16(v0);
                __nv_bfloat16 h1 = __float2bfloat16(v1);
                __nv_bfloat16 h2 = __float2bfloat16(v2);
                __nv_bfloat16 h3 = __float2bfloat16(v3);
                uint2 hh, ll;
                hh.x = pack_bf2(v0, v1); hh.y = pack_bf2(v2, v3);
                ll.x = pack_bf2(v0 - __bfloat162float(h0), v1 - __bfloat162float(h1));
                ll.y = pack_bf2(v2 - __bfloat162float(h2), v3 - __bfloat162float(h3));
                *(uint2*)(Chi + grow * N + gcol) = hh;
                *(uint2*)(Clo + grow * N + gcol) = ll;
            } else {
                *(float4*)(C + grow * N + gcol) = v;
            }
        }
        __syncthreads();
    }
    if (tid == 0) { mbar_inval(sb + 8); mbar_inval(sb + 16); }
    if (wid == 0) tmem_dealloc(tmem, 128);
#endif
}

// ---------------- tcgen05 flash attention (pipelined) ----------------
// q-tile 128, kv-tile 64, double-buffered K/V, QK(j+1) overlapped with PV(j).
#define AT_RED    1024                 // float[256] (tmax)
#define AT_RED2   2048                 // float[256] (psum)
#define AT_QHI    3072                 // [128][128] bf16, blocked atoms
#define AT_QLO    35840
#define AT_KV0    68608                // buf0: KHI | KLO(+16K) | VTHI(+32K) | VTLO(+48K)
#define AT_KV1    134144               // buf1
#define AT_PHI    199680               // [128][64] bf16
#define AT_PLO    216064
#define AT_TOTAL  232448               // 227 KB exactly
#define AT_STAGE  AT_KV0               // fp32 [128][132] output staging (reuses KV)

__device__ __forceinline__ void attn_fill(
    char* smem, uint32_t kvb,
    const __nv_bfloat16* __restrict__ Khi, const __nv_bfloat16* __restrict__ Klo,
    const __nv_bfloat16* __restrict__ VThi, const __nv_bfloat16* __restrict__ VTlo,
    int tid, int b, int bh, int h, int jt)
{
#pragma unroll
    for (int j = 0; j < 4; j++) {
        int u = tid + j * 256;               // 0..1023
        {   // K tile [64 kv][128 d]: 16 16B-units per row
            int row = u >> 4, cu = u & 15;
            size_t g = ((size_t)(b * S_LEN + jt * 64 + row)) * D_MODEL + h * DHEAD + cu * 8;
            uint32_t bo = ((uint32_t)(row >> 3) + ((uint32_t)(cu >> 3) << 3)) * 1024u
                        + (uint32_t)(row & 7) * 128u + (uint32_t)(cu & 7) * 16u;
            uint32_t sw = sw128(bo);
            *(uint4*)(smem + kvb + sw)          = *(const uint4*)(Khi + g);
            *(uint4*)(smem + kvb + 16384 + sw)  = *(const uint4*)(Klo + g);
        }
        {   // VT tile [128 d][64 kv]: 8 16B-units per row
            int row = u >> 3, cu = u & 7;
            size_t g = ((size_t)(bh * DHEAD + row)) * S_LEN + jt * 64 + cu * 8;
            uint32_t bo = (uint32_t)(row >> 3) * 1024u
                        + (uint32_t)(row & 7) * 128u + (uint32_t)cu * 16u;
            uint32_t sw = sw128(bo);
            *(uint4*)(smem + kvb + 32768 + sw)  = *(const uint4*)(VThi + g);
            *(uint4*)(smem + kvb + 49152 + sw)  = *(const uint4*)(VTlo + g);
        }
    }
}

__device__ __forceinline__ void issue_qk(uint32_t sb, uint32_t S_T, uint32_t kvb) {
    uint64_t dQh = DESC_BASE | ((uint64_t)((sb + AT_QHI) >> 4) & 0x3FFF);
    uint64_t dQl = DESC_BASE | ((uint64_t)((sb + AT_QLO) >> 4) & 0x3FFF);
    uint64_t dKh = DESC_BASE | ((uint64_t)((sb + kvb) >> 4) & 0x3FFF);
    uint64_t dKl = DESC_BASE | ((uint64_t)((sb + kvb + 16384) >> 4) & 0x3FFF);
    const uint64_t qo[8] = {0, 2, 4, 6, 1024, 1026, 1028, 1030};
    const uint64_t ko[8] = {0, 2, 4, 6, 512, 514, 516, 518};
    uint64_t aT[3] = {dQh, dQh, dQl};
    uint64_t bT[3] = {dKh, dKl, dKh};
#pragma unroll
    for (int t = 0; t < 3; t++)
#pragma unroll
        for (int s = 0; s < 8; s++)
            mma_f16_ss(S_T, aT[t] + qo[s], bT[t] + ko[s], IDESC_N64, !(t == 0 && s == 0));
    mma_commit(sb + 8);
}

__device__ __forceinline__ void issue_pv(uint32_t sb, uint32_t O_T, uint32_t kvb) {
    uint64_t dPh = DESC_BASE | ((uint64_t)((sb + AT_PHI) >> 4) & 0x3FFF);
    uint64_t dPl = DESC_BASE | ((uint64_t)((sb + AT_PLO) >> 4) & 0x3FFF);
    uint64_t dVh = DESC_BASE | ((uint64_t)((sb + kvb + 32768) >> 4) & 0x3FFF);
    uint64_t dVl = DESC_BASE | ((uint64_t)((sb + kvb + 49152) >> 4) & 0x3FFF);
    uint64_t aT[3] = {dPh, dPh, dPl};
    uint64_t bT[3] = {dVh, dVl, dVh};
#pragma unroll
    for (int t = 0; t < 3; t++)
#pragma unroll
        for (int s = 0; s < 4; s++)
            mma_f16_ss(O_T, aT[t] + 2 * s, bT[t] + 2 * s, IDESC_N128, !(t == 0 && s == 0));
    mma_commit(sb + 16);
}

__global__ __launch_bounds__(256) void attn_tc_kernel(
    const __nv_bfloat16* __restrict__ Qhi, const __nv_bfloat16* __restrict__ Qlo,
    const __nv_bfloat16* __restrict__ Khi, const __nv_bfloat16* __restrict__ Klo,
    const __nv_bfloat16* __restrict__ VThi, const __nv_bfloat16* __restrict__ VTlo,
    __nv_bfloat16* __restrict__ Yhi, __nv_bfloat16* __restrict__ Ylo)
{
#if TCGEN05_OK
    extern __shared__ char smem[];
    const uint32_t sb = smem_u32(smem);
    const int tid = threadIdx.x;
    const int w   = tid >> 5;
    const int l   = tid & 31;
    const int r   = (w & 3) * 32 + l;     // q row within tile / TMEM lane
    const int hf  = w >> 2;               // column half
    const int qt  = blockIdx.x;           // 0..15
    const int bh  = blockIdx.y;           // 0..31
    const int b   = bh >> 4;
    const int h   = bh & 15;
    const uint32_t woff = (uint32_t)(w & 3) << 21;

    if (w == 0) {
        tmem_alloc(sb, 256);
        tmem_relinquish();
    }
    if (tid == 0) {
        mbar_init(sb + 8, 1);    // S
        mbar_init(sb + 16, 1);   // O
    }
    __syncthreads();
    uint32_t tmem;
    asm volatile("ld.shared.b32 %0, [%1];" : "=r"(tmem) : "r"(sb));
    const uint32_t S_T = tmem;          // cols 0..63
    const uint32_t O_T = tmem + 64;     // cols 64..191

    // ---- load Q tile (hi+lo), blocked-atom SW128, 2 atom cols ----
#pragma unroll
    for (int j = 0; j < 8; j++) {
        int u = tid + j * 256;
        int row = u >> 4, cu = u & 15;
        size_t g = ((size_t)(b * S_LEN + qt * 128 + row)) * D_MODEL + h * DHEAD + cu * 8;
        uint32_t bo = ((uint32_t)(row >> 3) + ((uint32_t)(cu >> 3) << 4)) * 1024u
                    + (uint32_t)(row & 7) * 128u + (uint32_t)(cu & 7) * 16u;
        uint32_t sw = sw128(bo);
        *(uint4*)(smem + AT_QHI + sw) = *(const uint4*)(Qhi + g);
        *(uint4*)(smem + AT_QLO + sw) = *(const uint4*)(Qlo + g);
    }

    const int qg = qt * 128 + r;
    float m_run = -1e30f, l_run = 0.0f;
    float O[64];
#pragma unroll
    for (int j = 0; j < 64; j++) O[j] = 0.0f;

    uint32_t phS = 0, phO = 0;
    const int njt = 2 * qt + 2;

    // prologue: fill tile 0, issue QK(0)
    attn_fill(smem, AT_KV0, Khi, Klo, VThi, VTlo, tid, b, bh, h, 0);
    __syncthreads();
    if (w == 0 && elect1()) {
        fence_proxy_async_s();
        issue_qk(sb, S_T, AT_KV0);
    }

    for (int jt = 0; jt < njt; jt++) {
        const uint32_t kvb  = (jt & 1) ? AT_KV1 : AT_KV0;
        const uint32_t kvbn = (jt & 1) ? AT_KV0 : AT_KV1;

        // prefetch next kv tile into the other buffer (hidden behind S wait)
        if (jt + 1 < njt)
            attn_fill(smem, kvbn, Khi, Klo, VThi, VTlo, tid, b, bh, h, jt + 1);

        mbar_wait(sb + 8, phS); phS ^= 1;
        tcg_fence_after();

        // ---- read S, softmax ----
        uint32_t sr[32];
        ldtm_x32(sr, S_T + hf * 32 + woff);
        tcg_wait_ld();
        float sv[32];
        const int kgb = jt * 64 + hf * 32;
#pragma unroll
        for (int i = 0; i < 32; i++) {
            float s = __uint_as_float(sr[i]);
            sv[i] = (kgb + i > qg) ? -1e30f : s;
        }
        float tmax = -1e30f;
#pragma unroll
        for (int i = 0; i < 32; i++) tmax = fmaxf(tmax, sv[i]);
        float* red1 = (float*)(smem + AT_RED);
        float* red2 = (float*)(smem + AT_RED2);
        red1[hf * 128 + r] = tmax;
        __syncthreads();
        tmax = fmaxf(tmax, red1[(1 - hf) * 128 + r]);
        float mnew = fmaxf(m_run, tmax);
        float corr = __expf(m_run - mnew);
        float p[32], psum = 0.0f;
#pragma unroll
        for (int i = 0; i < 32; i++) {
            p[i] = __expf(sv[i] - mnew);
            psum += p[i];
        }
        red2[hf * 128 + r] = psum;
        __syncthreads();
        l_run = l_run * corr + psum + red2[(1 - hf) * 128 + r];
        m_run = mnew;

        // ---- P -> bf16 hi/lo into smem ----
        {
            uint32_t rowbase = (uint32_t)(r >> 3) * 1024u + (uint32_t)(r & 7) * 128u;
#pragma unroll
            for (int i = 0; i < 32; i += 2) {
                float p0 = p[i], p1 = p[i + 1];
                __nv_bfloat16 h0 = __float2bfloat16(p0);
                __nv_bfloat16 h1 = __float2bfloat16(p1);
                __nv_bfloat162 hp; hp.x = h0; hp.y = h1;
                __nv_bfloat162 lp;
                lp.x = __float2bfloat16(p0 - __bfloat162float(h0));
                lp.y = __float2bfloat16(p1 - __bfloat162float(h1));
                uint32_t sw = sw128(rowbase + (uint32_t)(hf * 32 + i) * 2u);
                *(uint32_t*)(smem + AT_PHI + sw) = *(uint32_t*)&hp;
                *(uint32_t*)(smem + AT_PLO + sw) = *(uint32_t*)&lp;
            }
        }
        __syncthreads();   // P + next-kv fill visible; all warps done reading S

        // ---- issue PV(j), then QK(j+1) back-to-back on the tensor pipe ----
        if (w == 0 && elect1()) {
            fence_proxy_async_s();
            issue_pv(sb, O_T, kvb);
            if (jt + 1 < njt) issue_qk(sb, S_T, kvbn);
        }
        mbar_wait(sb + 16, phO); phO ^= 1;
        tcg_fence_after();

        // ---- accumulate PV tile into O regs (rescale fused) ----
        {
            uint32_t o0[32];
            ldtm_x32(o0, O_T + hf * 64 + woff);
            tcg_wait_ld();
#pragma unroll
            for (int j = 0; j < 32; j++)
                O[j] = fmaf(O[j], corr, __uint_as_float(o0[j]));
            ldtm_x32(o0, O_T + hf * 64 + 32 + woff);
            tcg_wait_ld();
#pragma unroll
            for (int j = 0; j < 32; j++)
                O[32 + j] = fmaf(O[32 + j], corr, __uint_as_float(o0[j]));
        }
    }

    // ---- normalize + stage + write hi/lo bf16 (coalesced) ----
    __syncthreads();   // KV buffers dead; reuse as staging
    {
        float inv = 1.0f / l_run;
        float* st = (float*)(smem + AT_STAGE);
#pragma unroll
        for (int j = 0; j < 64; j += 4) {
            float4 v = make_float4(O[j] * inv, O[j + 1] * inv,
                                   O[j + 2] * inv, O[j + 3] * inv);
            *(float4*)(st + r * 132 + hf * 64 + j) = v;
        }
    }
    __syncthreads();
    {
        const float* st = (const float*)(smem + AT_STAGE);
#pragma unroll
        for (int j = 0; j < 16; j++) {
            int u = tid + j * 256;
            int row = u >> 5, c4 = u & 31;
            float4 v = *(const float4*)(st + row * 132 + c4 * 4);
            size_t g = ((size_t)(b * S_LEN + qt * 128 + row)) * D_MODEL + h * DHEAD + c4 * 4;
            __nv_bfloat16 h0 = __float2bfloat16(v.x);
            __nv_bfloat16 h1 = __float2bfloat16(v.y);
            __nv_bfloat16 h2 = __float2bfloat16(v.z);
            __nv_bfloat16 h3 = __float2bfloat16(v.w);
            uint2 hh, ll;
            hh.x = pack_bf2(v.x, v.y); hh.y = pack_bf2(v.z, v.w);
            ll.x = pack_bf2(v.x - __bfloat162float(h0), v.y - __bfloat162float(h1));
            ll.y = pack_bf2(v.z - __bfloat162float(h2), v.w - __bfloat162float(h3));
            *(uint2*)(Yhi + g) = hh;
            *(uint2*)(Ylo + g) = ll;
        }
    }
    __syncthreads();
    if (tid == 0) { mbar_inval(sb + 8); mbar_inval(sb + 16); }
    if (w == 0) tmem_dealloc(tmem, 256);
#endif
}

// ---------------- launch ----------------
extern "C" void kernel_launch(void* const* d_in, const int* in_sizes, int n_in,
                              void* d_out, int out_size)
{
    (void)in_sizes; (void)n_in; (void)out_size;
    const float* x  = (const float*)d_in[0];
    const float* Wq = (const float*)d_in[2];
    const float* Wk = (const float*)d_in[3];
    const float* Wv = (const float*)d_in[4];
    const float* Wo = (const float*)d_in[5];
    float* out = (float*)d_out;

    float* Vb;
    cudaGetSymbolAddress((void**)&Vb, g_V);
    __nv_bfloat16 *xhi, *xlo, *yhi, *ylo, *whi, *wlo;
    __nv_bfloat16 *qhi, *qlo, *khi, *klo, *vthi, *vtlo;
    cudaGetSymbolAddress((void**)&xhi, g_xhi);
    cudaGetSymbolAddress((void**)&xlo, g_xlo);
    cudaGetSymbolAddress((void**)&yhi, g_yhi);
    cudaGetSymbolAddress((void**)&ylo, g_ylo);
    cudaGetSymbolAddress((void**)&whi, g_whi);
    cudaGetSymbolAddress((void**)&wlo, g_wlo);
    cudaGetSymbolAddress((void**)&qhi, g_qhi);
    cudaGetSymbolAddress((void**)&qlo, g_qlo);
    cudaGetSymbolAddress((void**)&khi, g_khi);
    cudaGetSymbolAddress((void**)&klo, g_klo);
    cudaGetSymbolAddress((void**)&vthi, g_vthi);
    cudaGetSymbolAddress((void**)&vtlo, g_vtlo);

    cudaFuncSetAttribute(gemm_bf16x3_kernel,
                         cudaFuncAttributeMaxDynamicSharedMemorySize, GSMEM_TOTAL);
    cudaFuncSetAttribute(attn_tc_kernel,
                         cudaFuncAttributeMaxDynamicSharedMemorySize, AT_TOTAL);

    const int n4x = M_ROWS * D_MODEL / 4;
    const int n4w = DD / 4;
    split_bf16_kernel<<<n4x / 256, 256>>>(x, xhi, xlo, n4x);
    split_bf16_kernel<<<n4w / 256, 256>>>(Wq, whi + 0 * (size_t)DD, wlo + 0 * (size_t)DD, n4w);
    split_bf16_kernel<<<n4w / 256, 256>>>(Wk, whi + 1 * (size_t)DD, wlo + 1 * (size_t)DD, n4w);
    split_bf16_kernel<<<n4w / 256, 256>>>(Wv, whi + 2 * (size_t)DD, wlo + 2 * (size_t)DD, n4w);
    split_bf16_kernel<<<n4w / 256, 256>>>(Wo, whi + 3 * (size_t)DD, wlo + 3 * (size_t)DD, n4w);

    const float qscale = 0.08838834764831845f;   // 1/sqrt(128)
    dim3 gGemm(D_MODEL / 128, M_ROWS / 128);
    gemm_bf16x3_kernel<<<gGemm, 256, GSMEM_TOTAL>>>(
        xhi, xlo, whi + 0 * (size_t)DD, wlo + 0 * (size_t)DD,
        nullptr, qhi, qlo, qscale, M_ROWS, D_MODEL, D_MODEL);
    gemm_bf16x3_kernel<<<gGemm, 256, GSMEM_TOTAL>>>(
        xhi, xlo, whi + 1 * (size_t)DD, wlo + 1 * (size_t)DD,
        nullptr, khi, klo, 1.0f, M_ROWS, D_MODEL, D_MODEL);
    gemm_bf16x3_kernel<<<gGemm, 256, GSMEM_TOTAL>>>(
        xhi, xlo, whi + 2 * (size_t)DD, wlo + 2 * (size_t)DD,
        Vb, nullptr, nullptr, 1.0f, M_ROWS, D_MODEL, D_MODEL);

    vtrans_kernel<<<dim3(S_LEN / 32, D_MODEL / 32, NBATCH), dim3(32, 8)>>>(Vb, vthi, vtlo);

    attn_tc_kernel<<<dim3(S_LEN / 128, NBATCH * NHEADS), 256, AT_TOTAL>>>(
        qhi, qlo, khi, klo, vthi, vtlo, yhi, ylo);

    gemm_bf16x3_kernel<<<gGemm, 256, GSMEM_TOTAL>>>(
        yhi, ylo, whi + 3 * (size_t)DD, wlo + 3 * (size_t)DD,
        out, nullptr, nullptr, 1.0f, M_ROWS, D_MODEL, D_MODEL);
}

// round 6
// speedup vs baseline: 8.3442x; 1.1203x over previous
#include <cuda_runtime.h>
#include <cuda_bf16.h>
#include <math.h>
#include <stdint.h>

#if defined(__CUDA_ARCH__)
#if defined(__CUDA_ARCH_FEAT_SM103_ALL) || defined(__CUDA_ARCH_FEAT_SM100_ALL) || defined(__CUDA_ARCH_FEAT_SM101_ALL)
#define TCGEN05_OK 1
#else
#define TCGEN05_OK 0
#endif
#else
#define TCGEN05_OK 0
#endif

#define NBATCH  2
#define S_LEN   2048
#define D_MODEL 2048
#define NHEADS  16
#define DHEAD   128
#define M_ROWS  (NBATCH * S_LEN)   // 4096
#define DD      (D_MODEL * D_MODEL)
#define NSM     148
#define NITEMS  512                 // 16 qt x 32 bh

// ---------------- scratch ----------------
__device__ float g_V[(size_t)M_ROWS * D_MODEL];

__device__ __nv_bfloat16 g_xhi[(size_t)M_ROWS * D_MODEL];
__device__ __nv_bfloat16 g_xlo[(size_t)M_ROWS * D_MODEL];
__device__ __nv_bfloat16 g_yhi[(size_t)M_ROWS * D_MODEL];
__device__ __nv_bfloat16 g_ylo[(size_t)M_ROWS * D_MODEL];
__device__ __nv_bfloat16 g_whi[(size_t)4 * DD];
__device__ __nv_bfloat16 g_wlo[(size_t)4 * DD];
__device__ __nv_bfloat16 g_qhi[(size_t)M_ROWS * D_MODEL];
__device__ __nv_bfloat16 g_qlo[(size_t)M_ROWS * D_MODEL];
__device__ __nv_bfloat16 g_khi[(size_t)M_ROWS * D_MODEL];
__device__ __nv_bfloat16 g_klo[(size_t)M_ROWS * D_MODEL];
__device__ __nv_bfloat16 g_vthi[(size_t)M_ROWS * D_MODEL];  // [b*2048+d][s]
__device__ __nv_bfloat16 g_vtlo[(size_t)M_ROWS * D_MODEL];

// ---------------- PTX helpers ----------------
__device__ __forceinline__ uint32_t smem_u32(const void* p) {
    uint32_t a;
    asm("{ .reg .u64 t; cvta.to.shared.u64 t, %1; cvt.u32.u64 %0, t; }"
        : "=r"(a) : "l"(p));
    return a;
}
__device__ __forceinline__ uint32_t elect1() {
#if TCGEN05_OK
    uint32_t p;
    asm volatile(
        "{\n\t.reg .pred p;\n\t"
        "elect.sync _|p, 0xFFFFFFFF;\n\t"
        "selp.b32 %0, 1, 0, p;\n\t}"
        : "=r"(p));
    return p;
#else
    return 0;
#endif
}
__device__ __forceinline__ void mbar_init(uint32_t addr, uint32_t count) {
    asm volatile("mbarrier.init.shared.b64 [%0], %1;" :: "r"(addr), "r"(count) : "memory");
}
__device__ __forceinline__ void mbar_inval(uint32_t addr) {
    asm volatile("mbarrier.inval.shared.b64 [%0];" :: "r"(addr) : "memory");
}
__device__ __forceinline__ void mbar_wait(uint32_t addr, uint32_t parity) {
    asm volatile(
        "{\n\t.reg .pred P;\n\t"
        "WL_%=:\n\t"
        "mbarrier.try_wait.parity.acquire.cta.shared::cta.b64 P, [%0], %1, 0x989680;\n\t"
        "@P bra.uni WD_%=;\n\t"
        "bra.uni WL_%=;\n\t"
        "WD_%=:\n\t}"
        :: "r"(addr), "r"(parity) : "memory");
}
__device__ __forceinline__ void tmem_alloc(uint32_t smem_dst, uint32_t ncols) {
#if TCGEN05_OK
    asm volatile("tcgen05.alloc.cta_group::1.sync.aligned.shared::cta.b32 [%0], %1;"
                 :: "r"(smem_dst), "r"(ncols) : "memory");
#endif
}
__device__ __forceinline__ void tmem_dealloc(uint32_t tmem, uint32_t ncols) {
#if TCGEN05_OK
    asm volatile("tcgen05.dealloc.cta_group::1.sync.aligned.b32 %0, %1;"
                 :: "r"(tmem), "r"(ncols));
#endif
}
__device__ __forceinline__ void tmem_relinquish() {
#if TCGEN05_OK
    asm volatile("tcgen05.relinquish_alloc_permit.cta_group::1.sync.aligned;");
#endif
}
__device__ __forceinline__ void mma_f16_ss(uint32_t d_tmem, uint64_t a_desc,
                                           uint64_t b_desc, uint32_t idesc,
                                           uint32_t enable_d) {
#if TCGEN05_OK
    asm volatile(
        "{\n\t.reg .pred p;\n\t"
        "setp.ne.u32 p, %4, 0;\n\t"
        "tcgen05.mma.cta_group::1.kind::f16 [%0], %1, %2, %3, {%5, %5, %5, %5}, p;\n\t}"
        :: "r"(d_tmem), "l"(a_desc), "l"(b_desc), "r"(idesc), "r"(enable_d), "r"(0u)
        : "memory");
#endif
}
__device__ __forceinline__ void mma_commit(uint32_t mbar_addr) {
#if TCGEN05_OK
    asm volatile(
        "tcgen05.commit.cta_group::1.mbarrier::arrive::one.shared::cluster.b64 [%0];"
        :: "r"(mbar_addr) : "memory");
#endif
}
__device__ __forceinline__ void tcg_fence_after() {
#if TCGEN05_OK
    asm volatile("tcgen05.fence::after_thread_sync;" ::: "memory");
#endif
}
__device__ __forceinline__ void fence_proxy_async_s() {
    asm volatile("fence.proxy.async.shared::cta;" ::: "memory");
}
__device__ __forceinline__ void tcg_wait_ld() {
#if TCGEN05_OK
    asm volatile("tcgen05.wait::ld.sync.aligned;" ::: "memory");
#endif
}
__device__ __forceinline__ void ldtm_x32(uint32_t* r, uint32_t addr) {
#if TCGEN05_OK
    asm volatile(
        "tcgen05.ld.sync.aligned.32x32b.x32.b32 "
        "{%0, %1, %2, %3, %4, %5, %6, %7, "
        " %8, %9, %10, %11, %12, %13, %14, %15, "
        " %16, %17, %18, %19, %20, %21, %22, %23, "
        " %24, %25, %26, %27, %28, %29, %30, %31}, [%32];"
        : "=r"(r[0]),  "=r"(r[1]),  "=r"(r[2]),  "=r"(r[3]),
          "=r"(r[4]),  "=r"(r[5]),  "=r"(r[6]),  "=r"(r[7]),
          "=r"(r[8]),  "=r"(r[9]),  "=r"(r[10]), "=r"(r[11]),
          "=r"(r[12]), "=r"(r[13]), "=r"(r[14]), "=r"(r[15]),
          "=r"(r[16]), "=r"(r[17]), "=r"(r[18]), "=r"(r[19]),
          "=r"(r[20]), "=r"(r[21]), "=r"(r[22]), "=r"(r[23]),
          "=r"(r[24]), "=r"(r[25]), "=r"(r[26]), "=r"(r[27]),
          "=r"(r[28]), "=r"(r[29]), "=r"(r[30]), "=r"(r[31])
        : "r"(addr));
#else
    for (int i = 0; i < 32; i++) r[i] = 0;
#endif
}

#define DESC_BASE ((2ull << 61) | (1ull << 46) | (64ull << 32) | (1ull << 16))
#define IDESC_N128 ((1u << 4) | (1u << 7) | (1u << 10) | (16u << 17) | (8u << 24))
#define IDESC_N64  ((1u << 4) | (1u << 7) | (1u << 10) | (8u << 17)  | (8u << 24))

__device__ __forceinline__ uint32_t sw128(uint32_t bo) {
    return bo ^ ((bo >> 3) & 0x70);
}
__device__ __forceinline__ uint32_t pack_bf2(float a, float b) {
    __nv_bfloat162 v;
    v.x = __float2bfloat16(a);
    v.y = __float2bfloat16(b);
    return *(uint32_t*)&v;
}

// ---------------- fp32 -> (hi, lo) bf16 split ----------------
__device__ __forceinline__ void split_body(const float* src, __nv_bfloat16* hi,
                                           __nv_bfloat16* lo, int i) {
    float4 v = ((const float4*)src)[i];
    __nv_bfloat16 h0 = __float2bfloat16(v.x);
    __nv_bfloat16 h1 = __float2bfloat16(v.y);
    __nv_bfloat16 h2 = __float2bfloat16(v.z);
    __nv_bfloat16 h3 = __float2bfloat16(v.w);
    uint2 hh, ll;
    hh.x = pack_bf2(v.x, v.y); hh.y = pack_bf2(v.z, v.w);
    ll.x = pack_bf2(v.x - __bfloat162float(h0), v.y - __bfloat162float(h1));
    ll.y = pack_bf2(v.z - __bfloat162float(h2), v.w - __bfloat162float(h3));
    *(uint2*)(hi + 4 * (size_t)i) = hh;
    *(uint2*)(lo + 4 * (size_t)i) = ll;
}

__global__ __launch_bounds__(256) void split_bf16_kernel(
    const float* __restrict__ src,
    __nv_bfloat16* __restrict__ hi, __nv_bfloat16* __restrict__ lo, int n4)
{
    int i = blockIdx.x * 256 + threadIdx.x;
    if (i < n4) split_body(src, hi, lo, i);
}

__global__ __launch_bounds__(256) void wsplit4_kernel(
    const float* __restrict__ s0, const float* __restrict__ s1,
    const float* __restrict__ s2, const float* __restrict__ s3,
    __nv_bfloat16* __restrict__ hi, __nv_bfloat16* __restrict__ lo, int n4)
{
    int i = blockIdx.x * 256 + threadIdx.x;
    if (i >= n4) return;
    int k = blockIdx.y;
    const float* src = (k == 0) ? s0 : (k == 1) ? s1 : (k == 2) ? s2 : s3;
    split_body(src, hi + (size_t)k * DD, lo + (size_t)k * DD, i);
}

// ---------------- V transpose + split ----------------
__global__ __launch_bounds__(256) void vtrans_kernel(
    const float* __restrict__ V,
    __nv_bfloat16* __restrict__ vthi, __nv_bfloat16* __restrict__ vtlo)
{
    __shared__ float t[32][33];
    const int b  = blockIdx.z;
    const int s0 = blockIdx.x * 32;
    const int d0 = blockIdx.y * 32;
    const int tx = threadIdx.x;
    const int ty = threadIdx.y;
#pragma unroll
    for (int i = 0; i < 4; i++) {
        int s = s0 + ty + i * 8;
        t[ty + i * 8][tx] = V[((size_t)b * S_LEN + s) * D_MODEL + d0 + tx];
    }
    __syncthreads();
#pragma unroll
    for (int i = 0; i < 4; i++) {
        int d = d0 + ty + i * 8;
        float v = t[tx][ty + i * 8];
        __nv_bfloat16 h = __float2bfloat16(v);
        __nv_bfloat16 l = __float2bfloat16(v - __bfloat162float(h));
        size_t o = ((size_t)b * D_MODEL + d) * S_LEN + s0 + tx;
        vthi[o] = h;
        vtlo[o] = l;
    }
}

// ---------------- GEMM common mainloop macro ----------------
#define OFF_A0 1024
#define OFF_B0 (1024 + 16384)
#define OFF_A1 (1024 + 2 * 16384)
#define OFF_B1 (1024 + 3 * 16384)
#define GSMEM_TOTAL (1024 + 4 * 16384)

#if TCGEN05_OK
__device__ __forceinline__ void gemm_mainloop(
    char* smem, uint32_t sb, uint32_t tmem, int tid, int wid,
    const __nv_bfloat16* Ahi, const __nv_bfloat16* Alo,
    const __nv_bfloat16* Bhi, const __nv_bfloat16* Blo,
    int bm, int bn, int K)
{
    const int nk = K / 64;
    const int nchunks = 3 * nk;
    uint32_t ph0 = 0, ph1 = 0;
    for (int i = 0; i < nchunks; i++) {
        const int term = i / nk;
        const int k0 = (i - term * nk) * 64;
        const __nv_bfloat16* As = (term == 2) ? Alo : Ahi;
        const __nv_bfloat16* Bs = (term == 1) ? Blo : Bhi;
        uint4 ra[4], rb[4];
#pragma unroll
        for (int j = 0; j < 4; j++) {
            int u = tid + j * 256;
            int r = u >> 3, cs = u & 7;
            ra[j] = *(const uint4*)(As + (size_t)(bm + r) * K + k0 + cs * 8);
            rb[j] = *(const uint4*)(Bs + (size_t)(bn + r) * K + k0 + cs * 8);
        }
        const int buf = i & 1;
        if (i >= 2) {
            if (buf == 0) { mbar_wait(sb + 8, ph0);  ph0 ^= 1; }
            else          { mbar_wait(sb + 16, ph1); ph1 ^= 1; }
        }
        const uint32_t offA = buf ? OFF_A1 : OFF_A0;
        const uint32_t offB = buf ? OFF_B1 : OFF_B0;
#pragma unroll
        for (int j = 0; j < 4; j++) {
            int u = tid + j * 256;
            uint32_t sw = sw128((uint32_t)u * 16u);
            *(uint4*)(smem + offA + sw) = ra[j];
            *(uint4*)(smem + offB + sw) = rb[j];
        }
        __syncthreads();
        if (wid == 0 && elect1()) {
            fence_proxy_async_s();
            uint64_t ad = DESC_BASE | ((uint64_t)((sb + offA) >> 4) & 0x3FFF);
            uint64_t bd = DESC_BASE | ((uint64_t)((sb + offB) >> 4) & 0x3FFF);
#pragma unroll
            for (int k = 0; k < 4; k++) {
                uint32_t en = !(i == 0 && k == 0);
                mma_f16_ss(tmem, ad + k * 2, bd + k * 2, IDESC_N128, en);
            }
            mma_commit(buf ? (sb + 16) : (sb + 8));
        }
    }
    mbar_wait(sb + 16, ph1);
    tcg_fence_after();
    __syncthreads();
}
#endif

// ---------------- output-projection GEMM (fp32 out) ----------------
__global__ __launch_bounds__(256) void gemm_out_kernel(
    const __nv_bfloat16* __restrict__ Ahi, const __nv_bfloat16* __restrict__ Alo,
    const __nv_bfloat16* __restrict__ Bhi, const __nv_bfloat16* __restrict__ Blo,
    float* __restrict__ C, int K, int N)
{
#if TCGEN05_OK
    extern __shared__ char smem[];
    const uint32_t sb = smem_u32(smem);
    const int tid = threadIdx.x;
    const int wid = tid >> 5;
    const int lid = tid & 31;
    const int bm = blockIdx.y * 128;
    const int bn = blockIdx.x * 128;

    if (wid == 0) { tmem_alloc(sb, 128); tmem_relinquish(); }
    if (tid == 0) { mbar_init(sb + 8, 1); mbar_init(sb + 16, 1); }
    __syncthreads();
    uint32_t tmem;
    asm volatile("ld.shared.b32 %0, [%1];" : "=r"(tmem) : "r"(sb));

    gemm_mainloop(smem, sb, tmem, tid, wid, Ahi, Alo, Bhi, Blo, bm, bn, K);

    float* st = (float*)(smem + OFF_A0);
#pragma unroll
    for (int half = 0; half < 2; half++) {
        if (wid < 4) {
            uint32_t d0[32], d1[32];
            ldtm_x32(d0, tmem + half * 64);
            ldtm_x32(d1, tmem + half * 64 + 32);
            tcg_wait_ld();
            float* srow = st + (wid * 32 + lid) * 68;
#pragma unroll
            for (int c = 0; c < 32; c++) {
                srow[c]      = __uint_as_float(d0[c]);
                srow[32 + c] = __uint_as_float(d1[c]);
            }
        }
        __syncthreads();
#pragma unroll
        for (int j = 0; j < 8; j++) {
            int u = tid + j * 256;
            int row = u >> 4, c4 = u & 15;
            float4 v = *(const float4*)(st + row * 68 + c4 * 4);
            *(float4*)(C + (size_t)(bm + row) * N + bn + half * 64 + c4 * 4) = v;
        }
        __syncthreads();
    }
    if (tid == 0) { mbar_inval(sb + 8); mbar_inval(sb + 16); }
    if (wid == 0) tmem_dealloc(tmem, 128);
#endif
}

// ---------------- fused QKV GEMM ----------------
__global__ __launch_bounds__(256) void gemm_qkv_kernel(
    const __nv_bfloat16* __restrict__ Ahi, const __nv_bfloat16* __restrict__ Alo,
    const __nv_bfloat16* __restrict__ Whi, const __nv_bfloat16* __restrict__ Wlo,
    __nv_bfloat16* __restrict__ Qh, __nv_bfloat16* __restrict__ Ql,
    __nv_bfloat16* __restrict__ Kh, __nv_bfloat16* __restrict__ Kl,
    float* __restrict__ Vf, float qscale)
{
#if TCGEN05_OK
    extern __shared__ char smem[];
    const uint32_t sb = smem_u32(smem);
    const int tid = threadIdx.x;
    const int wid = tid >> 5;
    const int lid = tid & 31;
    const int rgn = blockIdx.x >> 4;           // 0=Q,1=K,2=V
    const int bn  = (blockIdx.x & 15) * 128;
    const int bm  = blockIdx.y * 128;
    const int N   = D_MODEL, K = D_MODEL;

    if (wid == 0) { tmem_alloc(sb, 128); tmem_relinquish(); }
    if (tid == 0) { mbar_init(sb + 8, 1); mbar_init(sb + 16, 1); }
    __syncthreads();
    uint32_t tmem;
    asm volatile("ld.shared.b32 %0, [%1];" : "=r"(tmem) : "r"(sb));

    gemm_mainloop(smem, sb, tmem, tid, wid, Ahi, Alo,
                  Whi + (size_t)rgn * DD, Wlo + (size_t)rgn * DD, bm, bn, K);

    const float scale = (rgn == 0) ? qscale : 1.0f;
    float* st = (float*)(smem + OFF_A0);
#pragma unroll
    for (int half = 0; half < 2; half++) {
        if (wid < 4) {
            uint32_t d0[32], d1[32];
            ldtm_x32(d0, tmem + half * 64);
            ldtm_x32(d1, tmem + half * 64 + 32);
            tcg_wait_ld();
            float* srow = st + (wid * 32 + lid) * 68;
#pragma unroll
            for (int c = 0; c < 32; c++) {
                srow[c]      = __uint_as_float(d0[c]);
                srow[32 + c] = __uint_as_float(d1[c]);
            }
        }
        __syncthreads();
#pragma unroll
        for (int j = 0; j < 8; j++) {
            int u = tid + j * 256;
            int row = u >> 4, c4 = u & 15;
            float4 v = *(const float4*)(st + row * 68 + c4 * 4);
            size_t grow = (size_t)(bm + row);
            int gcol = bn + half * 64 + c4 * 4;
            if (rgn == 2) {
                *(float4*)(Vf + grow * N + gcol) = v;
            } else {
                float v0 = v.x * scale, v1 = v.y * scale;
                float v2 = v.z * scale, v3 = v.w * scale;
                __nv_bfloat16 h0 = __float2bfloat16(v0);
                __nv_bfloat16 h1 = __float2bfloat16(v1);
                __nv_bfloat16 h2 = __float2bfloat16(v2);
                __nv_bfloat16 h3 = __float2bfloat16(v3);
                uint2 hh, ll;
                hh.x = pack_bf2(v0, v1); hh.y = pack_bf2(v2, v3);
                ll.x = pack_bf2(v0 - __bfloat162float(h0), v1 - __bfloat162float(h1));
                ll.y = pack_bf2(v2 - __bfloat162float(h2), v3 - __bfloat162float(h3));
                __nv_bfloat16* H = (rgn == 0) ? Qh : Kh;
                __nv_bfloat16* L = (rgn == 0) ? Ql : Kl;
                *(uint2*)(H + grow * N + gcol) = hh;
                *(uint2*)(L + grow * N + gcol) = ll;
            }
        }
        __syncthreads();
    }
    if (tid == 0) { mbar_inval(sb + 8); mbar_inval(sb + 16); }
    if (wid == 0) tmem_dealloc(tmem, 128);
#endif
}

// ---------------- persistent tcgen05 flash attention ----------------
#define AT_RED    1024
#define AT_RED2   2048
#define AT_QHI    3072
#define AT_QLO    35840
#define AT_KV0    68608                // KHI | KLO(+16K) | VTHI(+32K) | VTLO(+48K)
#define AT_KV1    134144
#define AT_PHI    199680
#define AT_PLO    216064
#define AT_TOTAL  232448               // 227 KB
#define AT_STAGE  AT_KV0

#if TCGEN05_OK
__device__ __forceinline__ void fill_K(
    char* smem, uint32_t kvb,
    const __nv_bfloat16* __restrict__ Khi, const __nv_bfloat16* __restrict__ Klo,
    int tid, int b, int h, int jt)
{
#pragma unroll
    for (int j = 0; j < 4; j++) {
        int u = tid + j * 256;
        int row = u >> 4, cu = u & 15;
        size_t g = ((size_t)(b * S_LEN + jt * 64 + row)) * D_MODEL + h * DHEAD + cu * 8;
        uint32_t bo = ((uint32_t)(row >> 3) + ((uint32_t)(cu >> 3) << 3)) * 1024u
                    + (uint32_t)(row & 7) * 128u + (uint32_t)(cu & 7) * 16u;
        uint32_t sw = sw128(bo);
        *(uint4*)(smem + kvb + sw)         = *(const uint4*)(Khi + g);
        *(uint4*)(smem + kvb + 16384 + sw) = *(const uint4*)(Klo + g);
    }
}
__device__ __forceinline__ void fill_V(
    char* smem, uint32_t kvb,
    const __nv_bfloat16* __restrict__ VThi, const __nv_bfloat16* __restrict__ VTlo,
    int tid, int bh, int jt)
{
#pragma unroll
    for (int j = 0; j < 4; j++) {
        int u = tid + j * 256;
        int row = u >> 3, cu = u & 7;
        size_t g = ((size_t)(bh * DHEAD + row)) * S_LEN + jt * 64 + cu * 8;
        uint32_t bo = (uint32_t)(row >> 3) * 1024u
                    + (uint32_t)(row & 7) * 128u + (uint32_t)cu * 16u;
        uint32_t sw = sw128(bo);
        *(uint4*)(smem + kvb + 32768 + sw) = *(const uint4*)(VThi + g);
        *(uint4*)(smem + kvb + 49152 + sw) = *(const uint4*)(VTlo + g);
    }
}
__device__ __forceinline__ void issue_qk(uint32_t sb, uint32_t S_T, uint32_t kvb) {
    uint64_t dQh = DESC_BASE | ((uint64_t)((sb + AT_QHI) >> 4) & 0x3FFF);
    uint64_t dQl = DESC_BASE | ((uint64_t)((sb + AT_QLO) >> 4) & 0x3FFF);
    uint64_t dKh = DESC_BASE | ((uint64_t)((sb + kvb) >> 4) & 0x3FFF);
    uint64_t dKl = DESC_BASE | ((uint64_t)((sb + kvb + 16384) >> 4) & 0x3FFF);
    const uint64_t qo[8] = {0, 2, 4, 6, 1024, 1026, 1028, 1030};
    const uint64_t ko[8] = {0, 2, 4, 6, 512, 514, 516, 518};
    uint64_t aT[3] = {dQh, dQh, dQl};
    uint64_t bT[3] = {dKh, dKl, dKh};
#pragma unroll
    for (int t = 0; t < 3; t++)
#pragma unroll
        for (int s = 0; s < 8; s++)
            mma_f16_ss(S_T, aT[t] + qo[s], bT[t] + ko[s], IDESC_N64, !(t == 0 && s == 0));
    mma_commit(sb + 8);
}
__device__ __forceinline__ void issue_pv(uint32_t sb, uint32_t O_T, uint32_t kvb,
                                         int do_commit) {
    uint64_t dPh = DESC_BASE | ((uint64_t)((sb + AT_PHI) >> 4) & 0x3FFF);
    uint64_t dPl = DESC_BASE | ((uint64_t)((sb + AT_PLO) >> 4) & 0x3FFF);
    uint64_t dVh = DESC_BASE | ((uint64_t)((sb + kvb + 32768) >> 4) & 0x3FFF);
    uint64_t dVl = DESC_BASE | ((uint64_t)((sb + kvb + 49152) >> 4) & 0x3FFF);
    uint64_t aT[3] = {dPh, dPh, dPl};
    uint64_t bT[3] = {dVh, dVl, dVh};
#pragma unroll
    for (int t = 0; t < 3; t++)
#pragma unroll
        for (int s = 0; s < 4; s++)
            mma_f16_ss(O_T, aT[t] + 2 * s, bT[t] + 2 * s, IDESC_N128, !(t == 0 && s == 0));
    if (do_commit) mma_commit(sb + 16);
}
#endif

__global__ __launch_bounds__(256) void attn_tc_kernel(
    const __nv_bfloat16* __restrict__ Qhi, const __nv_bfloat16* __restrict__ Qlo,
    const __nv_bfloat16* __restrict__ Khi, const __nv_bfloat16* __restrict__ Klo,
    const __nv_bfloat16* __restrict__ VThi, const __nv_bfloat16* __restrict__ VTlo,
    __nv_bfloat16* __restrict__ Yhi, __nv_bfloat16* __restrict__ Ylo)
{
#if TCGEN05_OK
    extern __shared__ char smem[];
    const uint32_t sb = smem_u32(smem);
    const int tid = threadIdx.x;
    const int w   = tid >> 5;
    const int l   = tid & 31;
    const int r   = (w & 3) * 32 + l;
    const int hf  = w >> 2;
    const uint32_t woff = (uint32_t)(w & 3) << 21;

    if (w == 0) { tmem_alloc(sb, 512); tmem_relinquish(); }
    if (tid == 0) { mbar_init(sb + 8, 1); mbar_init(sb + 16, 1); }
    __syncthreads();
    uint32_t tmem;
    asm volatile("ld.shared.b32 %0, [%1];" : "=r"(tmem) : "r"(sb));
    const uint32_t S_T  = tmem;          // cols 0..63
    const uint32_t O_T0 = tmem + 64;     // cols 64..191
    const uint32_t O_T1 = tmem + 192;    // cols 192..319

    uint32_t phS = 0, phO = 0;

    for (int rnd = 0; rnd < 4; rnd++) {
        int s = rnd * NSM + ((rnd & 1) ? (NSM - 1 - (int)blockIdx.x)
                                       : (int)blockIdx.x);
        if (s >= NITEMS) continue;
        const int qt = 15 - (s >> 5);     // descending work (serpentine LPT)
        const int bh = s & 31;
        const int b  = bh >> 4;
        const int h  = bh & 15;
        const int njt = 2 * qt + 2;
        const int qg = qt * 128 + r;

        // ---- load Q tile (hi+lo) ----
#pragma unroll
        for (int j = 0; j < 8; j++) {
            int u = tid + j * 256;
            int row = u >> 4, cu = u & 15;
            size_t g = ((size_t)(b * S_LEN + qt * 128 + row)) * D_MODEL + h * DHEAD + cu * 8;
            uint32_t bo = ((uint32_t)(row >> 3) + ((uint32_t)(cu >> 3) << 4)) * 1024u
                        + (uint32_t)(row & 7) * 128u + (uint32_t)(cu & 7) * 16u;
            uint32_t sw = sw128(bo);
            *(uint4*)(smem + AT_QHI + sw) = *(const uint4*)(Qhi + g);
            *(uint4*)(smem + AT_QLO + sw) = *(const uint4*)(Qlo + g);
        }

        fill_K(smem, AT_KV0, Khi, Klo, tid, b, h, 0);
        fill_V(smem, AT_KV0, VThi, VTlo, tid, bh, 0);
        __syncthreads();
        if (w == 0 && elect1()) {
            fence_proxy_async_s();
            issue_qk(sb, S_T, AT_KV0);
        }

        float m_run = -1e30f, l_run = 0.0f, corr_prev = 0.0f;
        float O[64];
#pragma unroll
        for (int j = 0; j < 64; j++) O[j] = 0.0f;

        for (int jt = 0; jt < njt; jt++) {
            const uint32_t kvb  = (jt & 1) ? AT_KV1 : AT_KV0;
            const uint32_t kvbn = (jt & 1) ? AT_KV0 : AT_KV1;

            // K-part of next tile: last reader QK(jt-1) long done
            if (jt + 1 < njt) fill_K(smem, kvbn, Khi, Klo, tid, b, h, jt + 1);

            mbar_wait(sb + 8, phS); phS ^= 1;     // implies PV(jt-1) complete
            tcg_fence_after();

            uint32_t sr_[32];
            ldtm_x32(sr_, S_T + hf * 32 + woff);
            tcg_wait_ld();

            // V-part of next tile: safe now (PV(jt-1) done)
            if (jt + 1 < njt) fill_V(smem, kvbn, VThi, VTlo, tid, bh, jt + 1);

            // accumulate previous PV tile (overlaps nothing on tensor; free now)
            if (jt > 0) {
                const uint32_t OP = (jt & 1) ? O_T0 : O_T1;   // buffer (jt-1)&1
                uint32_t o0[32];
                ldtm_x32(o0, OP + hf * 64 + woff);
                tcg_wait_ld();
#pragma unroll
                for (int j = 0; j < 32; j++)
                    O[j] = fmaf(O[j], corr_prev, __uint_as_float(o0[j]));
                ldtm_x32(o0, OP + hf * 64 + 32 + woff);
                tcg_wait_ld();
#pragma unroll
                for (int j = 0; j < 32; j++)
                    O[32 + j] = fmaf(O[32 + j], corr_prev, __uint_as_float(o0[j]));
            }

            // ---- softmax ----
            float sv[32];
            const int kgb = jt * 64 + hf * 32;
#pragma unroll
            for (int i = 0; i < 32; i++) {
                float x = __uint_as_float(sr_[i]);
                sv[i] = (kgb + i > qg) ? -1e30f : x;
            }
            float tmax = -1e30f;
#pragma unroll
            for (int i = 0; i < 32; i++) tmax = fmaxf(tmax, sv[i]);
            float* red1 = (float*)(smem + AT_RED);
            float* red2 = (float*)(smem + AT_RED2);
            red1[hf * 128 + r] = tmax;
            __syncthreads();
            tmax = fmaxf(tmax, red1[(1 - hf) * 128 + r]);
            float mnew = fmaxf(m_run, tmax);
            float corr = __expf(m_run - mnew);
            float p[32], psum = 0.0f;
#pragma unroll
            for (int i = 0; i < 32; i++) {
                p[i] = __expf(sv[i] - mnew);
                psum += p[i];
            }
            red2[hf * 128 + r] = psum;
            __syncthreads();
            l_run = l_run * corr + psum + red2[(1 - hf) * 128 + r];
            m_run = mnew;

            // ---- P -> bf16 hi/lo ----
            {
                uint32_t rowbase = (uint32_t)(r >> 3) * 1024u + (uint32_t)(r & 7) * 128u;
#pragma unroll
                for (int i = 0; i < 32; i += 2) {
                    float p0 = p[i], p1 = p[i + 1];
                    __nv_bfloat16 h0 = __float2bfloat16(p0);
                    __nv_bfloat16 h1 = __float2bfloat16(p1);
                    uint32_t hp = pack_bf2(p0, p1);
                    uint32_t lp = pack_bf2(p0 - __bfloat162float(h0),
                                           p1 - __bfloat162float(h1));
                    uint32_t sw = sw128(rowbase + (uint32_t)(hf * 32 + i) * 2u);
                    *(uint32_t*)(smem + AT_PHI + sw) = hp;
                    *(uint32_t*)(smem + AT_PLO + sw) = lp;
                }
            }
            __syncthreads();   // P + next-KV fill visible; S fully consumed

            if (w == 0 && elect1()) {
                fence_proxy_async_s();
                issue_pv(sb, (jt & 1) ? O_T1 : O_T0, kvb, jt == njt - 1);
                if (jt + 1 < njt) issue_qk(sb, S_T, kvbn);
            }
            corr_prev = corr;
        }

        // final PV tile
        mbar_wait(sb + 16, phO); phO ^= 1;
        tcg_fence_after();
        {
            const uint32_t OP = ((njt - 1) & 1) ? O_T1 : O_T0;
            uint32_t o0[32];
            ldtm_x32(o0, OP + hf * 64 + woff);
            tcg_wait_ld();
#pragma unroll
            for (int j = 0; j < 32; j++)
                O[j] = fmaf(O[j], corr_prev, __uint_as_float(o0[j]));
            ldtm_x32(o0, OP + hf * 64 + 32 + woff);
            tcg_wait_ld();
#pragma unroll
            for (int j = 0; j < 32; j++)
                O[32 + j] = fmaf(O[32 + j], corr_prev, __uint_as_float(o0[j]));
        }

        // ---- normalize + stage + write ----
        __syncthreads();   // KV buffers dead -> staging
        {
            float inv = 1.0f / l_run;
            float* st = (float*)(smem + AT_STAGE);
#pragma unroll
            for (int j = 0; j < 64; j += 4) {
                float4 v = make_float4(O[j] * inv, O[j + 1] * inv,
                                       O[j + 2] * inv, O[j + 3] * inv);
                *(float4*)(st + r * 132 + hf * 64 + j) = v;
            }
        }
        __syncthreads();
        {
            const float* st = (const float*)(smem + AT_STAGE);
#pragma unroll
            for (int j = 0; j < 16; j++) {
                int u = tid + j * 256;
                int row = u >> 5, c4 = u & 31;
                float4 v = *(const float4*)(st + row * 132 + c4 * 4);
                size_t g = ((size_t)(b * S_LEN + qt * 128 + row)) * D_MODEL + h * DHEAD + c4 * 4;
                __nv_bfloat16 h0 = __float2bfloat16(v.x);
                __nv_bfloat16 h1 = __float2bfloat16(v.y);
                __nv_bfloat16 h2 = __float2bfloat16(v.z);
                __nv_bfloat16 h3 = __float2bfloat16(v.w);
                uint2 hh, ll;
                hh.x = pack_bf2(v.x, v.y); hh.y = pack_bf2(v.z, v.w);
                ll.x = pack_bf2(v.x - __bfloat162float(h0), v.y - __bfloat162float(h1));
                ll.y = pack_bf2(v.z - __bfloat162float(h2), v.w - __bfloat162float(h3));
                *(uint2*)(Yhi + g) = hh;
                *(uint2*)(Ylo + g) = ll;
            }
        }
        __syncthreads();   // staging consumed before next item's fill
    }

    if (tid == 0) { mbar_inval(sb + 8); mbar_inval(sb + 16); }
    if (w == 0) tmem_dealloc(tmem, 512);
#endif
}

// ---------------- launch ----------------
extern "C" void kernel_launch(void* const* d_in, const int* in_sizes, int n_in,
                              void* d_out, int out_size)
{
    (void)in_sizes; (void)n_in; (void)out_size;
    const float* x  = (const float*)d_in[0];
    const float* Wq = (const float*)d_in[2];
    const float* Wk = (const float*)d_in[3];
    const float* Wv = (const float*)d_in[4];
    const float* Wo = (const float*)d_in[5];
    float* out = (float*)d_out;

    float* Vb;
    cudaGetSymbolAddress((void**)&Vb, g_V);
    __nv_bfloat16 *xhi, *xlo, *yhi, *ylo, *whi, *wlo;
    __nv_bfloat16 *qhi, *qlo, *khi, *klo, *vthi, *vtlo;
    cudaGetSymbolAddress((void**)&xhi, g_xhi);
    cudaGetSymbolAddress((void**)&xlo, g_xlo);
    cudaGetSymbolAddress((void**)&yhi, g_yhi);
    cudaGetSymbolAddress((void**)&ylo, g_ylo);
    cudaGetSymbolAddress((void**)&whi, g_whi);
    cudaGetSymbolAddress((void**)&wlo, g_wlo);
    cudaGetSymbolAddress((void**)&qhi, g_qhi);
    cudaGetSymbolAddress((void**)&qlo, g_qlo);
    cudaGetSymbolAddress((void**)&khi, g_khi);
    cudaGetSymbolAddress((void**)&klo, g_klo);
    cudaGetSymbolAddress((void**)&vthi, g_vthi);
    cudaGetSymbolAddress((void**)&vtlo, g_vtlo);

    cudaFuncSetAttribute(gemm_qkv_kernel,
                         cudaFuncAttributeMaxDynamicSharedMemorySize, GSMEM_TOTAL);
    cudaFuncSetAttribute(gemm_out_kernel,
                         cudaFuncAttributeMaxDynamicSharedMemorySize, GSMEM_TOTAL);
    cudaFuncSetAttribute(attn_tc_kernel,
                         cudaFuncAttributeMaxDynamicSharedMemorySize, AT_TOTAL);

    const int n4x = M_ROWS * D_MODEL / 4;
    const int n4w = DD / 4;
    split_bf16_kernel<<<n4x / 256, 256>>>(x, xhi, xlo, n4x);
    wsplit4_kernel<<<dim3(n4w / 256, 4), 256>>>(Wq, Wk, Wv, Wo, whi, wlo, n4w);

    const float qscale = 0.08838834764831845f;   // 1/sqrt(128)
    gemm_qkv_kernel<<<dim3(48, 32), 256, GSMEM_TOTAL>>>(
        xhi, xlo, whi, wlo, qhi, qlo, khi, klo, Vb, qscale);

    vtrans_kernel<<<dim3(S_LEN / 32, D_MODEL / 32, NBATCH), dim3(32, 8)>>>(Vb, vthi, vtlo);

    attn_tc_kernel<<<NSM, 256, AT_TOTAL>>>(qhi, qlo, khi, klo, vthi, vtlo, yhi, ylo);

    gemm_out_kernel<<<dim3(16, 32), 256, GSMEM_TOTAL>>>(
        yhi, ylo, whi + 3 * (size_t)DD, wlo + 3 * (size_t)DD, out, D_MODEL, D_MODEL);
}

// round 7
// speedup vs baseline: 8.3654x; 1.0025x over previous
#include <cuda_runtime.h>
#include <cuda_bf16.h>
#include <math.h>
#include <stdint.h>

#if defined(__CUDA_ARCH__)
#if defined(__CUDA_ARCH_FEAT_SM103_ALL) || defined(__CUDA_ARCH_FEAT_SM100_ALL) || defined(__CUDA_ARCH_FEAT_SM101_ALL)
#define TCGEN05_OK 1
#else
#define TCGEN05_OK 0
#endif
#else
#define TCGEN05_OK 0
#endif

#define NBATCH  2
#define S_LEN   2048
#define D_MODEL 2048
#define NHEADS  16
#define DHEAD   128
#define M_ROWS  (NBATCH * S_LEN)   // 4096
#define DD      (D_MODEL * D_MODEL)
#define NSM     148
#define NITEMS  512                 // 16 qt x 32 bh

// ---------------- scratch ----------------
__device__ float g_V[(size_t)M_ROWS * D_MODEL];

__device__ __nv_bfloat16 g_xhi[(size_t)M_ROWS * D_MODEL];
__device__ __nv_bfloat16 g_xlo[(size_t)M_ROWS * D_MODEL];
__device__ __nv_bfloat16 g_yhi[(size_t)M_ROWS * D_MODEL];
__device__ __nv_bfloat16 g_ylo[(size_t)M_ROWS * D_MODEL];
__device__ __nv_bfloat16 g_whi[(size_t)4 * DD];
__device__ __nv_bfloat16 g_wlo[(size_t)4 * DD];
__device__ __nv_bfloat16 g_qhi[(size_t)M_ROWS * D_MODEL];
__device__ __nv_bfloat16 g_qlo[(size_t)M_ROWS * D_MODEL];
__device__ __nv_bfloat16 g_khi[(size_t)M_ROWS * D_MODEL];
__device__ __nv_bfloat16 g_klo[(size_t)M_ROWS * D_MODEL];
__device__ __nv_bfloat16 g_vthi[(size_t)M_ROWS * D_MODEL];  // [b*2048+d][s]
__device__ __nv_bfloat16 g_vtlo[(size_t)M_ROWS * D_MODEL];

// ---------------- PTX helpers ----------------
__device__ __forceinline__ uint32_t smem_u32(const void* p) {
    uint32_t a;
    asm("{ .reg .u64 t; cvta.to.shared.u64 t, %1; cvt.u32.u64 %0, t; }"
        : "=r"(a) : "l"(p));
    return a;
}
__device__ __forceinline__ uint32_t elect1() {
#if TCGEN05_OK
    uint32_t p;
    asm volatile(
        "{\n\t.reg .pred p;\n\t"
        "elect.sync _|p, 0xFFFFFFFF;\n\t"
        "selp.b32 %0, 1, 0, p;\n\t}"
        : "=r"(p));
    return p;
#else
    return 0;
#endif
}
__device__ __forceinline__ void mbar_init(uint32_t addr, uint32_t count) {
    asm volatile("mbarrier.init.shared.b64 [%0], %1;" :: "r"(addr), "r"(count) : "memory");
}
__device__ __forceinline__ void mbar_inval(uint32_t addr) {
    asm volatile("mbarrier.inval.shared.b64 [%0];" :: "r"(addr) : "memory");
}
__device__ __forceinline__ void mbar_wait(uint32_t addr, uint32_t parity) {
    asm volatile(
        "{\n\t.reg .pred P;\n\t"
        "WL_%=:\n\t"
        "mbarrier.try_wait.parity.acquire.cta.shared::cta.b64 P, [%0], %1, 0x989680;\n\t"
        "@P bra.uni WD_%=;\n\t"
        "bra.uni WL_%=;\n\t"
        "WD_%=:\n\t}"
        :: "r"(addr), "r"(parity) : "memory");
}
__device__ __forceinline__ void tmem_alloc(uint32_t smem_dst, uint32_t ncols) {
#if TCGEN05_OK
    asm volatile("tcgen05.alloc.cta_group::1.sync.aligned.shared::cta.b32 [%0], %1;"
                 :: "r"(smem_dst), "r"(ncols) : "memory");
#endif
}
__device__ __forceinline__ void tmem_dealloc(uint32_t tmem, uint32_t ncols) {
#if TCGEN05_OK
    asm volatile("tcgen05.dealloc.cta_group::1.sync.aligned.b32 %0, %1;"
                 :: "r"(tmem), "r"(ncols));
#endif
}
__device__ __forceinline__ void tmem_relinquish() {
#if TCGEN05_OK
    asm volatile("tcgen05.relinquish_alloc_permit.cta_group::1.sync.aligned;");
#endif
}
__device__ __forceinline__ void mma_f16_ss(uint32_t d_tmem, uint64_t a_desc,
                                           uint64_t b_desc, uint32_t idesc,
                                           uint32_t enable_d) {
#if TCGEN05_OK
    asm volatile(
        "{\n\t.reg .pred p;\n\t"
        "setp.ne.u32 p, %4, 0;\n\t"
        "tcgen05.mma.cta_group::1.kind::f16 [%0], %1, %2, %3, {%5, %5, %5, %5}, p;\n\t}"
        :: "r"(d_tmem), "l"(a_desc), "l"(b_desc), "r"(idesc), "r"(enable_d), "r"(0u)
        : "memory");
#endif
}
__device__ __forceinline__ void mma_commit(uint32_t mbar_addr) {
#if TCGEN05_OK
    asm volatile(
        "tcgen05.commit.cta_group::1.mbarrier::arrive::one.shared::cluster.b64 [%0];"
        :: "r"(mbar_addr) : "memory");
#endif
}
__device__ __forceinline__ void tcg_fence_after() {
#if TCGEN05_OK
    asm volatile("tcgen05.fence::after_thread_sync;" ::: "memory");
#endif
}
__device__ __forceinline__ void fence_proxy_async_s() {
    asm volatile("fence.proxy.async.shared::cta;" ::: "memory");
}
__device__ __forceinline__ void tcg_wait_ld() {
#if TCGEN05_OK
    asm volatile("tcgen05.wait::ld.sync.aligned;" ::: "memory");
#endif
}
__device__ __forceinline__ void ldtm_x32(uint32_t* r, uint32_t addr) {
#if TCGEN05_OK
    asm volatile(
        "tcgen05.ld.sync.aligned.32x32b.x32.b32 "
        "{%0, %1, %2, %3, %4, %5, %6, %7, "
        " %8, %9, %10, %11, %12, %13, %14, %15, "
        " %16, %17, %18, %19, %20, %21, %22, %23, "
        " %24, %25, %26, %27, %28, %29, %30, %31}, [%32];"
        : "=r"(r[0]),  "=r"(r[1]),  "=r"(r[2]),  "=r"(r[3]),
          "=r"(r[4]),  "=r"(r[5]),  "=r"(r[6]),  "=r"(r[7]),
          "=r"(r[8]),  "=r"(r[9]),  "=r"(r[10]), "=r"(r[11]),
          "=r"(r[12]), "=r"(r[13]), "=r"(r[14]), "=r"(r[15]),
          "=r"(r[16]), "=r"(r[17]), "=r"(r[18]), "=r"(r[19]),
          "=r"(r[20]), "=r"(r[21]), "=r"(r[22]), "=r"(r[23]),
          "=r"(r[24]), "=r"(r[25]), "=r"(r[26]), "=r"(r[27]),
          "=r"(r[28]), "=r"(r[29]), "=r"(r[30]), "=r"(r[31])
        : "r"(addr));
#else
    for (int i = 0; i < 32; i++) r[i] = 0;
#endif
}

#define DESC_BASE ((2ull << 61) | (1ull << 46) | (64ull << 32) | (1ull << 16))
#define IDESC_N128 ((1u << 4) | (1u << 7) | (1u << 10) | (16u << 17) | (8u << 24))
#define IDESC_N64  ((1u << 4) | (1u << 7) | (1u << 10) | (8u << 17)  | (8u << 24))

__device__ __forceinline__ uint32_t sw128(uint32_t bo) {
    return bo ^ ((bo >> 3) & 0x70);
}
__device__ __forceinline__ uint32_t pack_bf2(float a, float b) {
    __nv_bfloat162 v;
    v.x = __float2bfloat16(a);
    v.y = __float2bfloat16(b);
    return *(uint32_t*)&v;
}

// ---------------- fp32 -> (hi, lo) bf16 split ----------------
__device__ __forceinline__ void split_body(const float* src, __nv_bfloat16* hi,
                                           __nv_bfloat16* lo, int i) {
    float4 v = ((const float4*)src)[i];
    __nv_bfloat16 h0 = __float2bfloat16(v.x);
    __nv_bfloat16 h1 = __float2bfloat16(v.y);
    __nv_bfloat16 h2 = __float2bfloat16(v.z);
    __nv_bfloat16 h3 = __float2bfloat16(v.w);
    uint2 hh, ll;
    hh.x = pack_bf2(v.x, v.y); hh.y = pack_bf2(v.z, v.w);
    ll.x = pack_bf2(v.x - __bfloat162float(h0), v.y - __bfloat162float(h1));
    ll.y = pack_bf2(v.z - __bfloat162float(h2), v.w - __bfloat162float(h3));
    *(uint2*)(hi + 4 * (size_t)i) = hh;
    *(uint2*)(lo + 4 * (size_t)i) = ll;
}

__global__ __launch_bounds__(256) void split_bf16_kernel(
    const float* __restrict__ src,
    __nv_bfloat16* __restrict__ hi, __nv_bfloat16* __restrict__ lo, int n4)
{
    int i = blockIdx.x * 256 + threadIdx.x;
    if (i < n4) split_body(src, hi, lo, i);
}

__global__ __launch_bounds__(256) void wsplit4_kernel(
    const float* __restrict__ s0, const float* __restrict__ s1,
    const float* __restrict__ s2, const float* __restrict__ s3,
    __nv_bfloat16* __restrict__ hi, __nv_bfloat16* __restrict__ lo, int n4)
{
    int i = blockIdx.x * 256 + threadIdx.x;
    if (i >= n4) return;
    int k = blockIdx.y;
    const float* src = (k == 0) ? s0 : (k == 1) ? s1 : (k == 2) ? s2 : s3;
    split_body(src, hi + (size_t)k * DD, lo + (size_t)k * DD, i);
}

// ---------------- V transpose + split ----------------
__global__ __launch_bounds__(256) void vtrans_kernel(
    const float* __restrict__ V,
    __nv_bfloat16* __restrict__ vthi, __nv_bfloat16* __restrict__ vtlo)
{
    __shared__ float t[32][33];
    const int b  = blockIdx.z;
    const int s0 = blockIdx.x * 32;
    const int d0 = blockIdx.y * 32;
    const int tx = threadIdx.x;
    const int ty = threadIdx.y;
#pragma unroll
    for (int i = 0; i < 4; i++) {
        int s = s0 + ty + i * 8;
        t[ty + i * 8][tx] = V[((size_t)b * S_LEN + s) * D_MODEL + d0 + tx];
    }
    __syncthreads();
#pragma unroll
    for (int i = 0; i < 4; i++) {
        int d = d0 + ty + i * 8;
        float v = t[tx][ty + i * 8];
        __nv_bfloat16 h = __float2bfloat16(v);
        __nv_bfloat16 l = __float2bfloat16(v - __bfloat162float(h));
        size_t o = ((size_t)b * D_MODEL + d) * S_LEN + s0 + tx;
        vthi[o] = h;
        vtlo[o] = l;
    }
}

// ---------------- GEMM common mainloop macro ----------------
#define OFF_A0 1024
#define OFF_B0 (1024 + 16384)
#define OFF_A1 (1024 + 2 * 16384)
#define OFF_B1 (1024 + 3 * 16384)
#define GSMEM_TOTAL (1024 + 4 * 16384)

#if TCGEN05_OK
__device__ __forceinline__ void gemm_mainloop(
    char* smem, uint32_t sb, uint32_t tmem, int tid, int wid,
    const __nv_bfloat16* Ahi, const __nv_bfloat16* Alo,
    const __nv_bfloat16* Bhi, const __nv_bfloat16* Blo,
    int bm, int bn, int K)
{
    const int nk = K / 64;
    const int nchunks = 3 * nk;
    uint32_t ph0 = 0, ph1 = 0;
    for (int i = 0; i < nchunks; i++) {
        const int term = i / nk;
        const int k0 = (i - term * nk) * 64;
        const __nv_bfloat16* As = (term == 2) ? Alo : Ahi;
        const __nv_bfloat16* Bs = (term == 1) ? Blo : Bhi;
        uint4 ra[4], rb[4];
#pragma unroll
        for (int j = 0; j < 4; j++) {
            int u = tid + j * 256;
            int r = u >> 3, cs = u & 7;
            ra[j] = *(const uint4*)(As + (size_t)(bm + r) * K + k0 + cs * 8);
            rb[j] = *(const uint4*)(Bs + (size_t)(bn + r) * K + k0 + cs * 8);
        }
        const int buf = i & 1;
        if (i >= 2) {
            if (buf == 0) { mbar_wait(sb + 8, ph0);  ph0 ^= 1; }
            else          { mbar_wait(sb + 16, ph1); ph1 ^= 1; }
        }
        const uint32_t offA = buf ? OFF_A1 : OFF_A0;
        const uint32_t offB = buf ? OFF_B1 : OFF_B0;
#pragma unroll
        for (int j = 0; j < 4; j++) {
            int u = tid + j * 256;
            uint32_t sw = sw128((uint32_t)u * 16u);
            *(uint4*)(smem + offA + sw) = ra[j];
            *(uint4*)(smem + offB + sw) = rb[j];
        }
        __syncthreads();
        if (wid == 0 && elect1()) {
            fence_proxy_async_s();
            uint64_t ad = DESC_BASE | ((uint64_t)((sb + offA) >> 4) & 0x3FFF);
            uint64_t bd = DESC_BASE | ((uint64_t)((sb + offB) >> 4) & 0x3FFF);
#pragma unroll
            for (int k = 0; k < 4; k++) {
                uint32_t en = !(i == 0 && k == 0);
                mma_f16_ss(tmem, ad + k * 2, bd + k * 2, IDESC_N128, en);
            }
            mma_commit(buf ? (sb + 16) : (sb + 8));
        }
    }
    mbar_wait(sb + 16, ph1);
    tcg_fence_after();
    __syncthreads();
}
#endif

// ---------------- output-projection GEMM (fp32 out) ----------------
__global__ __launch_bounds__(256) void gemm_out_kernel(
    const __nv_bfloat16* __restrict__ Ahi, const __nv_bfloat16* __restrict__ Alo,
    const __nv_bfloat16* __restrict__ Bhi, const __nv_bfloat16* __restrict__ Blo,
    float* __restrict__ C, int K, int N)
{
#if TCGEN05_OK
    extern __shared__ char smem[];
    const uint32_t sb = smem_u32(smem);
    const int tid = threadIdx.x;
    const int wid = tid >> 5;
    const int lid = tid & 31;
    const int bm = blockIdx.y * 128;
    const int bn = blockIdx.x * 128;

    if (wid == 0) { tmem_alloc(sb, 128); tmem_relinquish(); }
    if (tid == 0) { mbar_init(sb + 8, 1); mbar_init(sb + 16, 1); }
    __syncthreads();
    uint32_t tmem;
    asm volatile("ld.shared.b32 %0, [%1];" : "=r"(tmem) : "r"(sb));

    gemm_mainloop(smem, sb, tmem, tid, wid, Ahi, Alo, Bhi, Blo, bm, bn, K);

    float* st = (float*)(smem + OFF_A0);
#pragma unroll
    for (int half = 0; half < 2; half++) {
        if (wid < 4) {
            uint32_t d0[32], d1[32];
            ldtm_x32(d0, tmem + half * 64);
            ldtm_x32(d1, tmem + half * 64 + 32);
            tcg_wait_ld();
            float* srow = st + (wid * 32 + lid) * 68;
#pragma unroll
            for (int c = 0; c < 32; c++) {
                srow[c]      = __uint_as_float(d0[c]);
                srow[32 + c] = __uint_as_float(d1[c]);
            }
        }
        __syncthreads();
#pragma unroll
        for (int j = 0; j < 8; j++) {
            int u = tid + j * 256;
            int row = u >> 4, c4 = u & 15;
            float4 v = *(const float4*)(st + row * 68 + c4 * 4);
            *(float4*)(C + (size_t)(bm + row) * N + bn + half * 64 + c4 * 4) = v;
        }
        __syncthreads();
    }
    if (tid == 0) { mbar_inval(sb + 8); mbar_inval(sb + 16); }
    if (wid == 0) tmem_dealloc(tmem, 128);
#endif
}

// ---------------- fused QKV GEMM ----------------
__global__ __launch_bounds__(256) void gemm_qkv_kernel(
    const __nv_bfloat16* __restrict__ Ahi, const __nv_bfloat16* __restrict__ Alo,
    const __nv_bfloat16* __restrict__ Whi, const __nv_bfloat16* __restrict__ Wlo,
    __nv_bfloat16* __restrict__ Qh, __nv_bfloat16* __restrict__ Ql,
    __nv_bfloat16* __restrict__ Kh, __nv_bfloat16* __restrict__ Kl,
    float* __restrict__ Vf, float qscale)
{
#if TCGEN05_OK
    extern __shared__ char smem[];
    const uint32_t sb = smem_u32(smem);
    const int tid = threadIdx.x;
    const int wid = tid >> 5;
    const int lid = tid & 31;
    const int rgn = blockIdx.x >> 4;           // 0=Q,1=K,2=V
    const int bn  = (blockIdx.x & 15) * 128;
    const int bm  = blockIdx.y * 128;
    const int N   = D_MODEL, K = D_MODEL;

    if (wid == 0) { tmem_alloc(sb, 128); tmem_relinquish(); }
    if (tid == 0) { mbar_init(sb + 8, 1); mbar_init(sb + 16, 1); }
    __syncthreads();
    uint32_t tmem;
    asm volatile("ld.shared.b32 %0, [%1];" : "=r"(tmem) : "r"(sb));

    gemm_mainloop(smem, sb, tmem, tid, wid, Ahi, Alo,
                  Whi + (size_t)rgn * DD, Wlo + (size_t)rgn * DD, bm, bn, K);

    const float scale = (rgn == 0) ? qscale : 1.0f;
    float* st = (float*)(smem + OFF_A0);
#pragma unroll
    for (int half = 0; half < 2; half++) {
        if (wid < 4) {
            uint32_t d0[32], d1[32];
            ldtm_x32(d0, tmem + half * 64);
            ldtm_x32(d1, tmem + half * 64 + 32);
            tcg_wait_ld();
            float* srow = st + (wid * 32 + lid) * 68;
#pragma unroll
            for (int c = 0; c < 32; c++) {
                srow[c]      = __uint_as_float(d0[c]);
                srow[32 + c] = __uint_as_float(d1[c]);
            }
        }
        __syncthreads();
#pragma unroll
        for (int j = 0; j < 8; j++) {
            int u = tid + j * 256;
            int row = u >> 4, c4 = u & 15;
            float4 v = *(const float4*)(st + row * 68 + c4 * 4);
            size_t grow = (size_t)(bm + row);
            int gcol = bn + half * 64 + c4 * 4;
            if (rgn == 2) {
                *(float4*)(Vf + grow * N + gcol) = v;
            } else {
                float v0 = v.x * scale, v1 = v.y * scale;
                float v2 = v.z * scale, v3 = v.w * scale;
                __nv_bfloat16 h0 = __float2bfloat16(v0);
                __nv_bfloat16 h1 = __float2bfloat16(v1);
                __nv_bfloat16 h2 = __float2bfloat16(v2);
                __nv_bfloat16 h3 = __float2bfloat16(v3);
                uint2 hh, ll;
                hh.x = pack_bf2(v0, v1); hh.y = pack_bf2(v2, v3);
                ll.x = pack_bf2(v0 - __bfloat162float(h0), v1 - __bfloat162float(h1));
                ll.y = pack_bf2(v2 - __bfloat162float(h2), v3 - __bfloat162float(h3));
                __nv_bfloat16* H = (rgn == 0) ? Qh : Kh;
                __nv_bfloat16* L = (rgn == 0) ? Ql : Kl;
                *(uint2*)(H + grow * N + gcol) = hh;
                *(uint2*)(L + grow * N + gcol) = ll;
            }
        }
        __syncthreads();
    }
    if (tid == 0) { mbar_inval(sb + 8); mbar_inval(sb + 16); }
    if (wid == 0) tmem_dealloc(tmem, 128);
#endif
}

// ---------------- persistent tcgen05 flash attention ----------------
#define AT_RED    1024
#define AT_RED2   2048
#define AT_QHI    3072
#define AT_QLO    35840
#define AT_KV0    68608                // KHI | KLO(+16K) | VTHI(+32K) | VTLO(+48K)
#define AT_KV1    134144
#define AT_PHI    199680
#define AT_PLO    216064
#define AT_TOTAL  232448               // 227 KB
#define AT_STAGE  AT_KV0

#if TCGEN05_OK
__device__ __forceinline__ void fill_K(
    char* smem, uint32_t kvb,
    const __nv_bfloat16* __restrict__ Khi, const __nv_bfloat16* __restrict__ Klo,
    int tid, int b, int h, int jt)
{
#pragma unroll
    for (int j = 0; j < 4; j++) {
        int u = tid + j * 256;
        int row = u >> 4, cu = u & 15;
        size_t g = ((size_t)(b * S_LEN + jt * 64 + row)) * D_MODEL + h * DHEAD + cu * 8;
        uint32_t bo = ((uint32_t)(row >> 3) + ((uint32_t)(cu >> 3) << 3)) * 1024u
                    + (uint32_t)(row & 7) * 128u + (uint32_t)(cu & 7) * 16u;
        uint32_t sw = sw128(bo);
        *(uint4*)(smem + kvb + sw)         = *(const uint4*)(Khi + g);
        *(uint4*)(smem + kvb + 16384 + sw) = *(const uint4*)(Klo + g);
    }
}
__device__ __forceinline__ void fill_V(
    char* smem, uint32_t kvb,
    const __nv_bfloat16* __restrict__ VThi, const __nv_bfloat16* __restrict__ VTlo,
    int tid, int bh, int jt)
{
#pragma unroll
    for (int j = 0; j < 4; j++) {
        int u = tid + j * 256;
        int row = u >> 3, cu = u & 7;
        size_t g = ((size_t)(bh * DHEAD + row)) * S_LEN + jt * 64 + cu * 8;
        uint32_t bo = (uint32_t)(row >> 3) * 1024u
                    + (uint32_t)(row & 7) * 128u + (uint32_t)cu * 16u;
        uint32_t sw = sw128(bo);
        *(uint4*)(smem + kvb + 32768 + sw) = *(const uint4*)(VThi + g);
        *(uint4*)(smem + kvb + 49152 + sw) = *(const uint4*)(VTlo + g);
    }
}
__device__ __forceinline__ void issue_qk(uint32_t sb, uint32_t S_T, uint32_t kvb) {
    uint64_t dQh = DESC_BASE | ((uint64_t)((sb + AT_QHI) >> 4) & 0x3FFF);
    uint64_t dQl = DESC_BASE | ((uint64_t)((sb + AT_QLO) >> 4) & 0x3FFF);
    uint64_t dKh = DESC_BASE | ((uint64_t)((sb + kvb) >> 4) & 0x3FFF);
    uint64_t dKl = DESC_BASE | ((uint64_t)((sb + kvb + 16384) >> 4) & 0x3FFF);
    const uint64_t qo[8] = {0, 2, 4, 6, 1024, 1026, 1028, 1030};
    const uint64_t ko[8] = {0, 2, 4, 6, 512, 514, 516, 518};
    uint64_t aT[3] = {dQh, dQh, dQl};
    uint64_t bT[3] = {dKh, dKl, dKh};
#pragma unroll
    for (int t = 0; t < 3; t++)
#pragma unroll
        for (int s = 0; s < 8; s++)
            mma_f16_ss(S_T, aT[t] + qo[s], bT[t] + ko[s], IDESC_N64, !(t == 0 && s == 0));
    mma_commit(sb + 8);
}
__device__ __forceinline__ void issue_pv(uint32_t sb, uint32_t O_T, uint32_t kvb,
                                         int do_commit) {
    uint64_t dPh = DESC_BASE | ((uint64_t)((sb + AT_PHI) >> 4) & 0x3FFF);
    uint64_t dPl = DESC_BASE | ((uint64_t)((sb + AT_PLO) >> 4) & 0x3FFF);
    uint64_t dVh = DESC_BASE | ((uint64_t)((sb + kvb + 32768) >> 4) & 0x3FFF);
    uint64_t dVl = DESC_BASE | ((uint64_t)((sb + kvb + 49152) >> 4) & 0x3FFF);
    uint64_t aT[3] = {dPh, dPh, dPl};
    uint64_t bT[3] = {dVh, dVl, dVh};
#pragma unroll
    for (int t = 0; t < 3; t++)
#pragma unroll
        for (int s = 0; s < 4; s++)
            mma_f16_ss(O_T, aT[t] + 2 * s, bT[t] + 2 * s, IDESC_N128, !(t == 0 && s == 0));
    if (do_commit) mma_commit(sb + 16);
}
#endif

__global__ __launch_bounds__(256) void attn_tc_kernel(
    const __nv_bfloat16* __restrict__ Qhi, const __nv_bfloat16* __restrict__ Qlo,
    const __nv_bfloat16* __restrict__ Khi, const __nv_bfloat16* __restrict__ Klo,
    const __nv_bfloat16* __restrict__ VThi, const __nv_bfloat16* __restrict__ VTlo,
    __nv_bfloat16* __restrict__ Yhi, __nv_bfloat16* __restrict__ Ylo)
{
#if TCGEN05_OK
    extern __shared__ char smem[];
    const uint32_t sb = smem_u32(smem);
    const int tid = threadIdx.x;
    const int w   = tid >> 5;
    const int l   = tid & 31;
    const int r   = (w & 3) * 32 + l;
    const int hf  = w >> 2;
    const uint32_t woff = (uint32_t)(w & 3) << 21;

    if (w == 0) { tmem_alloc(sb, 512); tmem_relinquish(); }
    if (tid == 0) { mbar_init(sb + 8, 1); mbar_init(sb + 16, 1); }
    __syncthreads();
    uint32_t tmem;
    asm volatile("ld.shared.b32 %0, [%1];" : "=r"(tmem) : "r"(sb));
    const uint32_t S_T  = tmem;          // cols 0..63
    const uint32_t O_T0 = tmem + 64;     // cols 64..191
    const uint32_t O_T1 = tmem + 192;    // cols 192..319

    uint32_t phS = 0, phO = 0;

    for (int rnd = 0; rnd < 4; rnd++) {
        int s = rnd * NSM + ((rnd & 1) ? (NSM - 1 - (int)blockIdx.x)
                                       : (int)blockIdx.x);
        if (s >= NITEMS) continue;
        const int qt = 15 - (s >> 5);     // descending work (serpentine LPT)
        const int bh = s & 31;
        const int b  = bh >> 4;
        const int h  = bh & 15;
        const int njt = 2 * qt + 2;
        const int qg = qt * 128 + r;

        // ---- load Q tile (hi+lo) ----
#pragma unroll
        for (int j = 0; j < 8; j++) {
            int u = tid + j * 256;
            int row = u >> 4, cu = u & 15;
            size_t g = ((size_t)(b * S_LEN + qt * 128 + row)) * D_MODEL + h * DHEAD + cu * 8;
            uint32_t bo = ((uint32_t)(row >> 3) + ((uint32_t)(cu >> 3) << 4)) * 1024u
                        + (uint32_t)(row & 7) * 128u + (uint32_t)(cu & 7) * 16u;
            uint32_t sw = sw128(bo);
            *(uint4*)(smem + AT_QHI + sw) = *(const uint4*)(Qhi + g);
            *(uint4*)(smem + AT_QLO + sw) = *(const uint4*)(Qlo + g);
        }

        fill_K(smem, AT_KV0, Khi, Klo, tid, b, h, 0);
        fill_V(smem, AT_KV0, VThi, VTlo, tid, bh, 0);
        __syncthreads();
        if (w == 0 && elect1()) {
            fence_proxy_async_s();
            issue_qk(sb, S_T, AT_KV0);
        }

        float m_run = -1e30f, l_run = 0.0f, corr_prev = 0.0f;
        float O[64];
#pragma unroll
        for (int j = 0; j < 64; j++) O[j] = 0.0f;

        for (int jt = 0; jt < njt; jt++) {
            const uint32_t kvb  = (jt & 1) ? AT_KV1 : AT_KV0;
            const uint32_t kvbn = (jt & 1) ? AT_KV0 : AT_KV1;

            // K-part of next tile: last reader QK(jt-1) long done
            if (jt + 1 < njt) fill_K(smem, kvbn, Khi, Klo, tid, b, h, jt + 1);

            mbar_wait(sb + 8, phS); phS ^= 1;     // implies PV(jt-1) complete
            tcg_fence_after();

            uint32_t sr_[32];
            ldtm_x32(sr_, S_T + hf * 32 + woff);
            tcg_wait_ld();

            // V-part of next tile: safe now (PV(jt-1) done)
            if (jt + 1 < njt) fill_V(smem, kvbn, VThi, VTlo, tid, bh, jt + 1);

            // accumulate previous PV tile (overlaps nothing on tensor; free now)
            if (jt > 0) {
                const uint32_t OP = (jt & 1) ? O_T0 : O_T1;   // buffer (jt-1)&1
                uint32_t o0[32];
                ldtm_x32(o0, OP + hf * 64 + woff);
                tcg_wait_ld();
#pragma unroll
                for (int j = 0; j < 32; j++)
                    O[j] = fmaf(O[j], corr_prev, __uint_as_float(o0[j]));
                ldtm_x32(o0, OP + hf * 64 + 32 + woff);
                tcg_wait_ld();
#pragma unroll
                for (int j = 0; j < 32; j++)
                    O[32 + j] = fmaf(O[32 + j], corr_prev, __uint_as_float(o0[j]));
            }

            // ---- softmax ----
            float sv[32];
            const int kgb = jt * 64 + hf * 32;
#pragma unroll
            for (int i = 0; i < 32; i++) {
                float x = __uint_as_float(sr_[i]);
                sv[i] = (kgb + i > qg) ? -1e30f : x;
            }
            float tmax = -1e30f;
#pragma unroll
            for (int i = 0; i < 32; i++) tmax = fmaxf(tmax, sv[i]);
            float* red1 = (float*)(smem + AT_RED);
            float* red2 = (float*)(smem + AT_RED2);
            red1[hf * 128 + r] = tmax;
            __syncthreads();
            tmax = fmaxf(tmax, red1[(1 - hf) * 128 + r]);
            float mnew = fmaxf(m_run, tmax);
            float corr = __expf(m_run - mnew);
            float p[32], psum = 0.0f;
#pragma unroll
            for (int i = 0; i < 32; i++) {
                p[i] = __expf(sv[i] - mnew);
                psum += p[i];
            }
            red2[hf * 128 + r] = psum;
            __syncthreads();
            l_run = l_run * corr + psum + red2[(1 - hf) * 128 + r];
            m_run = mnew;

            // ---- P -> bf16 hi/lo ----
            {
                uint32_t rowbase = (uint32_t)(r >> 3) * 1024u + (uint32_t)(r & 7) * 128u;
#pragma unroll
                for (int i = 0; i < 32; i += 2) {
                    float p0 = p[i], p1 = p[i + 1];
                    __nv_bfloat16 h0 = __float2bfloat16(p0);
                    __nv_bfloat16 h1 = __float2bfloat16(p1);
                    uint32_t hp = pack_bf2(p0, p1);
                    uint32_t lp = pack_bf2(p0 - __bfloat162float(h0),
                                           p1 - __bfloat162float(h1));
                    uint32_t sw = sw128(rowbase + (uint32_t)(hf * 32 + i) * 2u);
                    *(uint32_t*)(smem + AT_PHI + sw) = hp;
                    *(uint32_t*)(smem + AT_PLO + sw) = lp;
                }
            }
            __syncthreads();   // P + next-KV fill visible; S fully consumed

            if (w == 0 && elect1()) {
                fence_proxy_async_s();
                issue_pv(sb, (jt & 1) ? O_T1 : O_T0, kvb, jt == njt - 1);
                if (jt + 1 < njt) issue_qk(sb, S_T, kvbn);
            }
            corr_prev = corr;
        }

        // final PV tile
        mbar_wait(sb + 16, phO); phO ^= 1;
        tcg_fence_after();
        {
            const uint32_t OP = ((njt - 1) & 1) ? O_T1 : O_T0;
            uint32_t o0[32];
            ldtm_x32(o0, OP + hf * 64 + woff);
            tcg_wait_ld();
#pragma unroll
            for (int j = 0; j < 32; j++)
                O[j] = fmaf(O[j], corr_prev, __uint_as_float(o0[j]));
            ldtm_x32(o0, OP + hf * 64 + 32 + woff);
            tcg_wait_ld();
#pragma unroll
            for (int j = 0; j < 32; j++)
                O[32 + j] = fmaf(O[32 + j], corr_prev, __uint_as_float(o0[j]));
        }

        // ---- normalize + stage + write ----
        __syncthreads();   // KV buffers dead -> staging
        {
            float inv = 1.0f / l_run;
            float* st = (float*)(smem + AT_STAGE);
#pragma unroll
            for (int j = 0; j < 64; j += 4) {
                float4 v = make_float4(O[j] * inv, O[j + 1] * inv,
                                       O[j + 2] * inv, O[j + 3] * inv);
                *(float4*)(st + r * 132 + hf * 64 + j) = v;
            }
        }
        __syncthreads();
        {
            const float* st = (const float*)(smem + AT_STAGE);
#pragma unroll
            for (int j = 0; j < 16; j++) {
                int u = tid + j * 256;
                int row = u >> 5, c4 = u & 31;
                float4 v = *(const float4*)(st + row * 132 + c4 * 4);
                size_t g = ((size_t)(b * S_LEN + qt * 128 + row)) * D_MODEL + h * DHEAD + c4 * 4;
                __nv_bfloat16 h0 = __float2bfloat16(v.x);
                __nv_bfloat16 h1 = __float2bfloat16(v.y);
                __nv_bfloat16 h2 = __float2bfloat16(v.z);
                __nv_bfloat16 h3 = __float2bfloat16(v.w);
                uint2 hh, ll;
                hh.x = pack_bf2(v.x, v.y); hh.y = pack_bf2(v.z, v.w);
                ll.x = pack_bf2(v.x - __bfloat162float(h0), v.y - __bfloat162float(h1));
                ll.y = pack_bf2(v.z - __bfloat162float(h2), v.w - __bfloat162float(h3));
                *(uint2*)(Yhi + g) = hh;
                *(uint2*)(Ylo + g) = ll;
            }
        }
        __syncthreads();   // staging consumed before next item's fill
    }

    if (tid == 0) { mbar_inval(sb + 8); mbar_inval(sb + 16); }
    if (w == 0) tmem_dealloc(tmem, 512);
#endif
}

// ---------------- launch ----------------
extern "C" void kernel_launch(void* const* d_in, const int* in_sizes, int n_in,
                              void* d_out, int out_size)
{
    (void)in_sizes; (void)n_in; (void)out_size;
    const float* x  = (const float*)d_in[0];
    const float* Wq = (const float*)d_in[2];
    const float* Wk = (const float*)d_in[3];
    const float* Wv = (const float*)d_in[4];
    const float* Wo = (const float*)d_in[5];
    float* out = (float*)d_out;

    float* Vb;
    cudaGetSymbolAddress((void**)&Vb, g_V);
    __nv_bfloat16 *xhi, *xlo, *yhi, *ylo, *whi, *wlo;
    __nv_bfloat16 *qhi, *qlo, *khi, *klo, *vthi, *vtlo;
    cudaGetSymbolAddress((void**)&xhi, g_xhi);
    cudaGetSymbolAddress((void**)&xlo, g_xlo);
    cudaGetSymbolAddress((void**)&yhi, g_yhi);
    cudaGetSymbolAddress((void**)&ylo, g_ylo);
    cudaGetSymbolAddress((void**)&whi, g_whi);
    cudaGetSymbolAddress((void**)&wlo, g_wlo);
    cudaGetSymbolAddress((void**)&qhi, g_qhi);
    cudaGetSymbolAddress((void**)&qlo, g_qlo);
    cudaGetSymbolAddress((void**)&khi, g_khi);
    cudaGetSymbolAddress((void**)&klo, g_klo);
    cudaGetSymbolAddress((void**)&vthi, g_vthi);
    cudaGetSymbolAddress((void**)&vtlo, g_vtlo);

    cudaFuncSetAttribute(gemm_qkv_kernel,
                         cudaFuncAttributeMaxDynamicSharedMemorySize, GSMEM_TOTAL);
    cudaFuncSetAttribute(gemm_out_kernel,
                         cudaFuncAttributeMaxDynamicSharedMemorySize, GSMEM_TOTAL);
    cudaFuncSetAttribute(attn_tc_kernel,
                         cudaFuncAttributeMaxDynamicSharedMemorySize, AT_TOTAL);

    const int n4x = M_ROWS * D_MODEL / 4;
    const int n4w = DD / 4;
    split_bf16_kernel<<<n4x / 256, 256>>>(x, xhi, xlo, n4x);
    wsplit4_kernel<<<dim3(n4w / 256, 4), 256>>>(Wq, Wk, Wv, Wo, whi, wlo, n4w);

    const float qscale = 0.08838834764831845f;   // 1/sqrt(128)
    gemm_qkv_kernel<<<dim3(48, 32), 256, GSMEM_TOTAL>>>(
        xhi, xlo, whi, wlo, qhi, qlo, khi, klo, Vb, qscale);

    vtrans_kernel<<<dim3(S_LEN / 32, D_MODEL / 32, NBATCH), dim3(32, 8)>>>(Vb, vthi, vtlo);

    attn_tc_kernel<<<NSM, 256, AT_TOTAL>>>(qhi, qlo, khi, klo, vthi, vtlo, yhi, ylo);

    gemm_out_kernel<<<dim3(16, 32), 256, GSMEM_TOTAL>>>(
        yhi, ylo, whi + 3 * (size_t)DD, wlo + 3 * (size_t)DD, out, D_MODEL, D_MODEL);
}

// round 8
// speedup vs baseline: 9.0037x; 1.0763x over previous
#include <cuda_runtime.h>
#include <cuda.h>
#include <cuda_bf16.h>
#include <math.h>
#include <stdint.h>

#if defined(__CUDA_ARCH__)
#if defined(__CUDA_ARCH_FEAT_SM103_ALL) || defined(__CUDA_ARCH_FEAT_SM100_ALL) || defined(__CUDA_ARCH_FEAT_SM101_ALL)
#define TCGEN05_OK 1
#else
#define TCGEN05_OK 0
#endif
#else
#define TCGEN05_OK 0
#endif

#define NBATCH  2
#define S_LEN   2048
#define D_MODEL 2048
#define DHEAD   128
#define M_ROWS  4096
#define DD      (D_MODEL * D_MODEL)
#define NSM     148
#define NITEMS  512
#define LOG2E   1.4426950408889634f

// ---------------- scratch ----------------
__device__ float g_V[(size_t)M_ROWS * D_MODEL];
__device__ __nv_bfloat16 g_xhi[(size_t)M_ROWS * D_MODEL];
__device__ __nv_bfloat16 g_xlo[(size_t)M_ROWS * D_MODEL];
__device__ __nv_bfloat16 g_yhi[(size_t)M_ROWS * D_MODEL];
__device__ __nv_bfloat16 g_ylo[(size_t)M_ROWS * D_MODEL];
__device__ __nv_bfloat16 g_whi[(size_t)4 * DD];
__device__ __nv_bfloat16 g_wlo[(size_t)4 * DD];
__device__ __nv_bfloat16 g_qhi[(size_t)M_ROWS * D_MODEL];
__device__ __nv_bfloat16 g_qlo[(size_t)M_ROWS * D_MODEL];
__device__ __nv_bfloat16 g_khi[(size_t)M_ROWS * D_MODEL];
__device__ __nv_bfloat16 g_klo[(size_t)M_ROWS * D_MODEL];
__device__ __nv_bfloat16 g_vthi[(size_t)M_ROWS * D_MODEL];  // [b*2048+d][s]
__device__ __nv_bfloat16 g_vtlo[(size_t)M_ROWS * D_MODEL];

// ---------------- PTX helpers ----------------
__device__ __forceinline__ uint32_t smem_u32(const void* p) {
    uint32_t a;
    asm("{ .reg .u64 t; cvta.to.shared.u64 t, %1; cvt.u32.u64 %0, t; }"
        : "=r"(a) : "l"(p));
    return a;
}
__device__ __forceinline__ uint32_t elect1() {
#if TCGEN05_OK
    uint32_t p;
    asm volatile(
        "{\n\t.reg .pred p;\n\t"
        "elect.sync _|p, 0xFFFFFFFF;\n\t"
        "selp.b32 %0, 1, 0, p;\n\t}"
        : "=r"(p));
    return p;
#else
    return 0;
#endif
}
__device__ __forceinline__ void mbar_init(uint32_t addr, uint32_t count) {
    asm volatile("mbarrier.init.shared.b64 [%0], %1;" :: "r"(addr), "r"(count) : "memory");
}
__device__ __forceinline__ void mbar_inval(uint32_t addr) {
    asm volatile("mbarrier.inval.shared.b64 [%0];" :: "r"(addr) : "memory");
}
__device__ __forceinline__ void mbar_wait(uint32_t addr, uint32_t parity) {
    asm volatile(
        "{\n\t.reg .pred P;\n\t"
        "WL_%=:\n\t"
        "mbarrier.try_wait.parity.acquire.cta.shared::cta.b64 P, [%0], %1, 0x989680;\n\t"
        "@P bra.uni WD_%=;\n\t"
        "bra.uni WL_%=;\n\t"
        "WD_%=:\n\t}"
        :: "r"(addr), "r"(parity) : "memory");
}
__device__ __forceinline__ void mbar_expect(uint32_t mbar, uint32_t bytes) {
    asm volatile("mbarrier.arrive.expect_tx.shared.b64 _, [%0], %1;"
                 :: "r"(mbar), "r"(bytes) : "memory");
}
__device__ __forceinline__ void tma2d(uint32_t dst, const CUtensorMap* m,
                                      int x, int y, uint32_t mbar) {
    asm volatile(
        "cp.async.bulk.tensor.2d.shared::cta.global.tile.mbarrier::complete_tx::bytes "
        "[%0], [%1, {%2, %3}], [%4];"
        :: "r"(dst), "l"(m), "r"(x), "r"(y), "r"(mbar) : "memory");
}
__device__ __forceinline__ void tmem_alloc(uint32_t smem_dst, uint32_t ncols) {
#if TCGEN05_OK
    asm volatile("tcgen05.alloc.cta_group::1.sync.aligned.shared::cta.b32 [%0], %1;"
                 :: "r"(smem_dst), "r"(ncols) : "memory");
#endif
}
__device__ __forceinline__ void tmem_dealloc(uint32_t tmem, uint32_t ncols) {
#if TCGEN05_OK
    asm volatile("tcgen05.dealloc.cta_group::1.sync.aligned.b32 %0, %1;"
                 :: "r"(tmem), "r"(ncols));
#endif
}
__device__ __forceinline__ void tmem_relinquish() {
#if TCGEN05_OK
    asm volatile("tcgen05.relinquish_alloc_permit.cta_group::1.sync.aligned;");
#endif
}
__device__ __forceinline__ void mma_f16_ss(uint32_t d_tmem, uint64_t a_desc,
                                           uint64_t b_desc, uint32_t idesc,
                                           uint32_t enable_d) {
#if TCGEN05_OK
    asm volatile(
        "{\n\t.reg .pred p;\n\t"
        "setp.ne.u32 p, %4, 0;\n\t"
        "tcgen05.mma.cta_group::1.kind::f16 [%0], %1, %2, %3, {%5, %5, %5, %5}, p;\n\t}"
        :: "r"(d_tmem), "l"(a_desc), "l"(b_desc), "r"(idesc), "r"(enable_d), "r"(0u)
        : "memory");
#endif
}
__device__ __forceinline__ void mma_commit(uint32_t mbar_addr) {
#if TCGEN05_OK
    asm volatile(
        "tcgen05.commit.cta_group::1.mbarrier::arrive::one.shared::cluster.b64 [%0];"
        :: "r"(mbar_addr) : "memory");
#endif
}
__device__ __forceinline__ void tcg_fence_after() {
#if TCGEN05_OK
    asm volatile("tcgen05.fence::after_thread_sync;" ::: "memory");
#endif
}
__device__ __forceinline__ void fence_proxy_async_s() {
    asm volatile("fence.proxy.async.shared::cta;" ::: "memory");
}
__device__ __forceinline__ void tcg_wait_ld() {
#if TCGEN05_OK
    asm volatile("tcgen05.wait::ld.sync.aligned;" ::: "memory");
#endif
}
__device__ __forceinline__ void ldtm_x32(uint32_t* r, uint32_t addr) {
#if TCGEN05_OK
    asm volatile(
        "tcgen05.ld.sync.aligned.32x32b.x32.b32 "
        "{%0, %1, %2, %3, %4, %5, %6, %7, "
        " %8, %9, %10, %11, %12, %13, %14, %15, "
        " %16, %17, %18, %19, %20, %21, %22, %23, "
        " %24, %25, %26, %27, %28, %29, %30, %31}, [%32];"
        : "=r"(r[0]),  "=r"(r[1]),  "=r"(r[2]),  "=r"(r[3]),
          "=r"(r[4]),  "=r"(r[5]),  "=r"(r[6]),  "=r"(r[7]),
          "=r"(r[8]),  "=r"(r[9]),  "=r"(r[10]), "=r"(r[11]),
          "=r"(r[12]), "=r"(r[13]), "=r"(r[14]), "=r"(r[15]),
          "=r"(r[16]), "=r"(r[17]), "=r"(r[18]), "=r"(r[19]),
          "=r"(r[20]), "=r"(r[21]), "=r"(r[22]), "=r"(r[23]),
          "=r"(r[24]), "=r"(r[25]), "=r"(r[26]), "=r"(r[27]),
          "=r"(r[28]), "=r"(r[29]), "=r"(r[30]), "=r"(r[31])
        : "r"(addr));
#else
    for (int i = 0; i < 32; i++) r[i] = 0;
#endif
}

#define DESC_BASE ((2ull << 61) | (1ull << 46) | (64ull << 32) | (1ull << 16))
#define IDESC_N128 ((1u << 4) | (1u << 7) | (1u << 10) | (16u << 17) | (8u << 24))
#define IDESC_N64  ((1u << 4) | (1u << 7) | (1u << 10) | (8u << 17)  | (8u << 24))

__device__ __forceinline__ uint32_t sw128(uint32_t bo) {
    return bo ^ ((bo >> 3) & 0x70);
}
__device__ __forceinline__ uint32_t pack_bf2(float a, float b) {
    __nv_bfloat162 v;
    v.x = __float2bfloat16(a);
    v.y = __float2bfloat16(b);
    return *(uint32_t*)&v;
}
__device__ __forceinline__ float ex2f(float x) {
    float y;
    asm("ex2.approx.ftz.f32 %0, %1;" : "=f"(y) : "f"(x));
    return y;
}

// ---------------- fp32 -> (hi, lo) bf16 split ----------------
__device__ __forceinline__ void split_body(const float* src, __nv_bfloat16* hi,
                                           __nv_bfloat16* lo, int i) {
    float4 v = ((const float4*)src)[i];
    __nv_bfloat16 h0 = __float2bfloat16(v.x);
    __nv_bfloat16 h1 = __float2bfloat16(v.y);
    __nv_bfloat16 h2 = __float2bfloat16(v.z);
    __nv_bfloat16 h3 = __float2bfloat16(v.w);
    uint2 hh, ll;
    hh.x = pack_bf2(v.x, v.y); hh.y = pack_bf2(v.z, v.w);
    ll.x = pack_bf2(v.x - __bfloat162float(h0), v.y - __bfloat162float(h1));
    ll.y = pack_bf2(v.z - __bfloat162float(h2), v.w - __bfloat162float(h3));
    *(uint2*)(hi + 4 * (size_t)i) = hh;
    *(uint2*)(lo + 4 * (size_t)i) = ll;
}

__global__ __launch_bounds__(256) void split_bf16_kernel(
    const float* __restrict__ src,
    __nv_bfloat16* __restrict__ hi, __nv_bfloat16* __restrict__ lo, int n4)
{
    int i = blockIdx.x * 256 + threadIdx.x;
    if (i < n4) split_body(src, hi, lo, i);
}

__global__ __launch_bounds__(256) void wsplit4_kernel(
    const float* __restrict__ s0, const float* __restrict__ s1,
    const float* __restrict__ s2, const float* __restrict__ s3,
    __nv_bfloat16* __restrict__ hi, __nv_bfloat16* __restrict__ lo, int n4)
{
    int i = blockIdx.x * 256 + threadIdx.x;
    if (i >= n4) return;
    int k = blockIdx.y;
    const float* src = (k == 0) ? s0 : (k == 1) ? s1 : (k == 2) ? s2 : s3;
    split_body(src, hi + (size_t)k * DD, lo + (size_t)k * DD, i);
}

// ---------------- V transpose + split ----------------
__global__ __launch_bounds__(256) void vtrans_kernel(
    const float* __restrict__ V,
    __nv_bfloat16* __restrict__ vthi, __nv_bfloat16* __restrict__ vtlo)
{
    __shared__ float t[32][33];
    const int b  = blockIdx.z;
    const int s0 = blockIdx.x * 32;
    const int d0 = blockIdx.y * 32;
    const int tx = threadIdx.x;
    const int ty = threadIdx.y;
#pragma unroll
    for (int i = 0; i < 4; i++) {
        int s = s0 + ty + i * 8;
        t[ty + i * 8][tx] = V[((size_t)b * S_LEN + s) * D_MODEL + d0 + tx];
    }
    __syncthreads();
#pragma unroll
    for (int i = 0; i < 4; i++) {
        int d = d0 + ty + i * 8;
        float v = t[tx][ty + i * 8];
        __nv_bfloat16 h = __float2bfloat16(v);
        __nv_bfloat16 l = __float2bfloat16(v - __bfloat162float(h));
        size_t o = ((size_t)b * D_MODEL + d) * S_LEN + s0 + tx;
        vthi[o] = h;
        vtlo[o] = l;
    }
}

// ---------------- GEMM (round-6 verified, unchanged) ----------------
#define OFF_A0 1024
#define OFF_B0 (1024 + 16384)
#define OFF_A1 (1024 + 2 * 16384)
#define OFF_B1 (1024 + 3 * 16384)
#define GSMEM_TOTAL (1024 + 4 * 16384)

#if TCGEN05_OK
__device__ __forceinline__ void gemm_mainloop(
    char* smem, uint32_t sb, uint32_t tmem, int tid, int wid,
    const __nv_bfloat16* Ahi, const __nv_bfloat16* Alo,
    const __nv_bfloat16* Bhi, const __nv_bfloat16* Blo,
    int bm, int bn, int K)
{
    const int nk = K / 64;
    const int nchunks = 3 * nk;
    uint32_t ph0 = 0, ph1 = 0;
    for (int i = 0; i < nchunks; i++) {
        const int term = i / nk;
        const int k0 = (i - term * nk) * 64;
        const __nv_bfloat16* As = (term == 2) ? Alo : Ahi;
        const __nv_bfloat16* Bs = (term == 1) ? Blo : Bhi;
        uint4 ra[4], rb[4];
#pragma unroll
        for (int j = 0; j < 4; j++) {
            int u = tid + j * 256;
            int r = u >> 3, cs = u & 7;
            ra[j] = *(const uint4*)(As + (size_t)(bm + r) * K + k0 + cs * 8);
            rb[j] = *(const uint4*)(Bs + (size_t)(bn + r) * K + k0 + cs * 8);
        }
        const int buf = i & 1;
        if (i >= 2) {
            if (buf == 0) { mbar_wait(sb + 8, ph0);  ph0 ^= 1; }
            else          { mbar_wait(sb + 16, ph1); ph1 ^= 1; }
        }
        const uint32_t offA = buf ? OFF_A1 : OFF_A0;
        const uint32_t offB = buf ? OFF_B1 : OFF_B0;
#pragma unroll
        for (int j = 0; j < 4; j++) {
            int u = tid + j * 256;
            uint32_t sw = sw128((uint32_t)u * 16u);
            *(uint4*)(smem + offA + sw) = ra[j];
            *(uint4*)(smem + offB + sw) = rb[j];
        }
        __syncthreads();
        if (wid == 0 && elect1()) {
            fence_proxy_async_s();
            uint64_t ad = DESC_BASE | ((uint64_t)((sb + offA) >> 4) & 0x3FFF);
            uint64_t bd = DESC_BASE | ((uint64_t)((sb + offB) >> 4) & 0x3FFF);
#pragma unroll
            for (int k = 0; k < 4; k++) {
                uint32_t en = !(i == 0 && k == 0);
                mma_f16_ss(tmem, ad + k * 2, bd + k * 2, IDESC_N128, en);
            }
            mma_commit(buf ? (sb + 16) : (sb + 8));
        }
    }
    mbar_wait(sb + 16, ph1);
    tcg_fence_after();
    __syncthreads();
}
#endif

__global__ __launch_bounds__(256) void gemm_out_kernel(
    const __nv_bfloat16* __restrict__ Ahi, const __nv_bfloat16* __restrict__ Alo,
    const __nv_bfloat16* __restrict__ Bhi, const __nv_bfloat16* __restrict__ Blo,
    float* __restrict__ C, int K, int N)
{
#if TCGEN05_OK
    extern __shared__ char smem[];
    const uint32_t sb = smem_u32(smem);
    const int tid = threadIdx.x;
    const int wid = tid >> 5;
    const int lid = tid & 31;
    const int bm = blockIdx.y * 128;
    const int bn = blockIdx.x * 128;

    if (wid == 0) { tmem_alloc(sb, 128); tmem_relinquish(); }
    if (tid == 0) { mbar_init(sb + 8, 1); mbar_init(sb + 16, 1); }
    __syncthreads();
    uint32_t tmem;
    asm volatile("ld.shared.b32 %0, [%1];" : "=r"(tmem) : "r"(sb));

    gemm_mainloop(smem, sb, tmem, tid, wid, Ahi, Alo, Bhi, Blo, bm, bn, K);

    float* st = (float*)(smem + OFF_A0);
#pragma unroll
    for (int half = 0; half < 2; half++) {
        if (wid < 4) {
            uint32_t d0[32], d1[32];
            ldtm_x32(d0, tmem + half * 64);
            ldtm_x32(d1, tmem + half * 64 + 32);
            tcg_wait_ld();
            float* srow = st + (wid * 32 + lid) * 68;
#pragma unroll
            for (int c = 0; c < 32; c++) {
                srow[c]      = __uint_as_float(d0[c]);
                srow[32 + c] = __uint_as_float(d1[c]);
            }
        }
        __syncthreads();
#pragma unroll
        for (int j = 0; j < 8; j++) {
            int u = tid + j * 256;
            int row = u >> 4, c4 = u & 15;
            float4 v = *(const float4*)(st + row * 68 + c4 * 4);
            *(float4*)(C + (size_t)(bm + row) * N + bn + half * 64 + c4 * 4) = v;
        }
        __syncthreads();
    }
    if (tid == 0) { mbar_inval(sb + 8); mbar_inval(sb + 16); }
    if (wid == 0) tmem_dealloc(tmem, 128);
#endif
}

__global__ __launch_bounds__(256) void gemm_qkv_kernel(
    const __nv_bfloat16* __restrict__ Ahi, const __nv_bfloat16* __restrict__ Alo,
    const __nv_bfloat16* __restrict__ Whi, const __nv_bfloat16* __restrict__ Wlo,
    __nv_bfloat16* __restrict__ Qh, __nv_bfloat16* __restrict__ Ql,
    __nv_bfloat16* __restrict__ Kh, __nv_bfloat16* __restrict__ Kl,
    float* __restrict__ Vf, float qscale)
{
#if TCGEN05_OK
    extern __shared__ char smem[];
    const uint32_t sb = smem_u32(smem);
    const int tid = threadIdx.x;
    const int wid = tid >> 5;
    const int lid = tid & 31;
    const int rgn = blockIdx.x >> 4;
    const int bn  = (blockIdx.x & 15) * 128;
    const int bm  = blockIdx.y * 128;
    const int N   = D_MODEL, K = D_MODEL;

    if (wid == 0) { tmem_alloc(sb, 128); tmem_relinquish(); }
    if (tid == 0) { mbar_init(sb + 8, 1); mbar_init(sb + 16, 1); }
    __syncthreads();
    uint32_t tmem;
    asm volatile("ld.shared.b32 %0, [%1];" : "=r"(tmem) : "r"(sb));

    gemm_mainloop(smem, sb, tmem, tid, wid, Ahi, Alo,
                  Whi + (size_t)rgn * DD, Wlo + (size_t)rgn * DD, bm, bn, K);

    const float scale = (rgn == 0) ? qscale : 1.0f;
    float* st = (float*)(smem + OFF_A0);
#pragma unroll
    for (int half = 0; half < 2; half++) {
        if (wid < 4) {
            uint32_t d0[32], d1[32];
            ldtm_x32(d0, tmem + half * 64);
            ldtm_x32(d1, tmem + half * 64 + 32);
            tcg_wait_ld();
            float* srow = st + (wid * 32 + lid) * 68;
#pragma unroll
            for (int c = 0; c < 32; c++) {
                srow[c]      = __uint_as_float(d0[c]);
                srow[32 + c] = __uint_as_float(d1[c]);
            }
        }
        __syncthreads();
#pragma unroll
        for (int j = 0; j < 8; j++) {
            int u = tid + j * 256;
            int row = u >> 4, c4 = u & 15;
            float4 v = *(const float4*)(st + row * 68 + c4 * 4);
            size_t grow = (size_t)(bm + row);
            int gcol = bn + half * 64 + c4 * 4;
            if (rgn == 2) {
                *(float4*)(Vf + grow * N + gcol) = v;
            } else {
                float v0 = v.x * scale, v1 = v.y * scale;
                float v2 = v.z * scale, v3 = v.w * scale;
                __nv_bfloat16 h0 = __float2bfloat16(v0);
                __nv_bfloat16 h1 = __float2bfloat16(v1);
                __nv_bfloat16 h2 = __float2bfloat16(v2);
                __nv_bfloat16 h3 = __float2bfloat16(v3);
                uint2 hh, ll;
                hh.x = pack_bf2(v0, v1); hh.y = pack_bf2(v2, v3);
                ll.x = pack_bf2(v0 - __bfloat162float(h0), v1 - __bfloat162float(h1));
                ll.y = pack_bf2(v2 - __bfloat162float(h2), v3 - __bfloat162float(h3));
                __nv_bfloat16* H = (rgn == 0) ? Qh : Kh;
                __nv_bfloat16* L = (rgn == 0) ? Ql : Kl;
                *(uint2*)(H + grow * N + gcol) = hh;
                *(uint2*)(L + grow * N + gcol) = ll;
            }
        }
        __syncthreads();
    }
    if (tid == 0) { mbar_inval(sb + 8); mbar_inval(sb + 16); }
    if (wid == 0) tmem_dealloc(tmem, 128);
#endif
}

// ---------------- persistent tcgen05 flash attention (TMA fills) ------------
#define AT_RED    1024
#define AT_QHI    3072                 // 2 atom cols of 16K
#define AT_QLO    35840
#define AT_KV0    68608                // K: 2x8K | KLO: 2x8K(+16K) | VTHI(+32K) | VTLO(+48K)
#define AT_KV1    134144
#define AT_PHI    199680
#define AT_PLO    216064
#define AT_TOTAL  232448               // 227 KB
#define AT_STAGE  AT_KV0

#if TCGEN05_OK
__device__ __forceinline__ void fill_kv_tma(
    uint32_t sb, uint32_t kvb,
    const CUtensorMap* mKh, const CUtensorMap* mKl,
    const CUtensorMap* mVh, const CUtensorMap* mVl,
    int b, int bh, int h, int jt, uint32_t mbar)
{
    const int kx = h * 128, ky = b * S_LEN + jt * 64;
    tma2d(sb + kvb,         mKh, kx,      ky, mbar);
    tma2d(sb + kvb + 8192,  mKh, kx + 64, ky, mbar);
    tma2d(sb + kvb + 16384, mKl, kx,      ky, mbar);
    tma2d(sb + kvb + 24576, mKl, kx + 64, ky, mbar);
    tma2d(sb + kvb + 32768, mVh, jt * 64, bh * 128, mbar);
    tma2d(sb + kvb + 49152, mVl, jt * 64, bh * 128, mbar);
}
__device__ __forceinline__ void issue_qk(uint32_t sb, uint32_t S_T, uint32_t kvb) {
    uint64_t dQh = DESC_BASE | ((uint64_t)((sb + AT_QHI) >> 4) & 0x3FFF);
    uint64_t dQl = DESC_BASE | ((uint64_t)((sb + AT_QLO) >> 4) & 0x3FFF);
    uint64_t dKh = DESC_BASE | ((uint64_t)((sb + kvb) >> 4) & 0x3FFF);
    uint64_t dKl = DESC_BASE | ((uint64_t)((sb + kvb + 16384) >> 4) & 0x3FFF);
    const uint64_t qo[8] = {0, 2, 4, 6, 1024, 1026, 1028, 1030};
    const uint64_t ko[8] = {0, 2, 4, 6, 512, 514, 516, 518};
    uint64_t aT[3] = {dQh, dQh, dQl};
    uint64_t bT[3] = {dKh, dKl, dKh};
#pragma unroll
    for (int t = 0; t < 3; t++)
#pragma unroll
        for (int s = 0; s < 8; s++)
            mma_f16_ss(S_T, aT[t] + qo[s], bT[t] + ko[s], IDESC_N64, !(t == 0 && s == 0));
    mma_commit(sb + 8);
}
__device__ __forceinline__ void issue_pv(uint32_t sb, uint32_t O_T, uint32_t kvb,
                                         int do_commit) {
    uint64_t dPh = DESC_BASE | ((uint64_t)((sb + AT_PHI) >> 4) & 0x3FFF);
    uint64_t dPl = DESC_BASE | ((uint64_t)((sb + AT_PLO) >> 4) & 0x3FFF);
    uint64_t dVh = DESC_BASE | ((uint64_t)((sb + kvb + 32768) >> 4) & 0x3FFF);
    uint64_t dVl = DESC_BASE | ((uint64_t)((sb + kvb + 49152) >> 4) & 0x3FFF);
    uint64_t aT[3] = {dPh, dPh, dPl};
    uint64_t bT[3] = {dVh, dVl, dVh};
#pragma unroll
    for (int t = 0; t < 3; t++)
#pragma unroll
        for (int s = 0; s < 4; s++)
            mma_f16_ss(O_T, aT[t] + 2 * s, bT[t] + 2 * s, IDESC_N128, !(t == 0 && s == 0));
    if (do_commit) mma_commit(sb + 16);
}
#endif

__global__ __launch_bounds__(256) void attn_tc_kernel(
    const __grid_constant__ CUtensorMap mQh, const __grid_constant__ CUtensorMap mQl,
    const __grid_constant__ CUtensorMap mKh, const __grid_constant__ CUtensorMap mKl,
    const __grid_constant__ CUtensorMap mVh, const __grid_constant__ CUtensorMap mVl,
    __nv_bfloat16* __restrict__ Yhi, __nv_bfloat16* __restrict__ Ylo)
{
#if TCGEN05_OK
    extern __shared__ char smem[];
    const uint32_t sb = smem_u32(smem);
    const int tid = threadIdx.x;
    const int w   = tid >> 5;
    const int l   = tid & 31;
    const int r   = (w & 3) * 32 + l;
    const int hf  = w >> 2;
    const uint32_t woff = (uint32_t)(w & 3) << 21;

    if (w == 0) { tmem_alloc(sb, 512); tmem_relinquish(); }
    if (tid == 0) {
        mbar_init(sb + 8, 1);    // S
        mbar_init(sb + 16, 1);   // O final
        mbar_init(sb + 24, 1);   // kv_full[0]
        mbar_init(sb + 32, 1);   // kv_full[1]
    }
    __syncthreads();
    uint32_t tmem;
    asm volatile("ld.shared.b32 %0, [%1];" : "=r"(tmem) : "r"(sb));
    const uint32_t S_T  = tmem;
    const uint32_t O_T0 = tmem + 64;
    const uint32_t O_T1 = tmem + 192;

    uint32_t phS = 0, phO = 0, phK0 = 0, phK1 = 0;

    for (int rnd = 0; rnd < 4; rnd++) {
        int s = rnd * NSM + ((rnd & 1) ? (NSM - 1 - (int)blockIdx.x) : (int)blockIdx.x);
        if (s >= NITEMS) continue;
        const int qt = 15 - (s >> 5);     // serpentine LPT
        const int bh = s & 31;
        const int b  = bh >> 4;
        const int h  = bh & 15;
        const int njt = 2 * qt + 2;
        const int qg = qt * 128 + r;

        // ---- prologue: Q + KV(0) via TMA, then QK(0) ----
        if (tid == 0) {
            mbar_expect(sb + 24, 131072u);
            const int qx = h * 128, qy = b * S_LEN + qt * 128;
            tma2d(sb + AT_QHI,         &mQh, qx,      qy, sb + 24);
            tma2d(sb + AT_QHI + 16384, &mQh, qx + 64, qy, sb + 24);
            tma2d(sb + AT_QLO,         &mQl, qx,      qy, sb + 24);
            tma2d(sb + AT_QLO + 16384, &mQl, qx + 64, qy, sb + 24);
            fill_kv_tma(sb, AT_KV0, &mKh, &mKl, &mVh, &mVl, b, bh, h, 0, sb + 24);
            mbar_wait(sb + 24, phK0); phK0 ^= 1;
            issue_qk(sb, S_T, AT_KV0);
        }

        float m_run = -1e30f, l_run = 0.0f, corr_prev = 0.0f;
        float O[64];
#pragma unroll
        for (int j = 0; j < 64; j++) O[j] = 0.0f;

        for (int jt = 0; jt < njt; jt++) {
            const uint32_t kvb  = (jt & 1) ? AT_KV1 : AT_KV0;
            const uint32_t kvbn = (jt & 1) ? AT_KV0 : AT_KV1;

            mbar_wait(sb + 8, phS); phS ^= 1;      // S(jt) ready; PV(jt-1) done
            tcg_fence_after();

            // prefetch tile jt+1 (buffer fully free: QK & PV of jt-1 done)
            if (tid == 0 && jt + 1 < njt) {
                uint32_t kf = sb + 24 + 8 * ((jt + 1) & 1);
                mbar_expect(kf, 65536u);
                fill_kv_tma(sb, kvbn, &mKh, &mKl, &mVh, &mVl, b, bh, h, jt + 1, kf);
            }

            uint32_t sr_[32];
            ldtm_x32(sr_, S_T + hf * 32 + woff);
            tcg_wait_ld();

            // accumulate O(jt-1)
            if (jt > 0) {
                const uint32_t OP = (jt & 1) ? O_T0 : O_T1;
                uint32_t o0[32], o1[32];
                ldtm_x32(o0, OP + hf * 64 + woff);
                ldtm_x32(o1, OP + hf * 64 + 32 + woff);
                tcg_wait_ld();
#pragma unroll
                for (int j = 0; j < 32; j++) {
                    O[j]      = fmaf(O[j],      corr_prev, __uint_as_float(o0[j]));
                    O[32 + j] = fmaf(O[32 + j], corr_prev, __uint_as_float(o1[j]));
                }
            }

            // ---- softmax (scores already in log2 domain via qscale) ----
            float sv[32];
            const int kgb = jt * 64 + hf * 32;
#pragma unroll
            for (int i = 0; i < 32; i++) {
                float x = __uint_as_float(sr_[i]);
                sv[i] = (kgb + i > qg) ? -1e30f : x;
            }
            float tmax = -1e30f;
#pragma unroll
            for (int i = 0; i < 32; i++) tmax = fmaxf(tmax, sv[i]);
            float* red1 = (float*)(smem + AT_RED);
            red1[hf * 128 + r] = tmax;
            __syncthreads();
            tmax = fmaxf(tmax, red1[(1 - hf) * 128 + r]);
            float mnew = fmaxf(m_run, tmax);
            float corr = ex2f(m_run - mnew);
            float p[32], psum = 0.0f;
#pragma unroll
            for (int i = 0; i < 32; i++) {
                p[i] = ex2f(sv[i] - mnew);
                psum += p[i];
            }
            l_run = l_run * corr + psum;       // per-half; reduced at item end
            m_run = mnew;

            // ---- P -> bf16 hi/lo ----
            {
                uint32_t rowbase = (uint32_t)(r >> 3) * 1024u + (uint32_t)(r & 7) * 128u;
#pragma unroll
                for (int i = 0; i < 32; i += 2) {
                    float p0 = p[i], p1 = p[i + 1];
                    __nv_bfloat16 h0 = __float2bfloat16(p0);
                    __nv_bfloat16 h1 = __float2bfloat16(p1);
                    uint32_t hp = pack_bf2(p0, p1);
                    uint32_t lp = pack_bf2(p0 - __bfloat162float(h0),
                                           p1 - __bfloat162float(h1));
                    uint32_t sw = sw128(rowbase + (uint32_t)(hf * 32 + i) * 2u);
                    *(uint32_t*)(smem + AT_PHI + sw) = hp;
                    *(uint32_t*)(smem + AT_PLO + sw) = lp;
                }
            }
            __syncthreads();   // P visible; S fully consumed by all warps

            if (tid == 0) {
                fence_proxy_async_s();
                issue_pv(sb, (jt & 1) ? O_T1 : O_T0, kvb, jt == njt - 1);
                if (jt + 1 < njt) {
                    uint32_t kf = sb + 24 + 8 * ((jt + 1) & 1);
                    if ((jt + 1) & 1) { mbar_wait(kf, phK1); phK1 ^= 1; }
                    else              { mbar_wait(kf, phK0); phK0 ^= 1; }
                    issue_qk(sb, S_T, kvbn);
                }
            }
            corr_prev = corr;
        }

        // ---- final PV tile ----
        mbar_wait(sb + 16, phO); phO ^= 1;
        tcg_fence_after();
        {
            const uint32_t OP = ((njt - 1) & 1) ? O_T1 : O_T0;
            uint32_t o0[32], o1[32];
            ldtm_x32(o0, OP + hf * 64 + woff);
            ldtm_x32(o1, OP + hf * 64 + 32 + woff);
            tcg_wait_ld();
#pragma unroll
            for (int j = 0; j < 32; j++) {
                O[j]      = fmaf(O[j],      corr_prev, __uint_as_float(o0[j]));
                O[32 + j] = fmaf(O[32 + j], corr_prev, __uint_as_float(o1[j]));
            }
        }

        // ---- reduce l across halves, normalize, stage, write ----
        __syncthreads();
        {
            float* red1 = (float*)(smem + AT_RED);
            red1[hf * 128 + r] = l_run;
        }
        __syncthreads();
        {
            const float* red1 = (const float*)(smem + AT_RED);
            float inv = 1.0f / (red1[r] + red1[128 + r]);
            float* st = (float*)(smem + AT_STAGE);
#pragma unroll
            for (int j = 0; j < 64; j += 4) {
                float4 v = make_float4(O[j] * inv, O[j + 1] * inv,
                                       O[j + 2] * inv, O[j + 3] * inv);
                *(float4*)(st + r * 132 + hf * 64 + j) = v;
            }
        }
        __syncthreads();
        {
            const float* st = (const float*)(smem + AT_STAGE);
#pragma unroll
            for (int j = 0; j < 16; j++) {
                int u = tid + j * 256;
                int row = u >> 5, c4 = u & 31;
                float4 v = *(const float4*)(st + row * 132 + c4 * 4);
                size_t g = ((size_t)(b * S_LEN + qt * 128 + row)) * D_MODEL + h * DHEAD + c4 * 4;
                __nv_bfloat16 h0 = __float2bfloat16(v.x);
                __nv_bfloat16 h1 = __float2bfloat16(v.y);
                __nv_bfloat16 h2 = __float2bfloat16(v.z);
                __nv_bfloat16 h3 = __float2bfloat16(v.w);
                uint2 hh, ll;
                hh.x = pack_bf2(v.x, v.y); hh.y = pack_bf2(v.z, v.w);
                ll.x = pack_bf2(v.x - __bfloat162float(h0), v.y - __bfloat162float(h1));
                ll.y = pack_bf2(v.z - __bfloat162float(h2), v.w - __bfloat162float(h3));
                *(uint2*)(Yhi + g) = hh;
                *(uint2*)(Ylo + g) = ll;
            }
        }
        __syncthreads();   // staging consumed before next item's TMA
    }

    if (tid == 0) {
        mbar_inval(sb + 8);  mbar_inval(sb + 16);
        mbar_inval(sb + 24); mbar_inval(sb + 32);
    }
    if (w == 0) tmem_dealloc(tmem, 512);
#endif
}

// ---------------- host ----------------
typedef CUresult (CUDAAPI *PFN_tmap)(
    CUtensorMap*, CUtensorMapDataType, cuuint32_t, void*,
    const cuuint64_t*, const cuuint64_t*, const cuuint32_t*, const cuuint32_t*,
    CUtensorMapInterleave, CUtensorMapSwizzle, CUtensorMapL2promotion,
    CUtensorMapFloatOOBfill);

static void mk2d(PFN_tmap enc, CUtensorMap* m, void* ptr, uint32_t b0, uint32_t b1)
{
    cuuint64_t dims[2] = {D_MODEL, M_ROWS};
    cuuint64_t strides[1] = {D_MODEL * 2};
    cuuint32_t box[2] = {b0, b1};
    cuuint32_t es[2] = {1, 1};
    enc(m, CU_TENSOR_MAP_DATA_TYPE_BFLOAT16, 2, ptr, dims, strides, box, es,
        CU_TENSOR_MAP_INTERLEAVE_NONE, CU_TENSOR_MAP_SWIZZLE_128B,
        CU_TENSOR_MAP_L2_PROMOTION_L2_128B, CU_TENSOR_MAP_FLOAT_OOB_FILL_NONE);
}

extern "C" void kernel_launch(void* const* d_in, const int* in_sizes, int n_in,
                              void* d_out, int out_size)
{
    (void)in_sizes; (void)n_in; (void)out_size;
    const float* x  = (const float*)d_in[0];
    const float* Wq = (const float*)d_in[2];
    const float* Wk = (const float*)d_in[3];
    const float* Wv = (const float*)d_in[4];
    const float* Wo = (const float*)d_in[5];
    float* out = (float*)d_out;

    float* Vb;
    cudaGetSymbolAddress((void**)&Vb, g_V);
    __nv_bfloat16 *xhi, *xlo, *yhi, *ylo, *whi, *wlo;
    __nv_bfloat16 *qhi, *qlo, *khi, *klo, *vthi, *vtlo;
    cudaGetSymbolAddress((void**)&xhi, g_xhi);
    cudaGetSymbolAddress((void**)&xlo, g_xlo);
    cudaGetSymbolAddress((void**)&yhi, g_yhi);
    cudaGetSymbolAddress((void**)&ylo, g_ylo);
    cudaGetSymbolAddress((void**)&whi, g_whi);
    cudaGetSymbolAddress((void**)&wlo, g_wlo);
    cudaGetSymbolAddress((void**)&qhi, g_qhi);
    cudaGetSymbolAddress((void**)&qlo, g_qlo);
    cudaGetSymbolAddress((void**)&khi, g_khi);
    cudaGetSymbolAddress((void**)&klo, g_klo);
    cudaGetSymbolAddress((void**)&vthi, g_vthi);
    cudaGetSymbolAddress((void**)&vtlo, g_vtlo);

    void* pfn = nullptr;
    cudaDriverEntryPointQueryResult qres;
    cudaGetDriverEntryPoint("cuTensorMapEncodeTiled", &pfn, cudaEnableDefault, &qres);
    PFN_tmap enc = (PFN_tmap)pfn;

    static CUtensorMap mQh, mQl, mKh, mKl, mVh, mVl;
    mk2d(enc, &mQh, qhi, 64, 128);
    mk2d(enc, &mQl, qlo, 64, 128);
    mk2d(enc, &mKh, khi, 64, 64);
    mk2d(enc, &mKl, klo, 64, 64);
    mk2d(enc, &mVh, vthi, 64, 128);   // VT: dims [2048 s][4096 rows] same shape
    mk2d(enc, &mVl, vtlo, 64, 128);

    cudaFuncSetAttribute(gemm_qkv_kernel,
                         cudaFuncAttributeMaxDynamicSharedMemorySize, GSMEM_TOTAL);
    cudaFuncSetAttribute(gemm_out_kernel,
                         cudaFuncAttributeMaxDynamicSharedMemorySize, GSMEM_TOTAL);
    cudaFuncSetAttribute(attn_tc_kernel,
                         cudaFuncAttributeMaxDynamicSharedMemorySize, AT_TOTAL);

    const int n4x = M_ROWS * D_MODEL / 4;
    const int n4w = DD / 4;
    split_bf16_kernel<<<n4x / 256, 256>>>(x, xhi, xlo, n4x);
    wsplit4_kernel<<<dim3(n4w / 256, 4), 256>>>(Wq, Wk, Wv, Wo, whi, wlo, n4w);

    // fold log2e into Q so attention softmax can use ex2
    const float qscale = 0.08838834764831845f * LOG2E;
    gemm_qkv_kernel<<<dim3(48, 32), 256, GSMEM_TOTAL>>>(
        xhi, xlo, whi, wlo, qhi, qlo, khi, klo, Vb, qscale);

    vtrans_kernel<<<dim3(S_LEN / 32, D_MODEL / 32, NBATCH), dim3(32, 8)>>>(Vb, vthi, vtlo);

    attn_tc_kernel<<<NSM, 256, AT_TOTAL>>>(mQh, mQl, mKh, mKl, mVh, mVl, yhi, ylo);

    gemm_out_kernel<<<dim3(16, 32), 256, GSMEM_TOTAL>>>(
        yhi, ylo, whi + 3 * (size_t)DD, wlo + 3 * (size_t)DD, out, D_MODEL, D_MODEL);
}

// round 9
// speedup vs baseline: 10.9131x; 1.2121x over previous
#include <cuda_runtime.h>
#include <cuda.h>
#include <cuda_bf16.h>
#include <math.h>
#include <stdint.h>

#if defined(__CUDA_ARCH__)
#if defined(__CUDA_ARCH_FEAT_SM103_ALL) || defined(__CUDA_ARCH_FEAT_SM100_ALL) || defined(__CUDA_ARCH_FEAT_SM101_ALL)
#define TCGEN05_OK 1
#else
#define TCGEN05_OK 0
#endif
#else
#define TCGEN05_OK 0
#endif

#define NBATCH  2
#define S_LEN   2048
#define D_MODEL 2048
#define DHEAD   128
#define M_ROWS  4096
#define DD      (D_MODEL * D_MODEL)
#define NSM     148
#define NITEMS  512
#define LOG2E   1.4426950408889634f

// ---------------- scratch ----------------
__device__ float g_V[(size_t)M_ROWS * D_MODEL];
__device__ __nv_bfloat16 g_xhi[(size_t)M_ROWS * D_MODEL];
__device__ __nv_bfloat16 g_xlo[(size_t)M_ROWS * D_MODEL];
__device__ __nv_bfloat16 g_yhi[(size_t)M_ROWS * D_MODEL];
__device__ __nv_bfloat16 g_ylo[(size_t)M_ROWS * D_MODEL];
__device__ __nv_bfloat16 g_whi[(size_t)4 * DD];
__device__ __nv_bfloat16 g_wlo[(size_t)4 * DD];
__device__ __nv_bfloat16 g_qhi[(size_t)M_ROWS * D_MODEL];
__device__ __nv_bfloat16 g_qlo[(size_t)M_ROWS * D_MODEL];
__device__ __nv_bfloat16 g_khi[(size_t)M_ROWS * D_MODEL];
__device__ __nv_bfloat16 g_klo[(size_t)M_ROWS * D_MODEL];
__device__ __nv_bfloat16 g_vthi[(size_t)M_ROWS * D_MODEL];
__device__ __nv_bfloat16 g_vtlo[(size_t)M_ROWS * D_MODEL];

// ---------------- PTX helpers ----------------
__device__ __forceinline__ uint32_t smem_u32(const void* p) {
    uint32_t a;
    asm("{ .reg .u64 t; cvta.to.shared.u64 t, %1; cvt.u32.u64 %0, t; }"
        : "=r"(a) : "l"(p));
    return a;
}
__device__ __forceinline__ uint32_t elect1() {
#if TCGEN05_OK
    uint32_t p;
    asm volatile(
        "{\n\t.reg .pred p;\n\t"
        "elect.sync _|p, 0xFFFFFFFF;\n\t"
        "selp.b32 %0, 1, 0, p;\n\t}"
        : "=r"(p));
    return p;
#else
    return 0;
#endif
}
__device__ __forceinline__ void mbar_init(uint32_t addr, uint32_t count) {
    asm volatile("mbarrier.init.shared.b64 [%0], %1;" :: "r"(addr), "r"(count) : "memory");
}
__device__ __forceinline__ void mbar_inval(uint32_t addr) {
    asm volatile("mbarrier.inval.shared.b64 [%0];" :: "r"(addr) : "memory");
}
__device__ __forceinline__ void mbar_wait(uint32_t addr, uint32_t parity) {
    asm volatile(
        "{\n\t.reg .pred P;\n\t"
        "WL_%=:\n\t"
        "mbarrier.try_wait.parity.acquire.cta.shared::cta.b64 P, [%0], %1, 0x989680;\n\t"
        "@P bra.uni WD_%=;\n\t"
        "bra.uni WL_%=;\n\t"
        "WD_%=:\n\t}"
        :: "r"(addr), "r"(parity) : "memory");
}
__device__ __forceinline__ void mbar_expect(uint32_t mbar, uint32_t bytes) {
    asm volatile("mbarrier.arrive.expect_tx.shared.b64 _, [%0], %1;"
                 :: "r"(mbar), "r"(bytes) : "memory");
}
__device__ __forceinline__ void tma2d(uint32_t dst, const CUtensorMap* m,
                                      int x, int y, uint32_t mbar) {
    asm volatile(
        "cp.async.bulk.tensor.2d.shared::cta.global.tile.mbarrier::complete_tx::bytes "
        "[%0], [%1, {%2, %3}], [%4];"
        :: "r"(dst), "l"(m), "r"(x), "r"(y), "r"(mbar) : "memory");
}
__device__ __forceinline__ void tmem_alloc(uint32_t smem_dst, uint32_t ncols) {
#if TCGEN05_OK
    asm volatile("tcgen05.alloc.cta_group::1.sync.aligned.shared::cta.b32 [%0], %1;"
                 :: "r"(smem_dst), "r"(ncols) : "memory");
#endif
}
__device__ __forceinline__ void tmem_dealloc(uint32_t tmem, uint32_t ncols) {
#if TCGEN05_OK
    asm volatile("tcgen05.dealloc.cta_group::1.sync.aligned.b32 %0, %1;"
                 :: "r"(tmem), "r"(ncols));
#endif
}
__device__ __forceinline__ void tmem_relinquish() {
#if TCGEN05_OK
    asm volatile("tcgen05.relinquish_alloc_permit.cta_group::1.sync.aligned;");
#endif
}
__device__ __forceinline__ void mma_f16_ss(uint32_t d_tmem, uint64_t a_desc,
                                           uint64_t b_desc, uint32_t idesc,
                                           uint32_t enable_d) {
#if TCGEN05_OK
    asm volatile(
        "{\n\t.reg .pred p;\n\t"
        "setp.ne.u32 p, %4, 0;\n\t"
        "tcgen05.mma.cta_group::1.kind::f16 [%0], %1, %2, %3, {%5, %5, %5, %5}, p;\n\t}"
        :: "r"(d_tmem), "l"(a_desc), "l"(b_desc), "r"(idesc), "r"(enable_d), "r"(0u)
        : "memory");
#endif
}
__device__ __forceinline__ void mma_commit(uint32_t mbar_addr) {
#if TCGEN05_OK
    asm volatile(
        "tcgen05.commit.cta_group::1.mbarrier::arrive::one.shared::cluster.b64 [%0];"
        :: "r"(mbar_addr) : "memory");
#endif
}
__device__ __forceinline__ void tcg_fence_after() {
#if TCGEN05_OK
    asm volatile("tcgen05.fence::after_thread_sync;" ::: "memory");
#endif
}
__device__ __forceinline__ void fence_proxy_async_s() {
    asm volatile("fence.proxy.async.shared::cta;" ::: "memory");
}
__device__ __forceinline__ void tcg_wait_ld() {
#if TCGEN05_OK
    asm volatile("tcgen05.wait::ld.sync.aligned;" ::: "memory");
#endif
}
__device__ __forceinline__ void ldtm_x32(uint32_t* r, uint32_t addr) {
#if TCGEN05_OK
    asm volatile(
        "tcgen05.ld.sync.aligned.32x32b.x32.b32 "
        "{%0, %1, %2, %3, %4, %5, %6, %7, "
        " %8, %9, %10, %11, %12, %13, %14, %15, "
        " %16, %17, %18, %19, %20, %21, %22, %23, "
        " %24, %25, %26, %27, %28, %29, %30, %31}, [%32];"
        : "=r"(r[0]),  "=r"(r[1]),  "=r"(r[2]),  "=r"(r[3]),
          "=r"(r[4]),  "=r"(r[5]),  "=r"(r[6]),  "=r"(r[7]),
          "=r"(r[8]),  "=r"(r[9]),  "=r"(r[10]), "=r"(r[11]),
          "=r"(r[12]), "=r"(r[13]), "=r"(r[14]), "=r"(r[15]),
          "=r"(r[16]), "=r"(r[17]), "=r"(r[18]), "=r"(r[19]),
          "=r"(r[20]), "=r"(r[21]), "=r"(r[22]), "=r"(r[23]),
          "=r"(r[24]), "=r"(r[25]), "=r"(r[26]), "=r"(r[27]),
          "=r"(r[28]), "=r"(r[29]), "=r"(r[30]), "=r"(r[31])
        : "r"(addr));
#else
    for (int i = 0; i < 32; i++) r[i] = 0;
#endif
}

#define DESC_BASE ((2ull << 61) | (1ull << 46) | (64ull << 32) | (1ull << 16))
#define IDESC_N256 ((1u << 4) | (1u << 7) | (1u << 10) | (32u << 17) | (8u << 24))
#define IDESC_N128 ((1u << 4) | (1u << 7) | (1u << 10) | (16u << 17) | (8u << 24))
#define IDESC_N64  ((1u << 4) | (1u << 7) | (1u << 10) | (8u << 17)  | (8u << 24))

__device__ __forceinline__ uint32_t sw128(uint32_t bo) {
    return bo ^ ((bo >> 3) & 0x70);
}
__device__ __forceinline__ uint32_t pack_bf2(float a, float b) {
    __nv_bfloat162 v;
    v.x = __float2bfloat16(a);
    v.y = __float2bfloat16(b);
    return *(uint32_t*)&v;
}
__device__ __forceinline__ float ex2f(float x) {
    float y;
    asm("ex2.approx.ftz.f32 %0, %1;" : "=f"(y) : "f"(x));
    return y;
}

// ---------------- fp32 -> (hi, lo) bf16 split ----------------
__device__ __forceinline__ void split_body(const float* src, __nv_bfloat16* hi,
                                           __nv_bfloat16* lo, int i) {
    float4 v = ((const float4*)src)[i];
    __nv_bfloat16 h0 = __float2bfloat16(v.x);
    __nv_bfloat16 h1 = __float2bfloat16(v.y);
    __nv_bfloat16 h2 = __float2bfloat16(v.z);
    __nv_bfloat16 h3 = __float2bfloat16(v.w);
    uint2 hh, ll;
    hh.x = pack_bf2(v.x, v.y); hh.y = pack_bf2(v.z, v.w);
    ll.x = pack_bf2(v.x - __bfloat162float(h0), v.y - __bfloat162float(h1));
    ll.y = pack_bf2(v.z - __bfloat162float(h2), v.w - __bfloat162float(h3));
    *(uint2*)(hi + 4 * (size_t)i) = hh;
    *(uint2*)(lo + 4 * (size_t)i) = ll;
}

__global__ __launch_bounds__(256) void split_bf16_kernel(
    const float* __restrict__ src,
    __nv_bfloat16* __restrict__ hi, __nv_bfloat16* __restrict__ lo, int n4)
{
    int i = blockIdx.x * 256 + threadIdx.x;
    if (i < n4) split_body(src, hi, lo, i);
}

__global__ __launch_bounds__(256) void wsplit4_kernel(
    const float* __restrict__ s0, const float* __restrict__ s1,
    const float* __restrict__ s2, const float* __restrict__ s3,
    __nv_bfloat16* __restrict__ hi, __nv_bfloat16* __restrict__ lo, int n4)
{
    int i = blockIdx.x * 256 + threadIdx.x;
    if (i >= n4) return;
    int k = blockIdx.y;
    const float* src = (k == 0) ? s0 : (k == 1) ? s1 : (k == 2) ? s2 : s3;
    split_body(src, hi + (size_t)k * DD, lo + (size_t)k * DD, i);
}

// ---------------- V transpose + split ----------------
__global__ __launch_bounds__(256) void vtrans_kernel(
    const float* __restrict__ V,
    __nv_bfloat16* __restrict__ vthi, __nv_bfloat16* __restrict__ vtlo)
{
    __shared__ float t[32][33];
    const int b  = blockIdx.z;
    const int s0 = blockIdx.x * 32;
    const int d0 = blockIdx.y * 32;
    const int tx = threadIdx.x;
    const int ty = threadIdx.y;
#pragma unroll
    for (int i = 0; i < 4; i++) {
        int s = s0 + ty + i * 8;
        t[ty + i * 8][tx] = V[((size_t)b * S_LEN + s) * D_MODEL + d0 + tx];
    }
    __syncthreads();
#pragma unroll
    for (int i = 0; i < 4; i++) {
        int d = d0 + ty + i * 8;
        float v = t[tx][ty + i * 8];
        __nv_bfloat16 h = __float2bfloat16(v);
        __nv_bfloat16 l = __float2bfloat16(v - __bfloat162float(h));
        size_t o = ((size_t)b * D_MODEL + d) * S_LEN + s0 + tx;
        vthi[o] = h;
        vtlo[o] = l;
    }
}

// ---------------- 128x256 combined-term GEMM ----------------
// Per k-chunk: load Ahi/Alo (16K each) + Bhi/Blo (32K each) ONCE, issue 12 MMAs.
#define GST_A_HI 0
#define GST_A_LO 16384
#define GST_B_HI 32768
#define GST_B_LO 65536
#define GST_SIZE 98304
#define G_OFF(s) (1024 + (s) * GST_SIZE)
#define GSMEM_TOTAL (1024 + 2 * GST_SIZE)   // 197632

#if TCGEN05_OK
__device__ __forceinline__ void gemm256_mainloop(
    char* smem, uint32_t sb, uint32_t tmem, int tid, int wid,
    const __nv_bfloat16* Ahi, const __nv_bfloat16* Alo,
    const __nv_bfloat16* Bhi, const __nv_bfloat16* Blo,
    int bm, int bn, int K)
{
    uint32_t ph0 = 0, ph1 = 0;
    for (int i = 0; i < 32; i++) {
        const int k0 = i * 64;
        const int buf = i & 1;
        if (i >= 2) {
            if (buf == 0) { mbar_wait(sb + 8, ph0);  ph0 ^= 1; }
            else          { mbar_wait(sb + 16, ph1); ph1 ^= 1; }
        }
        const uint32_t off = G_OFF(buf);
        // A hi/lo: [128 rows][64 cols] each -> 1024 16B units
#pragma unroll
        for (int j = 0; j < 4; j++) {
            int u = tid + j * 256;
            int r = u >> 3, cs = u & 7;
            uint32_t sw = sw128((uint32_t)u * 16u);
            size_t g = (size_t)(bm + r) * K + k0 + cs * 8;
            *(uint4*)(smem + off + GST_A_HI + sw) = *(const uint4*)(Ahi + g);
            *(uint4*)(smem + off + GST_A_LO + sw) = *(const uint4*)(Alo + g);
        }
        // B hi/lo: [256 rows][64 cols] each -> 2048 16B units
#pragma unroll
        for (int j = 0; j < 8; j++) {
            int u = tid + j * 256;
            int r = u >> 3, cs = u & 7;
            uint32_t sw = sw128((uint32_t)u * 16u);
            size_t g = (size_t)(bn + r) * K + k0 + cs * 8;
            *(uint4*)(smem + off + GST_B_HI + sw) = *(const uint4*)(Bhi + g);
            *(uint4*)(smem + off + GST_B_LO + sw) = *(const uint4*)(Blo + g);
        }
        __syncthreads();
        if (wid == 0 && elect1()) {
            fence_proxy_async_s();
            uint64_t dAh = DESC_BASE | ((uint64_t)((sb + off + GST_A_HI) >> 4) & 0x3FFF);
            uint64_t dAl = DESC_BASE | ((uint64_t)((sb + off + GST_A_LO) >> 4) & 0x3FFF);
            uint64_t dBh = DESC_BASE | ((uint64_t)((sb + off + GST_B_HI) >> 4) & 0x3FFF);
            uint64_t dBl = DESC_BASE | ((uint64_t)((sb + off + GST_B_LO) >> 4) & 0x3FFF);
#pragma unroll
            for (int k = 0; k < 4; k++)
                mma_f16_ss(tmem, dAh + k * 2, dBh + k * 2, IDESC_N256, !(i == 0 && k == 0));
#pragma unroll
            for (int k = 0; k < 4; k++)
                mma_f16_ss(tmem, dAh + k * 2, dBl + k * 2, IDESC_N256, 1u);
#pragma unroll
            for (int k = 0; k < 4; k++)
                mma_f16_ss(tmem, dAl + k * 2, dBh + k * 2, IDESC_N256, 1u);
            mma_commit(buf ? (sb + 16) : (sb + 8));
        }
    }
    mbar_wait(sb + 16, ph1);
    tcg_fence_after();
    __syncthreads();
}
#endif

// out-projection: fp32 epilogue
__global__ __launch_bounds__(256) void gemm_out_kernel(
    const __nv_bfloat16* __restrict__ Ahi, const __nv_bfloat16* __restrict__ Alo,
    const __nv_bfloat16* __restrict__ Bhi, const __nv_bfloat16* __restrict__ Blo,
    float* __restrict__ C, int K, int N)
{
#if TCGEN05_OK
    extern __shared__ char smem[];
    const uint32_t sb = smem_u32(smem);
    const int tid = threadIdx.x;
    const int wid = tid >> 5;
    const int lid = tid & 31;
    const int bm = blockIdx.y * 128;
    const int bn = blockIdx.x * 256;

    if (wid == 0) { tmem_alloc(sb, 256); tmem_relinquish(); }
    if (tid == 0) { mbar_init(sb + 8, 1); mbar_init(sb + 16, 1); }
    __syncthreads();
    uint32_t tmem;
    asm volatile("ld.shared.b32 %0, [%1];" : "=r"(tmem) : "r"(sb));

    gemm256_mainloop(smem, sb, tmem, tid, wid, Ahi, Alo, Bhi, Blo, bm, bn, K);

    float* st = (float*)(smem + 1024);
#pragma unroll
    for (int hb = 0; hb < 4; hb++) {
        if (wid < 4) {
            uint32_t d0[32], d1[32];
            ldtm_x32(d0, tmem + hb * 64);
            ldtm_x32(d1, tmem + hb * 64 + 32);
            tcg_wait_ld();
            float* srow = st + (wid * 32 + lid) * 68;
#pragma unroll
            for (int c = 0; c < 32; c++) {
                srow[c]      = __uint_as_float(d0[c]);
                srow[32 + c] = __uint_as_float(d1[c]);
            }
        }
        __syncthreads();
#pragma unroll
        for (int j = 0; j < 8; j++) {
            int u = tid + j * 256;
            int row = u >> 4, c4 = u & 15;
            float4 v = *(const float4*)(st + row * 68 + c4 * 4);
            *(float4*)(C + (size_t)(bm + row) * N + bn + hb * 64 + c4 * 4) = v;
        }
        __syncthreads();
    }
    if (tid == 0) { mbar_inval(sb + 8); mbar_inval(sb + 16); }
    if (wid == 0) tmem_dealloc(tmem, 256);
#endif
}

// fused QKV: rgn 0=Q(hi/lo out, scaled), 1=K(hi/lo), 2=V(fp32)
__global__ __launch_bounds__(256) void gemm_qkv_kernel(
    const __nv_bfloat16* __restrict__ Ahi, const __nv_bfloat16* __restrict__ Alo,
    const __nv_bfloat16* __restrict__ Whi, const __nv_bfloat16* __restrict__ Wlo,
    __nv_bfloat16* __restrict__ Qh, __nv_bfloat16* __restrict__ Ql,
    __nv_bfloat16* __restrict__ Kh, __nv_bfloat16* __restrict__ Kl,
    float* __restrict__ Vf, float qscale)
{
#if TCGEN05_OK
    extern __shared__ char smem[];
    const uint32_t sb = smem_u32(smem);
    const int tid = threadIdx.x;
    const int wid = tid >> 5;
    const int lid = tid & 31;
    const int rgn = blockIdx.x >> 3;          // 0..2 (8 N-tiles of 256 per region)
    const int bn  = (blockIdx.x & 7) * 256;
    const int bm  = blockIdx.y * 128;
    const int N   = D_MODEL, K = D_MODEL;

    if (wid == 0) { tmem_alloc(sb, 256); tmem_relinquish(); }
    if (tid == 0) { mbar_init(sb + 8, 1); mbar_init(sb + 16, 1); }
    __syncthreads();
    uint32_t tmem;
    asm volatile("ld.shared.b32 %0, [%1];" : "=r"(tmem) : "r"(sb));

    gemm256_mainloop(smem, sb, tmem, tid, wid, Ahi, Alo,
                     Whi + (size_t)rgn * DD, Wlo + (size_t)rgn * DD, bm, bn, K);

    const float scale = (rgn == 0) ? qscale : 1.0f;
    float* st = (float*)(smem + 1024);
#pragma unroll
    for (int hb = 0; hb < 4; hb++) {
        if (wid < 4) {
            uint32_t d0[32], d1[32];
            ldtm_x32(d0, tmem + hb * 64);
            ldtm_x32(d1, tmem + hb * 64 + 32);
            tcg_wait_ld();
            float* srow = st + (wid * 32 + lid) * 68;
#pragma unroll
            for (int c = 0; c < 32; c++) {
                srow[c]      = __uint_as_float(d0[c]);
                srow[32 + c] = __uint_as_float(d1[c]);
            }
        }
        __syncthreads();
#pragma unroll
        for (int j = 0; j < 8; j++) {
            int u = tid + j * 256;
            int row = u >> 4, c4 = u & 15;
            float4 v = *(const float4*)(st + row * 68 + c4 * 4);
            size_t grow = (size_t)(bm + row);
            int gcol = bn + hb * 64 + c4 * 4;
            if (rgn == 2) {
                *(float4*)(Vf + grow * N + gcol) = v;
            } else {
                float v0 = v.x * scale, v1 = v.y * scale;
                float v2 = v.z * scale, v3 = v.w * scale;
                __nv_bfloat16 h0 = __float2bfloat16(v0);
                __nv_bfloat16 h1 = __float2bfloat16(v1);
                __nv_bfloat16 h2 = __float2bfloat16(v2);
                __nv_bfloat16 h3 = __float2bfloat16(v3);
                uint2 hh, ll;
                hh.x = pack_bf2(v0, v1); hh.y = pack_bf2(v2, v3);
                ll.x = pack_bf2(v0 - __bfloat162float(h0), v1 - __bfloat162float(h1));
                ll.y = pack_bf2(v2 - __bfloat162float(h2), v3 - __bfloat162float(h3));
                __nv_bfloat16* H = (rgn == 0) ? Qh : Kh;
                __nv_bfloat16* L = (rgn == 0) ? Ql : Kl;
                *(uint2*)(H + grow * N + gcol) = hh;
                *(uint2*)(L + grow * N + gcol) = ll;
            }
        }
        __syncthreads();
    }
    if (tid == 0) { mbar_inval(sb + 8); mbar_inval(sb + 16); }
    if (wid == 0) tmem_dealloc(tmem, 256);
#endif
}

// ---------------- persistent tcgen05 flash attention (R8, unchanged) --------
#define AT_RED    1024
#define AT_QHI    3072
#define AT_QLO    35840
#define AT_KV0    68608
#define AT_KV1    134144
#define AT_PHI    199680
#define AT_PLO    216064
#define AT_TOTAL  232448
#define AT_STAGE  AT_KV0

#if TCGEN05_OK
__device__ __forceinline__ void fill_kv_tma(
    uint32_t sb, uint32_t kvb,
    const CUtensorMap* mKh, const CUtensorMap* mKl,
    const CUtensorMap* mVh, const CUtensorMap* mVl,
    int b, int bh, int h, int jt, uint32_t mbar)
{
    const int kx = h * 128, ky = b * S_LEN + jt * 64;
    tma2d(sb + kvb,         mKh, kx,      ky, mbar);
    tma2d(sb + kvb + 8192,  mKh, kx + 64, ky, mbar);
    tma2d(sb + kvb + 16384, mKl, kx,      ky, mbar);
    tma2d(sb + kvb + 24576, mKl, kx + 64, ky, mbar);
    tma2d(sb + kvb + 32768, mVh, jt * 64, bh * 128, mbar);
    tma2d(sb + kvb + 49152, mVl, jt * 64, bh * 128, mbar);
}
__device__ __forceinline__ void issue_qk(uint32_t sb, uint32_t S_T, uint32_t kvb) {
    uint64_t dQh = DESC_BASE | ((uint64_t)((sb + AT_QHI) >> 4) & 0x3FFF);
    uint64_t dQl = DESC_BASE | ((uint64_t)((sb + AT_QLO) >> 4) & 0x3FFF);
    uint64_t dKh = DESC_BASE | ((uint64_t)((sb + kvb) >> 4) & 0x3FFF);
    uint64_t dKl = DESC_BASE | ((uint64_t)((sb + kvb + 16384) >> 4) & 0x3FFF);
    const uint64_t qo[8] = {0, 2, 4, 6, 1024, 1026, 1028, 1030};
    const uint64_t ko[8] = {0, 2, 4, 6, 512, 514, 516, 518};
    uint64_t aT[3] = {dQh, dQh, dQl};
    uint64_t bT[3] = {dKh, dKl, dKh};
#pragma unroll
    for (int t = 0; t < 3; t++)
#pragma unroll
        for (int s = 0; s < 8; s++)
            mma_f16_ss(S_T, aT[t] + qo[s], bT[t] + ko[s], IDESC_N64, !(t == 0 && s == 0));
    mma_commit(sb + 8);
}
__device__ __forceinline__ void issue_pv(uint32_t sb, uint32_t O_T, uint32_t kvb,
                                         int do_commit) {
    uint64_t dPh = DESC_BASE | ((uint64_t)((sb + AT_PHI) >> 4) & 0x3FFF);
    uint64_t dPl = DESC_BASE | ((uint64_t)((sb + AT_PLO) >> 4) & 0x3FFF);
    uint64_t dVh = DESC_BASE | ((uint64_t)((sb + kvb + 32768) >> 4) & 0x3FFF);
    uint64_t dVl = DESC_BASE | ((uint64_t)((sb + kvb + 49152) >> 4) & 0x3FFF);
    uint64_t aT[3] = {dPh, dPh, dPl};
    uint64_t bT[3] = {dVh, dVl, dVh};
#pragma unroll
    for (int t = 0; t < 3; t++)
#pragma unroll
        for (int s = 0; s < 4; s++)
            mma_f16_ss(O_T, aT[t] + 2 * s, bT[t] + 2 * s, IDESC_N128, !(t == 0 && s == 0));
    if (do_commit) mma_commit(sb + 16);
}
#endif

__global__ __launch_bounds__(256) void attn_tc_kernel(
    const __grid_constant__ CUtensorMap mQh, const __grid_constant__ CUtensorMap mQl,
    const __grid_constant__ CUtensorMap mKh, const __grid_constant__ CUtensorMap mKl,
    const __grid_constant__ CUtensorMap mVh, const __grid_constant__ CUtensorMap mVl,
    __nv_bfloat16* __restrict__ Yhi, __nv_bfloat16* __restrict__ Ylo)
{
#if TCGEN05_OK
    extern __shared__ char smem[];
    const uint32_t sb = smem_u32(smem);
    const int tid = threadIdx.x;
    const int w   = tid >> 5;
    const int l   = tid & 31;
    const int r   = (w & 3) * 32 + l;
    const int hf  = w >> 2;
    const uint32_t woff = (uint32_t)(w & 3) << 21;

    if (w == 0) { tmem_alloc(sb, 512); tmem_relinquish(); }
    if (tid == 0) {
        mbar_init(sb + 8, 1);
        mbar_init(sb + 16, 1);
        mbar_init(sb + 24, 1);
        mbar_init(sb + 32, 1);
    }
    __syncthreads();
    uint32_t tmem;
    asm volatile("ld.shared.b32 %0, [%1];" : "=r"(tmem) : "r"(sb));
    const uint32_t S_T  = tmem;
    const uint32_t O_T0 = tmem + 64;
    const uint32_t O_T1 = tmem + 192;

    uint32_t phS = 0, phO = 0, phK0 = 0, phK1 = 0;

    for (int rnd = 0; rnd < 4; rnd++) {
        int s = rnd * NSM + ((rnd & 1) ? (NSM - 1 - (int)blockIdx.x) : (int)blockIdx.x);
        if (s >= NITEMS) continue;
        const int qt = 15 - (s >> 5);
        const int bh = s & 31;
        const int b  = bh >> 4;
        const int h  = bh & 15;
        const int njt = 2 * qt + 2;
        const int qg = qt * 128 + r;

        if (tid == 0) {
            mbar_expect(sb + 24, 131072u);
            const int qx = h * 128, qy = b * S_LEN + qt * 128;
            tma2d(sb + AT_QHI,         &mQh, qx,      qy, sb + 24);
            tma2d(sb + AT_QHI + 16384, &mQh, qx + 64, qy, sb + 24);
            tma2d(sb + AT_QLO,         &mQl, qx,      qy, sb + 24);
            tma2d(sb + AT_QLO + 16384, &mQl, qx + 64, qy, sb + 24);
            fill_kv_tma(sb, AT_KV0, &mKh, &mKl, &mVh, &mVl, b, bh, h, 0, sb + 24);
            mbar_wait(sb + 24, phK0); phK0 ^= 1;
            issue_qk(sb, S_T, AT_KV0);
        }

        float m_run = -1e30f, l_run = 0.0f, corr_prev = 0.0f;
        float O[64];
#pragma unroll
        for (int j = 0; j < 64; j++) O[j] = 0.0f;

        for (int jt = 0; jt < njt; jt++) {
            const uint32_t kvb  = (jt & 1) ? AT_KV1 : AT_KV0;
            const uint32_t kvbn = (jt & 1) ? AT_KV0 : AT_KV1;

            mbar_wait(sb + 8, phS); phS ^= 1;
            tcg_fence_after();

            if (tid == 0 && jt + 1 < njt) {
                uint32_t kf = sb + 24 + 8 * ((jt + 1) & 1);
                mbar_expect(kf, 65536u);
                fill_kv_tma(sb, kvbn, &mKh, &mKl, &mVh, &mVl, b, bh, h, jt + 1, kf);
            }

            uint32_t sr_[32];
            ldtm_x32(sr_, S_T + hf * 32 + woff);
            tcg_wait_ld();

            if (jt > 0) {
                const uint32_t OP = (jt & 1) ? O_T0 : O_T1;
                uint32_t o0[32], o1[32];
                ldtm_x32(o0, OP + hf * 64 + woff);
                ldtm_x32(o1, OP + hf * 64 + 32 + woff);
                tcg_wait_ld();
#pragma unroll
                for (int j = 0; j < 32; j++) {
                    O[j]      = fmaf(O[j],      corr_prev, __uint_as_float(o0[j]));
                    O[32 + j] = fmaf(O[32 + j], corr_prev, __uint_as_float(o1[j]));
                }
            }

            float sv[32];
            const int kgb = jt * 64 + hf * 32;
#pragma unroll
            for (int i = 0; i < 32; i++) {
                float x = __uint_as_float(sr_[i]);
                sv[i] = (kgb + i > qg) ? -1e30f : x;
            }
            float tmax = -1e30f;
#pragma unroll
            for (int i = 0; i < 32; i++) tmax = fmaxf(tmax, sv[i]);
            float* red1 = (float*)(smem + AT_RED);
            red1[hf * 128 + r] = tmax;
            __syncthreads();
            tmax = fmaxf(tmax, red1[(1 - hf) * 128 + r]);
            float mnew = fmaxf(m_run, tmax);
            float corr = ex2f(m_run - mnew);
            float p[32], psum = 0.0f;
#pragma unroll
            for (int i = 0; i < 32; i++) {
                p[i] = ex2f(sv[i] - mnew);
                psum += p[i];
            }
            l_run = l_run * corr + psum;
            m_run = mnew;

            {
                uint32_t rowbase = (uint32_t)(r >> 3) * 1024u + (uint32_t)(r & 7) * 128u;
#pragma unroll
                for (int i = 0; i < 32; i += 2) {
                    float p0 = p[i], p1 = p[i + 1];
                    __nv_bfloat16 h0 = __float2bfloat16(p0);
                    __nv_bfloat16 h1 = __float2bfloat16(p1);
                    uint32_t hp = pack_bf2(p0, p1);
                    uint32_t lp = pack_bf2(p0 - __bfloat162float(h0),
                                           p1 - __bfloat162float(h1));
                    uint32_t sw = sw128(rowbase + (uint32_t)(hf * 32 + i) * 2u);
                    *(uint32_t*)(smem + AT_PHI + sw) = hp;
                    *(uint32_t*)(smem + AT_PLO + sw) = lp;
                }
            }
            __syncthreads();

            if (tid == 0) {
                fence_proxy_async_s();
                issue_pv(sb, (jt & 1) ? O_T1 : O_T0, kvb, jt == njt - 1);
                if (jt + 1 < njt) {
                    uint32_t kf = sb + 24 + 8 * ((jt + 1) & 1);
                    if ((jt + 1) & 1) { mbar_wait(kf, phK1); phK1 ^= 1; }
                    else              { mbar_wait(kf, phK0); phK0 ^= 1; }
                    issue_qk(sb, S_T, kvbn);
                }
            }
            corr_prev = corr;
        }

        mbar_wait(sb + 16, phO); phO ^= 1;
        tcg_fence_after();
        {
            const uint32_t OP = ((njt - 1) & 1) ? O_T1 : O_T0;
            uint32_t o0[32], o1[32];
            ldtm_x32(o0, OP + hf * 64 + woff);
            ldtm_x32(o1, OP + hf * 64 + 32 + woff);
            tcg_wait_ld();
#pragma unroll
            for (int j = 0; j < 32; j++) {
                O[j]      = fmaf(O[j],      corr_prev, __uint_as_float(o0[j]));
                O[32 + j] = fmaf(O[32 + j], corr_prev, __uint_as_float(o1[j]));
            }
        }

        __syncthreads();
        {
            float* red1 = (float*)(smem + AT_RED);
            red1[hf * 128 + r] = l_run;
        }
        __syncthreads();
        {
            const float* red1 = (const float*)(smem + AT_RED);
            float inv = 1.0f / (red1[r] + red1[128 + r]);
            float* st = (float*)(smem + AT_STAGE);
#pragma unroll
            for (int j = 0; j < 64; j += 4) {
                float4 v = make_float4(O[j] * inv, O[j + 1] * inv,
                                       O[j + 2] * inv, O[j + 3] * inv);
                *(float4*)(st + r * 132 + hf * 64 + j) = v;
            }
        }
        __syncthreads();
        {
            const float* st = (const float*)(smem + AT_STAGE);
#pragma unroll
            for (int j = 0; j < 16; j++) {
                int u = tid + j * 256;
                int row = u >> 5, c4 = u & 31;
                float4 v = *(const float4*)(st + row * 132 + c4 * 4);
                size_t g = ((size_t)(b * S_LEN + qt * 128 + row)) * D_MODEL + h * DHEAD + c4 * 4;
                __nv_bfloat16 h0 = __float2bfloat16(v.x);
                __nv_bfloat16 h1 = __float2bfloat16(v.y);
                __nv_bfloat16 h2 = __float2bfloat16(v.z);
                __nv_bfloat16 h3 = __float2bfloat16(v.w);
                uint2 hh, ll;
                hh.x = pack_bf2(v.x, v.y); hh.y = pack_bf2(v.z, v.w);
                ll.x = pack_bf2(v.x - __bfloat162float(h0), v.y - __bfloat162float(h1));
                ll.y = pack_bf2(v.z - __bfloat162float(h2), v.w - __bfloat162float(h3));
                *(uint2*)(Yhi + g) = hh;
                *(uint2*)(Ylo + g) = ll;
            }
        }
        __syncthreads();
    }

    if (tid == 0) {
        mbar_inval(sb + 8);  mbar_inval(sb + 16);
        mbar_inval(sb + 24); mbar_inval(sb + 32);
    }
    if (w == 0) tmem_dealloc(tmem, 512);
#endif
}

// ---------------- host ----------------
typedef CUresult (CUDAAPI *PFN_tmap)(
    CUtensorMap*, CUtensorMapDataType, cuuint32_t, void*,
    const cuuint64_t*, const cuuint64_t*, const cuuint32_t*, const cuuint32_t*,
    CUtensorMapInterleave, CUtensorMapSwizzle, CUtensorMapL2promotion,
    CUtensorMapFloatOOBfill);

static void mk2d(PFN_tmap enc, CUtensorMap* m, void* ptr, uint32_t b0, uint32_t b1)
{
    cuuint64_t dims[2] = {D_MODEL, M_ROWS};
    cuuint64_t strides[1] = {D_MODEL * 2};
    cuuint32_t box[2] = {b0, b1};
    cuuint32_t es[2] = {1, 1};
    enc(m, CU_TENSOR_MAP_DATA_TYPE_BFLOAT16, 2, ptr, dims, strides, box, es,
        CU_TENSOR_MAP_INTERLEAVE_NONE, CU_TENSOR_MAP_SWIZZLE_128B,
        CU_TENSOR_MAP_L2_PROMOTION_L2_128B, CU_TENSOR_MAP_FLOAT_OOB_FILL_NONE);
}

extern "C" void kernel_launch(void* const* d_in, const int* in_sizes, int n_in,
                              void* d_out, int out_size)
{
    (void)in_sizes; (void)n_in; (void)out_size;
    const float* x  = (const float*)d_in[0];
    const float* Wq = (const float*)d_in[2];
    const float* Wk = (const float*)d_in[3];
    const float* Wv = (const float*)d_in[4];
    const float* Wo = (const float*)d_in[5];
    float* out = (float*)d_out;

    float* Vb;
    cudaGetSymbolAddress((void**)&Vb, g_V);
    __nv_bfloat16 *xhi, *xlo, *yhi, *ylo, *whi, *wlo;
    __nv_bfloat16 *qhi, *qlo, *khi, *klo, *vthi, *vtlo;
    cudaGetSymbolAddress((void**)&xhi, g_xhi);
    cudaGetSymbolAddress((void**)&xlo, g_xlo);
    cudaGetSymbolAddress((void**)&yhi, g_yhi);
    cudaGetSymbolAddress((void**)&ylo, g_ylo);
    cudaGetSymbolAddress((void**)&whi, g_whi);
    cudaGetSymbolAddress((void**)&wlo, g_wlo);
    cudaGetSymbolAddress((void**)&qhi, g_qhi);
    cudaGetSymbolAddress((void**)&qlo, g_qlo);
    cudaGetSymbolAddress((void**)&khi, g_khi);
    cudaGetSymbolAddress((void**)&klo, g_klo);
    cudaGetSymbolAddress((void**)&vthi, g_vthi);
    cudaGetSymbolAddress((void**)&vtlo, g_vtlo);

    void* pfn = nullptr;
    cudaDriverEntryPointQueryResult qres;
    cudaGetDriverEntryPoint("cuTensorMapEncodeTiled", &pfn, cudaEnableDefault, &qres);
    PFN_tmap enc = (PFN_tmap)pfn;

    static CUtensorMap mQh, mQl, mKh, mKl, mVh, mVl;
    mk2d(enc, &mQh, qhi, 64, 128);
    mk2d(enc, &mQl, qlo, 64, 128);
    mk2d(enc, &mKh, khi, 64, 64);
    mk2d(enc, &mKl, klo, 64, 64);
    mk2d(enc, &mVh, vthi, 64, 128);
    mk2d(enc, &mVl, vtlo, 64, 128);

    cudaFuncSetAttribute(gemm_qkv_kernel,
                         cudaFuncAttributeMaxDynamicSharedMemorySize, GSMEM_TOTAL);
    cudaFuncSetAttribute(gemm_out_kernel,
                         cudaFuncAttributeMaxDynamicSharedMemorySize, GSMEM_TOTAL);
    cudaFuncSetAttribute(attn_tc_kernel,
                         cudaFuncAttributeMaxDynamicSharedMemorySize, AT_TOTAL);

    const int n4x = M_ROWS * D_MODEL / 4;
    const int n4w = DD / 4;
    split_bf16_kernel<<<n4x / 256, 256>>>(x, xhi, xlo, n4x);
    wsplit4_kernel<<<dim3(n4w / 256, 4), 256>>>(Wq, Wk, Wv, Wo, whi, wlo, n4w);

    const float qscale = 0.08838834764831845f * LOG2E;
    gemm_qkv_kernel<<<dim3(24, 32), 256, GSMEM_TOTAL>>>(
        xhi, xlo, whi, wlo, qhi, qlo, khi, klo, Vb, qscale);

    vtrans_kernel<<<dim3(S_LEN / 32, D_MODEL / 32, NBATCH), dim3(32, 8)>>>(Vb, vthi, vtlo);

    attn_tc_kernel<<<NSM, 256, AT_TOTAL>>>(mQh, mQl, mKh, mKl, mVh, mVl, yhi, ylo);

    gemm_out_kernel<<<dim3(8, 32), 256, GSMEM_TOTAL>>>(
        yhi, ylo, whi + 3 * (size_t)DD, wlo + 3 * (size_t)DD, out, D_MODEL, D_MODEL);
}